// round 2
// baseline (speedup 1.0000x reference)
#include <cuda_runtime.h>
#include <math.h>

#define BB 8
#define LL 1024
#define HH 768
#define NHEAD 12
#define HDIM 64
#define DIN 3072
#define ATT_SCALE 0.125f
#define FULLMASK 0xffffffffu

// ---------------- scratch (device globals; no allocations allowed) ----------------
__device__ float g_nodes[BB*LL*HH];
__device__ float g_h[BB*LL*HH];
__device__ float g_q[BB*LL*HH];
__device__ float g_k[BB*LL*HH];
__device__ float g_v[BB*LL*HH];
__device__ float g_att[BB*LL*HH];
__device__ float g_ff[BB*LL*DIN];
__device__ float g_relay[BB*HH];
__device__ float g_rk[BB*HH];
__device__ float g_rv[BB*HH];
__device__ float g_sq[BB*HH];
__device__ float g_skr[BB*HH];
__device__ float g_svr[BB*HH];
__device__ float g_satt[BB*HH];
__device__ float g_ft[BB*2*HH];
__device__ float g_hid[3*BB*1024];
__device__ int   g_mask[BB*LL];

// ---------------- embedding + positional ----------------
__global__ void embed_kernel(const int* __restrict__ src, const float* __restrict__ emb,
                             const float* __restrict__ pos, float* __restrict__ nodes)
{
    int idx = blockIdx.x * blockDim.x + threadIdx.x;
    if (idx >= BB*LL*HH) return;
    int hh = idx % HH;
    int bl = idx / HH;
    int l  = bl % LL;
    int j  = hh >> 8;      // which of 3 tokens
    int d  = hh & 255;     // dim within DW=256
    int tok = src[bl*3 + j];
    nodes[idx] = emb[tok*256 + d] + pos[l*HH + hh];
}

__global__ void mask_kernel(const int* __restrict__ src, int* __restrict__ mask)
{
    int i = blockIdx.x * blockDim.x + threadIdx.x;
    if (i < BB*LL) mask[i] = (src[i*3] == 0) ? 1 : 0;
}

__global__ void relay_mean_kernel(const float* __restrict__ nodes, float* __restrict__ relay)
{
    int b  = blockIdx.x;
    int hh = blockIdx.y * 256 + threadIdx.x;
    const float* p = nodes + (size_t)b*LL*HH + hh;
    float s = 0.f;
    for (int l = 0; l < LL; l++) s += p[(size_t)l*HH];
    relay[b*HH + hh] = s * (1.0f/1024.0f);
}

// ---------------- big GEMM: C[M,N] = A[M,K] * W[N,K]^T + bias, optional relu ----------------
// M,N multiples of 128; K multiple of 8.
__global__ void __launch_bounds__(256) gemm_nt_kernel(
    const float* __restrict__ A, const float* __restrict__ W,
    const float* __restrict__ bias, float* __restrict__ C,
    int M, int N, int K, int act)
{
    __shared__ __align__(16) float As[8][128];
    __shared__ __align__(16) float Bs[8][128];
    const int tid = threadIdx.x;
    const int bm = blockIdx.y * 128;
    const int bn = blockIdx.x * 128;
    const int tx = tid & 15;
    const int ty = tid >> 4;
    const int lrow = tid >> 1;
    const int lk   = (tid & 1) << 2;
    const float* Ap = A + (size_t)(bm + lrow) * K + lk;
    const float* Wp = W + (size_t)(bn + lrow) * K + lk;

    float acc[8][8];
    #pragma unroll
    for (int i = 0; i < 8; i++)
        #pragma unroll
        for (int j = 0; j < 8; j++) acc[i][j] = 0.f;

    for (int kt = 0; kt < K; kt += 8) {
        float4 a4 = *(const float4*)(Ap + kt);
        float4 w4 = *(const float4*)(Wp + kt);
        As[lk+0][lrow] = a4.x; As[lk+1][lrow] = a4.y; As[lk+2][lrow] = a4.z; As[lk+3][lrow] = a4.w;
        Bs[lk+0][lrow] = w4.x; Bs[lk+1][lrow] = w4.y; Bs[lk+2][lrow] = w4.z; Bs[lk+3][lrow] = w4.w;
        __syncthreads();
        #pragma unroll
        for (int k = 0; k < 8; k++) {
            float4 a0 = *(const float4*)&As[k][ty*8];
            float4 a1 = *(const float4*)&As[k][ty*8+4];
            float4 b0 = *(const float4*)&Bs[k][tx*8];
            float4 b1 = *(const float4*)&Bs[k][tx*8+4];
            float ar[8] = {a0.x,a0.y,a0.z,a0.w,a1.x,a1.y,a1.z,a1.w};
            float br[8] = {b0.x,b0.y,b0.z,b0.w,b1.x,b1.y,b1.z,b1.w};
            #pragma unroll
            for (int i = 0; i < 8; i++)
                #pragma unroll
                for (int j = 0; j < 8; j++)
                    acc[i][j] += ar[i]*br[j];
        }
        __syncthreads();
    }

    #pragma unroll
    for (int i = 0; i < 8; i++) {
        int row = bm + ty*8 + i;
        float* cp = C + (size_t)row*N + bn + tx*8;
        #pragma unroll
        for (int j = 0; j < 8; j += 4) {
            int col = bn + tx*8 + j;
            float4 r;
            r.x = acc[i][j+0] + bias[col+0];
            r.y = acc[i][j+1] + bias[col+1];
            r.z = acc[i][j+2] + bias[col+2];
            r.w = acc[i][j+3] + bias[col+3];
            if (act == 1) {
                r.x = fmaxf(r.x, 0.f); r.y = fmaxf(r.y, 0.f);
                r.z = fmaxf(r.z, 0.f); r.w = fmaxf(r.w, 0.f);
            }
            *(float4*)(cp + j) = r;
        }
    }
}

// ---------------- small GEMM (warp-per-output): C[m*ldc+n] = A[m,:K].W[n,:K] + bias ----------------
// act: 0 none, 1 relu, 2 leaky(0.01). K multiple of 4.
__global__ void small_nt_kernel(const float* __restrict__ A, const float* __restrict__ W,
                                const float* __restrict__ bias, float* __restrict__ C,
                                int M, int N, int K, int ldc, int act)
{
    int w = (blockIdx.x * blockDim.x + threadIdx.x) >> 5;
    int lane = threadIdx.x & 31;
    if (w >= M*N) return;
    int m = w / N, n = w % N;
    const float4* a  = (const float4*)(A + (size_t)m*K);
    const float4* wr = (const float4*)(W + (size_t)n*K);
    float s = 0.f;
    int K4 = K >> 2;
    for (int c = lane; c < K4; c += 32) {
        float4 av = a[c], wv = wr[c];
        s += av.x*wv.x + av.y*wv.y + av.z*wv.z + av.w*wv.w;
    }
    #pragma unroll
    for (int o = 16; o > 0; o >>= 1) s += __shfl_xor_sync(FULLMASK, s, o);
    if (lane == 0) {
        s += bias[n];
        if (act == 1) s = fmaxf(s, 0.f);
        else if (act == 2 && s < 0.f) s *= 0.01f;
        C[(size_t)m*ldc + n] = s;
    }
}

// ---------------- LayerNorm (row=768), optional residual and leaky ----------------
__global__ void __launch_bounds__(256) ln_kernel(
    const float* __restrict__ X, const float* __restrict__ RES,
    const float* __restrict__ g, const float* __restrict__ b,
    float* __restrict__ out, int leaky)
{
    __shared__ float shs[8], shs2[8];
    __shared__ float smean, sinv;
    int row = blockIdx.x;
    int tid = threadIdx.x;
    const float* x = X + (size_t)row*HH;
    float v0 = x[tid], v1 = x[tid+256], v2 = x[tid+512];
    if (RES) {
        const float* r = RES + (size_t)row*HH;
        v0 += r[tid]; v1 += r[tid+256]; v2 += r[tid+512];
    }
    float s  = v0+v1+v2;
    float s2 = v0*v0 + v1*v1 + v2*v2;
    #pragma unroll
    for (int o = 16; o > 0; o >>= 1) {
        s  += __shfl_xor_sync(FULLMASK, s, o);
        s2 += __shfl_xor_sync(FULLMASK, s2, o);
    }
    if ((tid & 31) == 0) { shs[tid>>5] = s; shs2[tid>>5] = s2; }
    __syncthreads();
    if (tid == 0) {
        float ts = 0.f, ts2 = 0.f;
        for (int i = 0; i < 8; i++) { ts += shs[i]; ts2 += shs2[i]; }
        float mean = ts * (1.0f/768.0f);
        float var  = ts2 * (1.0f/768.0f) - mean*mean;
        smean = mean;
        sinv  = rsqrtf(var + 1e-5f);
    }
    __syncthreads();
    float mean = smean, inv = sinv;
    float* o = out + (size_t)row*HH;
    float y0 = (v0-mean)*inv*g[tid]     + b[tid];
    float y1 = (v1-mean)*inv*g[tid+256] + b[tid+256];
    float y2 = (v2-mean)*inv*g[tid+512] + b[tid+512];
    if (leaky) {
        if (y0 < 0.f) y0 *= 0.01f;
        if (y1 < 0.f) y1 *= 0.01f;
        if (y2 < 0.f) y2 *= 0.01f;
    }
    o[tid] = y0; o[tid+256] = y1; o[tid+512] = y2;
}

// ---------------- ring attention: warp per (b,l,head); 3 local keys (zero-padded) + relay ----------------
__global__ void __launch_bounds__(256) ring_attn_kernel(
    const float* __restrict__ q, const float* __restrict__ k, const float* __restrict__ v,
    const float* __restrict__ rk, const float* __restrict__ rv, float* __restrict__ att)
{
    int gw = (blockIdx.x * 256 + threadIdx.x) >> 5;
    int lane = threadIdx.x & 31;
    if (gw >= BB*LL*NHEAD) return;
    int n  = gw % NHEAD;
    int bl = gw / NHEAD;
    int l  = bl % LL;
    int b  = bl / LL;
    const float* qp = q + (size_t)bl*HH + n*HDIM;
    float q0 = qp[lane], q1 = qp[lane+32];

    float s[4];
    #pragma unroll
    for (int w = 0; w < 3; w++) {
        int ll = l + w - 1;
        float d = 0.f;
        if (ll >= 0 && ll < LL) {
            const float* kp = k + ((size_t)b*LL + ll)*HH + n*HDIM;
            d = q0*kp[lane] + q1*kp[lane+32];
        }
        #pragma unroll
        for (int o = 16; o > 0; o >>= 1) d += __shfl_xor_sync(FULLMASK, d, o);
        s[w] = d;   // padded key -> exactly 0, still participates in softmax
    }
    {
        const float* kp = rk + b*HH + n*HDIM;
        float d = q0*kp[lane] + q1*kp[lane+32];
        #pragma unroll
        for (int o = 16; o > 0; o >>= 1) d += __shfl_xor_sync(FULLMASK, d, o);
        s[3] = d;
    }
    float sc0 = s[0]*ATT_SCALE, sc1 = s[1]*ATT_SCALE, sc2 = s[2]*ATT_SCALE, sc3 = s[3]*ATT_SCALE;
    float m = fmaxf(fmaxf(sc0, sc1), fmaxf(sc2, sc3));
    float e0 = expf(sc0-m), e1 = expf(sc1-m), e2 = expf(sc2-m), e3 = expf(sc3-m);
    float inv = 1.f / (e0+e1+e2+e3);
    float a0 = e0*inv, a1 = e1*inv, a2 = e2*inv, a3 = e3*inv;

    const float* rvp = rv + b*HH + n*HDIM;
    float o0 = a3 * rvp[lane];
    float o1 = a3 * rvp[lane+32];
    float aw[3] = {a0, a1, a2};
    #pragma unroll
    for (int w = 0; w < 3; w++) {
        int ll = l + w - 1;
        if (ll >= 0 && ll < LL) {
            const float* vp = v + ((size_t)b*LL + ll)*HH + n*HDIM;
            o0 += aw[w] * vp[lane];
            o1 += aw[w] * vp[lane+32];
        }
    }
    att[(size_t)bl*HH + n*HDIM + lane]    = o0;
    att[(size_t)bl*HH + n*HDIM + lane+32] = o1;
}

// ---------------- star attention: block per (b,head); 1 relay key + L node keys ----------------
__global__ void __launch_bounds__(256) star_attn_kernel(
    const float* __restrict__ sq, const float* __restrict__ skr, const float* __restrict__ svr,
    const float* __restrict__ k, const float* __restrict__ v, const int* __restrict__ mask,
    float* __restrict__ satt)
{
    __shared__ float sc[LL+1];
    __shared__ float qv[HDIM];
    __shared__ float red[8];
    __shared__ float bmax, bsum;
    __shared__ float part[4][HDIM];
    int b = blockIdx.x / NHEAD;
    int n = blockIdx.x % NHEAD;
    int tid = threadIdx.x;

    if (tid < HDIM) qv[tid] = sq[b*HH + n*HDIM + tid];
    __syncthreads();

    for (int s = tid; s <= LL; s += 256) {
        float d;
        if (s > 0 && mask[b*LL + s-1]) d = -INFINITY;
        else {
            const float* kp = (s == 0) ? (skr + b*HH + n*HDIM)
                                       : (k + ((size_t)b*LL + s-1)*HH + n*HDIM);
            float acc = 0.f;
            #pragma unroll 16
            for (int dd = 0; dd < HDIM; dd++) acc += qv[dd]*kp[dd];
            d = acc * ATT_SCALE;
        }
        sc[s] = d;
    }
    __syncthreads();

    float m = -INFINITY;
    for (int s = tid; s <= LL; s += 256) m = fmaxf(m, sc[s]);
    #pragma unroll
    for (int o = 16; o > 0; o >>= 1) m = fmaxf(m, __shfl_xor_sync(FULLMASK, m, o));
    if ((tid & 31) == 0) red[tid>>5] = m;
    __syncthreads();
    if (tid == 0) {
        float mm = red[0];
        for (int i = 1; i < 8; i++) mm = fmaxf(mm, red[i]);
        bmax = mm;
    }
    __syncthreads();

    float psum = 0.f;
    for (int s = tid; s <= LL; s += 256) {
        float e = expf(sc[s] - bmax);
        sc[s] = e;
        psum += e;
    }
    #pragma unroll
    for (int o = 16; o > 0; o >>= 1) psum += __shfl_xor_sync(FULLMASK, psum, o);
    if ((tid & 31) == 0) red[tid>>5] = psum;
    __syncthreads();
    if (tid == 0) {
        float ss = 0.f;
        for (int i = 0; i < 8; i++) ss += red[i];
        bsum = ss;
    }
    __syncthreads();

    int d = tid & 63, stripe = tid >> 6;
    float acc = 0.f;
    for (int s = stripe; s <= LL; s += 4) {
        float w = sc[s];
        float vv = (s == 0) ? svr[b*HH + n*HDIM + d]
                            : v[((size_t)b*LL + s-1)*HH + n*HDIM + d];
        acc += w*vv;
    }
    part[stripe][d] = acc;
    __syncthreads();
    if (tid < HDIM) {
        float r = (part[0][tid] + part[1][tid] + part[2][tid] + part[3][tid]) / bsum;
        satt[b*HH + n*HDIM + tid] = r;
    }
}

// ---------------- zero out masked node rows ----------------
__global__ void mask_nodes_kernel(float* __restrict__ nodes, const int* __restrict__ mask)
{
    int idx = blockIdx.x * blockDim.x + threadIdx.x;
    if (idx >= BB*LL*HH) return;
    if (mask[idx / HH]) nodes[idx] = 0.f;
}

// ---------------- build ft = [relay, nodes[b, positions[b]]] ----------------
__global__ void gather_ft_kernel(const float* __restrict__ relay, const float* __restrict__ nodes,
                                 const int* __restrict__ pos, float* __restrict__ ft)
{
    int i = blockIdx.x * blockDim.x + threadIdx.x;
    if (i >= BB*2*HH) return;
    int b = i / (2*HH), c = i % (2*HH);
    ft[i] = (c < HH) ? relay[b*HH + c]
                     : nodes[((size_t)b*LL + pos[b])*HH + (c - HH)];
}

// ---------------- host orchestration ----------------
extern "C" void kernel_launch(void* const* d_in, const int* in_sizes, int n_in,
                              void* d_out, int out_size)
{
    const int*   src       = (const int*)d_in[0];
    const int*   positions = (const int*)d_in[1];
    const float* emb       = (const float*)d_in[2];
    const float* pos_table = (const float*)d_in[3];
    const float* norm_g    = (const float*)d_in[4];
    const float* norm_b    = (const float*)d_in[5];
    const float* pw_w1     = (const float*)d_in[6];
    const float* pw_b1     = (const float*)d_in[7];
    const float* pw_w2     = (const float*)d_in[8];
    const float* pw_b2     = (const float*)d_in[9];
    const float* pw_g      = (const float*)d_in[10];
    const float* pw_bn     = (const float*)d_in[11];
    const float* ring_wq   = (const float*)d_in[12];
    const float* ring_bq   = (const float*)d_in[13];
    const float* ring_wk   = (const float*)d_in[14];
    const float* ring_bk   = (const float*)d_in[15];
    const float* ring_wv   = (const float*)d_in[16];
    const float* ring_bv   = (const float*)d_in[17];
    const float* ring_wo   = (const float*)d_in[18];
    const float* ring_bo   = (const float*)d_in[19];
    const float* star_wq   = (const float*)d_in[20];
    const float* star_bq   = (const float*)d_in[21];
    const float* star_wk   = (const float*)d_in[22];
    const float* star_bk   = (const float*)d_in[23];
    const float* star_wv   = (const float*)d_in[24];
    const float* star_bv   = (const float*)d_in[25];
    const float* star_wo   = (const float*)d_in[26];
    const float* star_bo   = (const float*)d_in[27];
    const float* head_w1   = (const float*)d_in[28];
    const float* head_b1   = (const float*)d_in[29];
    const float* head_w2   = (const float*)d_in[30];
    const float* head_b2   = (const float*)d_in[31];
    float* out = (float*)d_out;

    float *nodes, *h, *q, *k, *v, *att, *ff, *relay, *rk, *rv, *sq, *skr, *svr, *satt, *ft, *hid;
    int* maskp;
    cudaGetSymbolAddress((void**)&nodes, g_nodes);
    cudaGetSymbolAddress((void**)&h,     g_h);
    cudaGetSymbolAddress((void**)&q,     g_q);
    cudaGetSymbolAddress((void**)&k,     g_k);
    cudaGetSymbolAddress((void**)&v,     g_v);
    cudaGetSymbolAddress((void**)&att,   g_att);
    cudaGetSymbolAddress((void**)&ff,    g_ff);
    cudaGetSymbolAddress((void**)&relay, g_relay);
    cudaGetSymbolAddress((void**)&rk,    g_rk);
    cudaGetSymbolAddress((void**)&rv,    g_rv);
    cudaGetSymbolAddress((void**)&sq,    g_sq);
    cudaGetSymbolAddress((void**)&skr,   g_skr);
    cudaGetSymbolAddress((void**)&svr,   g_svr);
    cudaGetSymbolAddress((void**)&satt,  g_satt);
    cudaGetSymbolAddress((void**)&ft,    g_ft);
    cudaGetSymbolAddress((void**)&hid,   g_hid);
    cudaGetSymbolAddress((void**)&maskp, g_mask);

    const int M = BB*LL;                 // 8192
    dim3 gemm_wide(DIN/128, M/128);      // (24, 64)
    dim3 gemm_h(HH/128, M/128);          // (6, 64)

    embed_kernel<<<(BB*LL*HH + 255)/256, 256>>>(src, emb, pos_table, nodes);
    mask_kernel<<<(BB*LL + 255)/256, 256>>>(src, maskp);
    relay_mean_kernel<<<dim3(BB, 3), 256>>>(nodes, relay);

    for (int i = 0; i < 2; i++) {
        const float* w1 = pw_w1 + (size_t)i*DIN*HH;
        const float* b1 = pw_b1 + i*DIN;
        const float* w2 = pw_w2 + (size_t)i*HH*DIN;
        const float* b2 = pw_b2 + i*HH;
        const float* rwq = ring_wq + (size_t)i*HH*HH; const float* rbq = ring_bq + i*HH;
        const float* rwk = ring_wk + (size_t)i*HH*HH; const float* rbk = ring_bk + i*HH;
        const float* rwv = ring_wv + (size_t)i*HH*HH; const float* rbv = ring_bv + i*HH;
        const float* rwo = ring_wo + (size_t)i*HH*HH; const float* rbo = ring_bo + i*HH;
        const float* swq = star_wq + (size_t)i*HH*HH; const float* sbq = star_bq + i*HH;
        const float* swk = star_wk + (size_t)i*HH*HH; const float* sbk = star_bk + i*HH;
        const float* swv = star_wv + (size_t)i*HH*HH; const float* sbv = star_bv + i*HH;
        const float* swo = star_wo + (size_t)i*HH*HH; const float* sbo = star_bo + i*HH;

        // PWFF: ff = relu(nodes@w1^T + b1); h = LN(ff@w2^T + b2 + nodes)
        gemm_nt_kernel<<<gemm_wide, 256>>>(nodes, w1, b1, ff, M, DIN, HH, 1);
        gemm_nt_kernel<<<gemm_h,    256>>>(ff, w2, b2, h, M, HH, DIN, 0);
        ln_kernel<<<M, 256>>>(h, nodes, pw_g + i*HH, pw_bn + i*HH, h, 0);

        // ring q/k/v from h; relay k/v
        gemm_nt_kernel<<<gemm_h, 256>>>(h, rwq, rbq, q, M, HH, HH, 0);
        gemm_nt_kernel<<<gemm_h, 256>>>(h, rwk, rbk, k, M, HH, HH, 0);
        gemm_nt_kernel<<<gemm_h, 256>>>(h, rwv, rbv, v, M, HH, HH, 0);
        small_nt_kernel<<<(BB*HH + 7)/8, 256>>>(relay, rwk, rbk, rk, BB, HH, HH, HH, 0);
        small_nt_kernel<<<(BB*HH + 7)/8, 256>>>(relay, rwv, rbv, rv, BB, HH, HH, HH, 0);

        ring_attn_kernel<<<(BB*LL*NHEAD)/8, 256>>>(q, k, v, rk, rv, att);

        // ring output proj -> LN -> leaky -> nodes
        gemm_nt_kernel<<<gemm_h, 256>>>(att, rwo, rbo, q, M, HH, HH, 0);
        ln_kernel<<<M, 256>>>(q, (const float*)0, norm_g + i*HH, norm_b + i*HH, nodes, 1);

        // star attention: single relay query over [relay; nodes]
        small_nt_kernel<<<(BB*HH + 7)/8, 256>>>(relay, swq, sbq, sq,  BB, HH, HH, HH, 0);
        small_nt_kernel<<<(BB*HH + 7)/8, 256>>>(relay, swk, sbk, skr, BB, HH, HH, HH, 0);
        small_nt_kernel<<<(BB*HH + 7)/8, 256>>>(relay, swv, sbv, svr, BB, HH, HH, HH, 0);
        gemm_nt_kernel<<<gemm_h, 256>>>(nodes, swk, sbk, k, M, HH, HH, 0);
        gemm_nt_kernel<<<gemm_h, 256>>>(nodes, swv, sbv, v, M, HH, HH, 0);
        star_attn_kernel<<<BB*NHEAD, 256>>>(sq, skr, svr, k, v, maskp, satt);
        small_nt_kernel<<<(BB*HH + 7)/8, 256>>>(satt, swo, sbo, relay, BB, HH, HH, HH, 2);

        mask_nodes_kernel<<<(BB*LL*HH + 255)/256, 256>>>(nodes, maskp);
    }

    // heads: ft=[relay, target]; out[(3b+j), :] = head_j(ft[b])
    gather_ft_kernel<<<(BB*2*HH + 255)/256, 256>>>(relay, nodes, positions, ft);
    for (int j = 0; j < 3; j++) {
        small_nt_kernel<<<(BB*1024 + 7)/8, 256>>>(ft, head_w1 + (size_t)j*1024*2*HH,
                                                  head_b1 + j*1024, hid + (size_t)j*BB*1024,
                                                  BB, 1024, 2*HH, 1024, 1);
        small_nt_kernel<<<(BB*5000 + 7)/8, 256>>>(hid + (size_t)j*BB*1024,
                                                  head_w2 + (size_t)j*5000*1024,
                                                  head_b2 + j*5000, out + j*5000,
                                                  BB, 5000, 1024, 15000, 0);
    }
}

// round 4
// speedup vs baseline: 2.9009x; 2.9009x over previous
#include <cuda_runtime.h>
#include <cuda_bf16.h>
#include <math.h>
#include <stdint.h>

#define BB 8
#define LL 1024
#define HH 768
#define NHEAD 12
#define HDIM 64
#define DIN 3072
#define ATT_SCALE 0.125f
#define FULLMASK 0xffffffffu

typedef __nv_bfloat16 bf16;

// ---------------- scratch (device globals; no allocations allowed) ----------------
__device__ float g_nodes[BB*LL*HH];
__device__ float g_h[BB*LL*HH];
__device__ float g_q[BB*LL*HH];
__device__ float g_k[BB*LL*HH];
__device__ float g_v[BB*LL*HH];
__device__ float g_relay[BB*HH];
__device__ float g_rk[BB*HH];
__device__ float g_rv[BB*HH];
__device__ float g_sq[BB*HH];
__device__ float g_skr[BB*HH];
__device__ float g_svr[BB*HH];
__device__ float g_satt[BB*HH];
__device__ float g_ft[BB*2*HH];
__device__ float g_hid[3*BB*1024];
__device__ int   g_mask[BB*LL];

// bf16 hi/lo activation buffers
__device__ bf16 g_nodes_h[BB*LL*HH];
__device__ bf16 g_nodes_l[BB*LL*HH];
__device__ bf16 g_h_h[BB*LL*HH];
__device__ bf16 g_h_l[BB*LL*HH];
__device__ bf16 g_att_h[BB*LL*HH];
__device__ bf16 g_att_l[BB*LL*HH];
__device__ bf16 g_ff_h[BB*LL*DIN];
__device__ bf16 g_ff_l[BB*LL*DIN];

// bf16 hi/lo weight buffers (reused per layer)
__device__ bf16 g_w1_h[DIN*HH];
__device__ bf16 g_w1_l[DIN*HH];
__device__ bf16 g_w2_h[HH*DIN];
__device__ bf16 g_w2_l[HH*DIN];
__device__ bf16 g_wq_h[HH*HH], g_wq_l[HH*HH];
__device__ bf16 g_wk_h[HH*HH], g_wk_l[HH*HH];
__device__ bf16 g_wv_h[HH*HH], g_wv_l[HH*HH];
__device__ bf16 g_wo_h[HH*HH], g_wo_l[HH*HH];
__device__ bf16 g_sk_h[HH*HH], g_sk_l[HH*HH];
__device__ bf16 g_sv_h[HH*HH], g_sv_l[HH*HH];

// ---------------- helpers ----------------
__device__ __forceinline__ uint32_t smem_u32(const void* p) {
    return (uint32_t)__cvta_generic_to_shared(p);
}

#define CP16(dst, src) asm volatile("cp.async.cg.shared.global [%0], [%1], 16;" :: "r"(dst), "l"(src))

#define LDSM4(R, addr) \
    asm volatile("ldmatrix.sync.aligned.m8n8.x4.shared.b16 {%0,%1,%2,%3}, [%4];" \
                 : "=r"((R)[0]), "=r"((R)[1]), "=r"((R)[2]), "=r"((R)[3]) : "r"(addr))

#define MMA16816(D, A, B0, B1) \
    asm volatile("mma.sync.aligned.m16n8k16.row.col.f32.bf16.bf16.f32 " \
                 "{%0,%1,%2,%3}, {%4,%5,%6,%7}, {%8,%9}, {%0,%1,%2,%3};" \
                 : "+f"((D)[0]), "+f"((D)[1]), "+f"((D)[2]), "+f"((D)[3]) \
                 : "r"((A)[0]), "r"((A)[1]), "r"((A)[2]), "r"((A)[3]), "r"(B0), "r"(B1))

__device__ __forceinline__ void split_store(float v, bf16* h, bf16* l, size_t idx) {
    bf16 hi = __float2bfloat16(v);
    h[idx] = hi;
    l[idx] = __float2bfloat16(v - __bfloat162float(hi));
}

// ---------------- fp32 -> hi/lo bf16 split ----------------
__global__ void split_kernel(const float* __restrict__ x, bf16* __restrict__ h,
                             bf16* __restrict__ l, int n)
{
    int i = blockIdx.x * blockDim.x + threadIdx.x;
    if (i >= n) return;
    float v = x[i];
    bf16 hi = __float2bfloat16(v);
    h[i] = hi;
    l[i] = __float2bfloat16(v - __bfloat162float(hi));
}

// ---------------- embedding + positional (fp32 + hi/lo) ----------------
__global__ void embed_kernel(const int* __restrict__ src, const float* __restrict__ emb,
                             const float* __restrict__ pos, float* __restrict__ nodes,
                             bf16* __restrict__ nh, bf16* __restrict__ nl)
{
    int idx = blockIdx.x * blockDim.x + threadIdx.x;
    if (idx >= BB*LL*HH) return;
    int hh = idx % HH;
    int bl = idx / HH;
    int l  = bl % LL;
    int j  = hh >> 8;
    int d  = hh & 255;
    int tok = src[bl*3 + j];
    float v = emb[tok*256 + d] + pos[l*HH + hh];
    nodes[idx] = v;
    split_store(v, nh, nl, idx);
}

__global__ void mask_kernel(const int* __restrict__ src, int* __restrict__ mask)
{
    int i = blockIdx.x * blockDim.x + threadIdx.x;
    if (i < BB*LL) mask[i] = (src[i*3] == 0) ? 1 : 0;
}

__global__ void relay_zero_kernel(float* __restrict__ relay)
{
    int i = blockIdx.x * 256 + threadIdx.x;
    if (i < BB*HH) relay[i] = 0.f;
}

__global__ void relay_partial_kernel(const float* __restrict__ nodes, float* __restrict__ relay)
{
    int b  = blockIdx.x;
    int hh = blockIdx.y * 256 + threadIdx.x;
    int l0 = blockIdx.z * 64;
    const float* p = nodes + ((size_t)b*LL + l0)*HH + hh;
    float s = 0.f;
    #pragma unroll 8
    for (int l = 0; l < 64; l++) s += p[(size_t)l*HH];
    atomicAdd(&relay[b*HH + hh], s * (1.0f/1024.0f));
}

// ---------------- tensor-core GEMM (bf16x3): C = A*W^T + bias ----------------
// A: hi/lo [M,K] bf16 row-major; W: hi/lo [N,K] bf16 row-major.
// Block 128x64x32, 8 warps (4m x 2n), warp tile 32x32. K mult of 32, M mult 128, N mult 64.
// outpair=0: Cf fp32;  outpair=1: Ch/Cl bf16 pair.  act: 0 none, 1 relu.
__global__ void __launch_bounds__(256, 2) gemm_bf3(
    const bf16* __restrict__ Ah, const bf16* __restrict__ Al,
    const bf16* __restrict__ Wh, const bf16* __restrict__ Wl,
    const float* __restrict__ bias,
    float* __restrict__ Cf, bf16* __restrict__ Ch, bf16* __restrict__ Cl,
    int M, int N, int K, int act, int outpair)
{
    __shared__ __align__(16) bf16 sAh[2][4096];
    __shared__ __align__(16) bf16 sAl[2][4096];
    __shared__ __align__(16) bf16 sWh[2][2048];
    __shared__ __align__(16) bf16 sWl[2][2048];

    const int tid = threadIdx.x;
    const int bm = blockIdx.y * 128;
    const int bn = blockIdx.x * 64;
    const int lane = tid & 31;
    const int warp = tid >> 5;
    const int wm = warp & 3;    // 4 warps along M (32 rows each)
    const int wn = warp >> 2;   // 2 warps along N (32 cols each)

    const int niter = K >> 5;

    // ldmatrix byte offsets within a stage buffer
    const int li = lane >> 3;
    const int lr = lane & 7;
    uint32_t aoff[2][2], woff[2][2];
    #pragma unroll
    for (int mi = 0; mi < 2; mi++)
        #pragma unroll
        for (int ks = 0; ks < 2; ks++) {
            int row = wm*32 + mi*16 + ((li & 1) << 3) + lr;
            int c   = (ks << 1) + (li >> 1);
            aoff[mi][ks] = (uint32_t)((row*32 + ((c ^ ((row >> 1) & 3)) << 3)) * 2);
        }
    #pragma unroll
    for (int nj = 0; nj < 2; nj++)
        #pragma unroll
        for (int ks = 0; ks < 2; ks++) {
            int row = wn*32 + nj*16 + ((li >> 1) << 3) + lr;
            int c   = (ks << 1) + (li & 1);
            woff[nj][ks] = (uint32_t)((row*32 + ((c ^ ((row >> 1) & 3)) << 3)) * 2);
        }

    // global load coordinates (16B chunks)
    const int ar0 = tid >> 2,        ac0 = tid & 3;          // A chunk set 0
    const int ar1 = (tid + 256) >> 2, ac1 = (tid + 256) & 3;  // A chunk set 1
    const uint32_t asw0 = (uint32_t)((ar0*32 + ((ac0 ^ ((ar0 >> 1) & 3)) << 3)) * 2);
    const uint32_t asw1 = (uint32_t)((ar1*32 + ((ac1 ^ ((ar1 >> 1) & 3)) << 3)) * 2);
    const int wr = tid >> 2, wc = tid & 3;
    const uint32_t wsw = (uint32_t)((wr*32 + ((wc ^ ((wr >> 1) & 3)) << 3)) * 2);

    const uint32_t bAh0 = smem_u32(&sAh[0][0]);
    const uint32_t bAl0 = smem_u32(&sAl[0][0]);
    const uint32_t bWh0 = smem_u32(&sWh[0][0]);
    const uint32_t bWl0 = smem_u32(&sWl[0][0]);

    #define LOAD_STAGE(s, kt) do { \
        uint32_t aB = (s) ? 8192u : 0u; \
        uint32_t wB = (s) ? 4096u : 0u; \
        CP16(bAh0 + aB + asw0, Ah + (size_t)(bm + ar0)*K + (kt) + ac0*8); \
        CP16(bAh0 + aB + asw1, Ah + (size_t)(bm + ar1)*K + (kt) + ac1*8); \
        CP16(bAl0 + aB + asw0, Al + (size_t)(bm + ar0)*K + (kt) + ac0*8); \
        CP16(bAl0 + aB + asw1, Al + (size_t)(bm + ar1)*K + (kt) + ac1*8); \
        CP16(bWh0 + wB + wsw,  Wh + (size_t)(bn + wr)*K + (kt) + wc*8); \
        CP16(bWl0 + wB + wsw,  Wl + (size_t)(bn + wr)*K + (kt) + wc*8); \
        asm volatile("cp.async.commit_group;"); \
    } while (0)

    float acc[2][4][4];
    #pragma unroll
    for (int mi = 0; mi < 2; mi++)
        #pragma unroll
        for (int nf = 0; nf < 4; nf++)
            #pragma unroll
            for (int e = 0; e < 4; e++) acc[mi][nf][e] = 0.f;

    LOAD_STAGE(0, 0);

    for (int it = 0; it < niter; it++) {
        if (it + 1 < niter) {
            LOAD_STAGE((it + 1) & 1, (it + 1) * 32);
            asm volatile("cp.async.wait_group 1;");
        } else {
            asm volatile("cp.async.wait_group 0;");
        }
        __syncthreads();

        const int s = it & 1;
        const uint32_t cAh = bAh0 + (s ? 8192u : 0u);
        const uint32_t cAl = bAl0 + (s ? 8192u : 0u);
        const uint32_t cWh = bWh0 + (s ? 4096u : 0u);
        const uint32_t cWl = bWl0 + (s ? 4096u : 0u);

        #pragma unroll
        for (int ks = 0; ks < 2; ks++) {
            uint32_t fah[2][4], fal[2][4];
            LDSM4(fah[0], cAh + aoff[0][ks]);
            LDSM4(fah[1], cAh + aoff[1][ks]);
            LDSM4(fal[0], cAl + aoff[0][ks]);
            LDSM4(fal[1], cAl + aoff[1][ks]);
            uint32_t t4[4];
            uint32_t fwh[4][2], fwl[4][2];
            LDSM4(t4, cWh + woff[0][ks]);
            fwh[0][0]=t4[0]; fwh[0][1]=t4[1]; fwh[1][0]=t4[2]; fwh[1][1]=t4[3];
            LDSM4(t4, cWh + woff[1][ks]);
            fwh[2][0]=t4[0]; fwh[2][1]=t4[1]; fwh[3][0]=t4[2]; fwh[3][1]=t4[3];
            LDSM4(t4, cWl + woff[0][ks]);
            fwl[0][0]=t4[0]; fwl[0][1]=t4[1]; fwl[1][0]=t4[2]; fwl[1][1]=t4[3];
            LDSM4(t4, cWl + woff[1][ks]);
            fwl[2][0]=t4[0]; fwl[2][1]=t4[1]; fwl[3][0]=t4[2]; fwl[3][1]=t4[3];

            #pragma unroll
            for (int mi = 0; mi < 2; mi++)
                #pragma unroll
                for (int nf = 0; nf < 4; nf++) {
                    MMA16816(acc[mi][nf], fah[mi], fwh[nf][0], fwh[nf][1]);
                    MMA16816(acc[mi][nf], fah[mi], fwl[nf][0], fwl[nf][1]);
                    MMA16816(acc[mi][nf], fal[mi], fwh[nf][0], fwh[nf][1]);
                }
        }
        __syncthreads();
    }

    // epilogue
    const int em = lane >> 2;
    const int en = (lane & 3) << 1;
    #pragma unroll
    for (int mi = 0; mi < 2; mi++) {
        #pragma unroll
        for (int nf = 0; nf < 4; nf++) {
            int col = bn + wn*32 + nf*8 + en;
            float b0 = bias[col], b1 = bias[col + 1];
            #pragma unroll
            for (int half = 0; half < 2; half++) {
                int row = bm + wm*32 + mi*16 + em + half*8;
                float v0 = acc[mi][nf][half*2 + 0] + b0;
                float v1 = acc[mi][nf][half*2 + 1] + b1;
                if (act == 1) { v0 = fmaxf(v0, 0.f); v1 = fmaxf(v1, 0.f); }
                size_t o = (size_t)row*N + col;
                if (outpair) {
                    bf16 h0 = __float2bfloat16(v0);
                    bf16 h1 = __float2bfloat16(v1);
                    __nv_bfloat162 hp, lp;
                    hp.x = h0; hp.y = h1;
                    lp.x = __float2bfloat16(v0 - __bfloat162float(h0));
                    lp.y = __float2bfloat16(v1 - __bfloat162float(h1));
                    *(__nv_bfloat162*)(Ch + o) = hp;
                    *(__nv_bfloat162*)(Cl + o) = lp;
                } else {
                    float2 r; r.x = v0; r.y = v1;
                    *(float2*)(Cf + o) = r;
                }
            }
        }
    }
    #undef LOAD_STAGE
}

// ---------------- small GEMM (warp-per-output) ----------------
__global__ void small_nt_kernel(const float* __restrict__ A, const float* __restrict__ W,
                                const float* __restrict__ bias, float* __restrict__ C,
                                int M, int N, int K, int ldc, int act)
{
    int w = (blockIdx.x * blockDim.x + threadIdx.x) >> 5;
    int lane = threadIdx.x & 31;
    if (w >= M*N) return;
    int m = w / N, n = w % N;
    const float4* a  = (const float4*)(A + (size_t)m*K);
    const float4* wr = (const float4*)(W + (size_t)n*K);
    float s = 0.f;
    int K4 = K >> 2;
    for (int c = lane; c < K4; c += 32) {
        float4 av = a[c], wv = wr[c];
        s += av.x*wv.x + av.y*wv.y + av.z*wv.z + av.w*wv.w;
    }
    #pragma unroll
    for (int o = 16; o > 0; o >>= 1) s += __shfl_xor_sync(FULLMASK, s, o);
    if (lane == 0) {
        s += bias[n];
        if (act == 1) s = fmaxf(s, 0.f);
        else if (act == 2 && s < 0.f) s *= 0.01f;
        C[(size_t)m*ldc + n] = s;
    }
}

// ---------------- LayerNorm (row=768) with optional residual/leaky + hi/lo out ----------------
__global__ void __launch_bounds__(256) ln_kernel(
    const float* __restrict__ X, const float* __restrict__ RES,
    const float* __restrict__ g, const float* __restrict__ b,
    float* __restrict__ out, bf16* __restrict__ oh, bf16* __restrict__ ol, int leaky)
{
    __shared__ float shs[8], shs2[8];
    __shared__ float smean, sinv;
    int row = blockIdx.x;
    int tid = threadIdx.x;
    const float* x = X + (size_t)row*HH;
    float v0 = x[tid], v1 = x[tid+256], v2 = x[tid+512];
    if (RES) {
        const float* r = RES + (size_t)row*HH;
        v0 += r[tid]; v1 += r[tid+256]; v2 += r[tid+512];
    }
    float s  = v0+v1+v2;
    float s2 = v0*v0 + v1*v1 + v2*v2;
    #pragma unroll
    for (int o = 16; o > 0; o >>= 1) {
        s  += __shfl_xor_sync(FULLMASK, s, o);
        s2 += __shfl_xor_sync(FULLMASK, s2, o);
    }
    if ((tid & 31) == 0) { shs[tid>>5] = s; shs2[tid>>5] = s2; }
    __syncthreads();
    if (tid == 0) {
        float ts = 0.f, ts2 = 0.f;
        for (int i = 0; i < 8; i++) { ts += shs[i]; ts2 += shs2[i]; }
        float mean = ts * (1.0f/768.0f);
        float var  = ts2 * (1.0f/768.0f) - mean*mean;
        smean = mean;
        sinv  = rsqrtf(var + 1e-5f);
    }
    __syncthreads();
    float mean = smean, inv = sinv;
    size_t base = (size_t)row*HH;
    float y0 = (v0-mean)*inv*g[tid]     + b[tid];
    float y1 = (v1-mean)*inv*g[tid+256] + b[tid+256];
    float y2 = (v2-mean)*inv*g[tid+512] + b[tid+512];
    if (leaky) {
        if (y0 < 0.f) y0 *= 0.01f;
        if (y1 < 0.f) y1 *= 0.01f;
        if (y2 < 0.f) y2 *= 0.01f;
    }
    out[base+tid] = y0; out[base+tid+256] = y1; out[base+tid+512] = y2;
    if (oh) {
        split_store(y0, oh, ol, base+tid);
        split_store(y1, oh, ol, base+tid+256);
        split_store(y2, oh, ol, base+tid+512);
    }
}

// ---------------- ring attention (outputs hi/lo bf16) ----------------
__global__ void __launch_bounds__(256) ring_attn_kernel(
    const float* __restrict__ q, const float* __restrict__ k, const float* __restrict__ v,
    const float* __restrict__ rk, const float* __restrict__ rv,
    bf16* __restrict__ ah, bf16* __restrict__ al)
{
    int gw = (blockIdx.x * 256 + threadIdx.x) >> 5;
    int lane = threadIdx.x & 31;
    if (gw >= BB*LL*NHEAD) return;
    int n  = gw % NHEAD;
    int bl = gw / NHEAD;
    int l  = bl % LL;
    int b  = bl / LL;
    const float* qp = q + (size_t)bl*HH + n*HDIM;
    float q0 = qp[lane], q1 = qp[lane+32];

    float s[4];
    #pragma unroll
    for (int w = 0; w < 3; w++) {
        int ll = l + w - 1;
        float d = 0.f;
        if (ll >= 0 && ll < LL) {
            const float* kp = k + ((size_t)b*LL + ll)*HH + n*HDIM;
            d = q0*kp[lane] + q1*kp[lane+32];
        }
        #pragma unroll
        for (int o = 16; o > 0; o >>= 1) d += __shfl_xor_sync(FULLMASK, d, o);
        s[w] = d;
    }
    {
        const float* kp = rk + b*HH + n*HDIM;
        float d = q0*kp[lane] + q1*kp[lane+32];
        #pragma unroll
        for (int o = 16; o > 0; o >>= 1) d += __shfl_xor_sync(FULLMASK, d, o);
        s[3] = d;
    }
    float sc0 = s[0]*ATT_SCALE, sc1 = s[1]*ATT_SCALE, sc2 = s[2]*ATT_SCALE, sc3 = s[3]*ATT_SCALE;
    float m = fmaxf(fmaxf(sc0, sc1), fmaxf(sc2, sc3));
    float e0 = expf(sc0-m), e1 = expf(sc1-m), e2 = expf(sc2-m), e3 = expf(sc3-m);
    float inv = 1.f / (e0+e1+e2+e3);
    float a0 = e0*inv, a1 = e1*inv, a2 = e2*inv, a3 = e3*inv;

    const float* rvp = rv + b*HH + n*HDIM;
    float o0 = a3 * rvp[lane];
    float o1 = a3 * rvp[lane+32];
    float aw[3] = {a0, a1, a2};
    #pragma unroll
    for (int w = 0; w < 3; w++) {
        int ll = l + w - 1;
        if (ll >= 0 && ll < LL) {
            const float* vp = v + ((size_t)b*LL + ll)*HH + n*HDIM;
            o0 += aw[w] * vp[lane];
            o1 += aw[w] * vp[lane+32];
        }
    }
    size_t o = (size_t)bl*HH + n*HDIM;
    split_store(o0, ah, al, o + lane);
    split_store(o1, ah, al, o + lane + 32);
}

// ---------------- star attention: block per (b,head) ----------------
__global__ void __launch_bounds__(256) star_attn_kernel(
    const float* __restrict__ sq, const float* __restrict__ skr, const float* __restrict__ svr,
    const float* __restrict__ k, const float* __restrict__ v, const int* __restrict__ mask,
    float* __restrict__ satt)
{
    __shared__ float sc[LL+1];
    __shared__ float qv[HDIM];
    __shared__ float red[8];
    __shared__ float bmax, bsum;
    __shared__ float part[4][HDIM];
    int b = blockIdx.x / NHEAD;
    int n = blockIdx.x % NHEAD;
    int tid = threadIdx.x;

    if (tid < HDIM) qv[tid] = sq[b*HH + n*HDIM + tid];
    __syncthreads();

    for (int s = tid; s <= LL; s += 256) {
        float d;
        if (s > 0 && mask[b*LL + s-1]) d = -INFINITY;
        else {
            const float* kp = (s == 0) ? (skr + b*HH + n*HDIM)
                                       : (k + ((size_t)b*LL + s-1)*HH + n*HDIM);
            float acc = 0.f;
            #pragma unroll 16
            for (int dd = 0; dd < HDIM; dd++) acc += qv[dd]*kp[dd];
            d = acc * ATT_SCALE;
        }
        sc[s] = d;
    }
    __syncthreads();

    float m = -INFINITY;
    for (int s = tid; s <= LL; s += 256) m = fmaxf(m, sc[s]);
    #pragma unroll
    for (int o = 16; o > 0; o >>= 1) m = fmaxf(m, __shfl_xor_sync(FULLMASK, m, o));
    if ((tid & 31) == 0) red[tid>>5] = m;
    __syncthreads();
    if (tid == 0) {
        float mm = red[0];
        for (int i = 1; i < 8; i++) mm = fmaxf(mm, red[i]);
        bmax = mm;
    }
    __syncthreads();

    float psum = 0.f;
    for (int s = tid; s <= LL; s += 256) {
        float e = expf(sc[s] - bmax);
        sc[s] = e;
        psum += e;
    }
    #pragma unroll
    for (int o = 16; o > 0; o >>= 1) psum += __shfl_xor_sync(FULLMASK, psum, o);
    if ((tid & 31) == 0) red[tid>>5] = psum;
    __syncthreads();
    if (tid == 0) {
        float ss = 0.f;
        for (int i = 0; i < 8; i++) ss += red[i];
        bsum = ss;
    }
    __syncthreads();

    int d = tid & 63, stripe = tid >> 6;
    float acc = 0.f;
    for (int s = stripe; s <= LL; s += 4) {
        float w = sc[s];
        float vv = (s == 0) ? svr[b*HH + n*HDIM + d]
                            : v[((size_t)b*LL + s-1)*HH + n*HDIM + d];
        acc += w*vv;
    }
    part[stripe][d] = acc;
    __syncthreads();
    if (tid < HDIM) {
        float r = (part[0][tid] + part[1][tid] + part[2][tid] + part[3][tid]) / bsum;
        satt[b*HH + n*HDIM + tid] = r;
    }
}

// ---------------- zero out masked node rows (fp32 + hi/lo) ----------------
__global__ void mask_nodes_kernel(float* __restrict__ nodes, bf16* __restrict__ nh,
                                  bf16* __restrict__ nl, const int* __restrict__ mask)
{
    int idx = blockIdx.x * blockDim.x + threadIdx.x;
    if (idx >= BB*LL*HH) return;
    if (mask[idx / HH]) {
        nodes[idx] = 0.f;
        nh[idx] = __float2bfloat16(0.f);
        nl[idx] = __float2bfloat16(0.f);
    }
}

// ---------------- build ft = [relay, nodes[b, positions[b]]] ----------------
__global__ void gather_ft_kernel(const float* __restrict__ relay, const float* __restrict__ nodes,
                                 const int* __restrict__ pos, float* __restrict__ ft)
{
    int i = blockIdx.x * blockDim.x + threadIdx.x;
    if (i >= BB*2*HH) return;
    int b = i / (2*HH), c = i % (2*HH);
    ft[i] = (c < HH) ? relay[b*HH + c]
                     : nodes[((size_t)b*LL + pos[b])*HH + (c - HH)];
}

// ---------------- host orchestration ----------------
extern "C" void kernel_launch(void* const* d_in, const int* in_sizes, int n_in,
                              void* d_out, int out_size)
{
    const int*   src       = (const int*)d_in[0];
    const int*   positions = (const int*)d_in[1];
    const float* emb       = (const float*)d_in[2];
    const float* pos_table = (const float*)d_in[3];
    const float* norm_g    = (const float*)d_in[4];
    const float* norm_b    = (const float*)d_in[5];
    const float* pw_w1     = (const float*)d_in[6];
    const float* pw_b1     = (const float*)d_in[7];
    const float* pw_w2     = (const float*)d_in[8];
    const float* pw_b2     = (const float*)d_in[9];
    const float* pw_g      = (const float*)d_in[10];
    const float* pw_bn     = (const float*)d_in[11];
    const float* ring_wq   = (const float*)d_in[12];
    const float* ring_bq   = (const float*)d_in[13];
    const float* ring_wk   = (const float*)d_in[14];
    const float* ring_bk   = (const float*)d_in[15];
    const float* ring_wv   = (const float*)d_in[16];
    const float* ring_bv   = (const float*)d_in[17];
    const float* ring_wo   = (const float*)d_in[18];
    const float* ring_bo   = (const float*)d_in[19];
    const float* star_wq   = (const float*)d_in[20];
    const float* star_bq   = (const float*)d_in[21];
    const float* star_wk   = (const float*)d_in[22];
    const float* star_bk   = (const float*)d_in[23];
    const float* star_wv   = (const float*)d_in[24];
    const float* star_bv   = (const float*)d_in[25];
    const float* star_wo   = (const float*)d_in[26];
    const float* star_bo   = (const float*)d_in[27];
    const float* head_w1   = (const float*)d_in[28];
    const float* head_b1   = (const float*)d_in[29];
    const float* head_w2   = (const float*)d_in[30];
    const float* head_b2   = (const float*)d_in[31];
    float* out = (float*)d_out;

    float *nodes, *h, *q, *k, *v, *relay, *rk, *rv, *sq, *skr, *svr, *satt, *ft, *hid;
    int* maskp;
    bf16 *nodes_h, *nodes_l, *h_h, *h_l, *att_h, *att_l, *ff_h, *ff_l;
    bf16 *w1h, *w1l, *w2h, *w2l, *wqh, *wql, *wkh, *wkl, *wvh, *wvl, *woh, *wol, *skh, *skl, *svh, *svl;

    cudaGetSymbolAddress((void**)&nodes, g_nodes);
    cudaGetSymbolAddress((void**)&h,     g_h);
    cudaGetSymbolAddress((void**)&q,     g_q);
    cudaGetSymbolAddress((void**)&k,     g_k);
    cudaGetSymbolAddress((void**)&v,     g_v);
    cudaGetSymbolAddress((void**)&relay, g_relay);
    cudaGetSymbolAddress((void**)&rk,    g_rk);
    cudaGetSymbolAddress((void**)&rv,    g_rv);
    cudaGetSymbolAddress((void**)&sq,    g_sq);
    cudaGetSymbolAddress((void**)&skr,   g_skr);
    cudaGetSymbolAddress((void**)&svr,   g_svr);
    cudaGetSymbolAddress((void**)&satt,  g_satt);
    cudaGetSymbolAddress((void**)&ft,    g_ft);
    cudaGetSymbolAddress((void**)&hid,   g_hid);
    cudaGetSymbolAddress((void**)&maskp, g_mask);
    cudaGetSymbolAddress((void**)&nodes_h, g_nodes_h);
    cudaGetSymbolAddress((void**)&nodes_l, g_nodes_l);
    cudaGetSymbolAddress((void**)&h_h,   g_h_h);
    cudaGetSymbolAddress((void**)&h_l,   g_h_l);
    cudaGetSymbolAddress((void**)&att_h, g_att_h);
    cudaGetSymbolAddress((void**)&att_l, g_att_l);
    cudaGetSymbolAddress((void**)&ff_h,  g_ff_h);
    cudaGetSymbolAddress((void**)&ff_l,  g_ff_l);
    cudaGetSymbolAddress((void**)&w1h, g_w1_h); cudaGetSymbolAddress((void**)&w1l, g_w1_l);
    cudaGetSymbolAddress((void**)&w2h, g_w2_h); cudaGetSymbolAddress((void**)&w2l, g_w2_l);
    cudaGetSymbolAddress((void**)&wqh, g_wq_h); cudaGetSymbolAddress((void**)&wql, g_wq_l);
    cudaGetSymbolAddress((void**)&wkh, g_wk_h); cudaGetSymbolAddress((void**)&wkl, g_wk_l);
    cudaGetSymbolAddress((void**)&wvh, g_wv_h); cudaGetSymbolAddress((void**)&wvl, g_wv_l);
    cudaGetSymbolAddress((void**)&woh, g_wo_h); cudaGetSymbolAddress((void**)&wol, g_wo_l);
    cudaGetSymbolAddress((void**)&skh, g_sk_h); cudaGetSymbolAddress((void**)&skl, g_sk_l);
    cudaGetSymbolAddress((void**)&svh, g_sv_h); cudaGetSymbolAddress((void**)&svl, g_sv_l);

    const int M = BB*LL;                 // 8192
    dim3 gw_wide(DIN/64, M/128);         // (48, 64)
    dim3 gw_h(HH/64, M/128);             // (12, 64)

    embed_kernel<<<(BB*LL*HH + 255)/256, 256>>>(src, emb, pos_table, nodes, nodes_h, nodes_l);
    mask_kernel<<<(BB*LL + 255)/256, 256>>>(src, maskp);
    relay_zero_kernel<<<(BB*HH + 255)/256, 256>>>(relay);
    relay_partial_kernel<<<dim3(BB, 3, 16), 256>>>(nodes, relay);

    for (int i = 0; i < 2; i++) {
        const float* w1 = pw_w1 + (size_t)i*DIN*HH;
        const float* b1 = pw_b1 + i*DIN;
        const float* w2 = pw_w2 + (size_t)i*HH*DIN;
        const float* b2 = pw_b2 + i*HH;
        const float* rwq = ring_wq + (size_t)i*HH*HH; const float* rbq = ring_bq + i*HH;
        const float* rwk = ring_wk + (size_t)i*HH*HH; const float* rbk = ring_bk + i*HH;
        const float* rwv = ring_wv + (size_t)i*HH*HH; const float* rbv = ring_bv + i*HH;
        const float* rwo = ring_wo + (size_t)i*HH*HH; const float* rbo = ring_bo + i*HH;
        const float* swq = star_wq + (size_t)i*HH*HH; const float* sbq = star_bq + i*HH;
        const float* swk = star_wk + (size_t)i*HH*HH; const float* sbk = star_bk + i*HH;
        const float* swv = star_wv + (size_t)i*HH*HH; const float* sbv = star_bv + i*HH;
        const float* swo = star_wo + (size_t)i*HH*HH; const float* sbo = star_bo + i*HH;

        // split this layer's GEMM weights to bf16 hi/lo
        split_kernel<<<(DIN*HH + 255)/256, 256>>>(w1, w1h, w1l, DIN*HH);
        split_kernel<<<(HH*DIN + 255)/256, 256>>>(w2, w2h, w2l, HH*DIN);
        split_kernel<<<(HH*HH + 255)/256, 256>>>(rwq, wqh, wql, HH*HH);
        split_kernel<<<(HH*HH + 255)/256, 256>>>(rwk, wkh, wkl, HH*HH);
        split_kernel<<<(HH*HH + 255)/256, 256>>>(rwv, wvh, wvl, HH*HH);
        split_kernel<<<(HH*HH + 255)/256, 256>>>(rwo, woh, wol, HH*HH);
        split_kernel<<<(HH*HH + 255)/256, 256>>>(swk, skh, skl, HH*HH);
        split_kernel<<<(HH*HH + 255)/256, 256>>>(swv, svh, svl, HH*HH);

        // PWFF: ff = relu(nodes@w1^T + b1) -> bf16 pair; h = LN(ff@w2^T + b2 + nodes)
        gemm_bf3<<<gw_wide, 256>>>(nodes_h, nodes_l, w1h, w1l, b1,
                                   (float*)0, ff_h, ff_l, M, DIN, HH, 1, 1);
        gemm_bf3<<<gw_h, 256>>>(ff_h, ff_l, w2h, w2l, b2,
                                h, (bf16*)0, (bf16*)0, M, HH, DIN, 0, 0);
        ln_kernel<<<M, 256>>>(h, nodes, pw_g + i*HH, pw_bn + i*HH, h, h_h, h_l, 0);

        // ring q/k/v from h; relay k/v
        gemm_bf3<<<gw_h, 256>>>(h_h, h_l, wqh, wql, rbq, q, (bf16*)0, (bf16*)0, M, HH, HH, 0, 0);
        gemm_bf3<<<gw_h, 256>>>(h_h, h_l, wkh, wkl, rbk, k, (bf16*)0, (bf16*)0, M, HH, HH, 0, 0);
        gemm_bf3<<<gw_h, 256>>>(h_h, h_l, wvh, wvl, rbv, v, (bf16*)0, (bf16*)0, M, HH, HH, 0, 0);
        small_nt_kernel<<<(BB*HH + 7)/8, 256>>>(relay, rwk, rbk, rk, BB, HH, HH, HH, 0);
        small_nt_kernel<<<(BB*HH + 7)/8, 256>>>(relay, rwv, rbv, rv, BB, HH, HH, HH, 0);

        ring_attn_kernel<<<(BB*LL*NHEAD)/8, 256>>>(q, k, v, rk, rv, att_h, att_l);

        // ring output proj -> LN -> leaky -> nodes (+ hi/lo)
        gemm_bf3<<<gw_h, 256>>>(att_h, att_l, woh, wol, rbo, q, (bf16*)0, (bf16*)0, M, HH, HH, 0, 0);
        ln_kernel<<<M, 256>>>(q, (const float*)0, norm_g + i*HH, norm_b + i*HH,
                              nodes, nodes_h, nodes_l, 1);

        // star attention
        small_nt_kernel<<<(BB*HH + 7)/8, 256>>>(relay, swq, sbq, sq,  BB, HH, HH, HH, 0);
        small_nt_kernel<<<(BB*HH + 7)/8, 256>>>(relay, swk, sbk, skr, BB, HH, HH, HH, 0);
        small_nt_kernel<<<(BB*HH + 7)/8, 256>>>(relay, swv, sbv, svr, BB, HH, HH, HH, 0);
        gemm_bf3<<<gw_h, 256>>>(nodes_h, nodes_l, skh, skl, sbk, k, (bf16*)0, (bf16*)0, M, HH, HH, 0, 0);
        gemm_bf3<<<gw_h, 256>>>(nodes_h, nodes_l, svh, svl, sbv, v, (bf16*)0, (bf16*)0, M, HH, HH, 0, 0);
        star_attn_kernel<<<BB*NHEAD, 256>>>(sq, skr, svr, k, v, maskp, satt);
        small_nt_kernel<<<(BB*HH + 7)/8, 256>>>(satt, swo, sbo, relay, BB, HH, HH, HH, 2);

        mask_nodes_kernel<<<(BB*LL*HH + 255)/256, 256>>>(nodes, nodes_h, nodes_l, maskp);
    }

    // heads
    gather_ft_kernel<<<(BB*2*HH + 255)/256, 256>>>(relay, nodes, positions, ft);
    for (int j = 0; j < 3; j++) {
        small_nt_kernel<<<(BB*1024 + 7)/8, 256>>>(ft, head_w1 + (size_t)j*1024*2*HH,
                                                  head_b1 + j*1024, hid + (size_t)j*BB*1024,
                                                  BB, 1024, 2*HH, 1024, 1);
        small_nt_kernel<<<(BB*5000 + 7)/8, 256>>>(hid + (size_t)j*BB*1024,
                                                  head_w2 + (size_t)j*5000*1024,
                                                  head_b2 + j*5000, out + j*5000,
                                                  BB, 5000, 1024, 15000, 0);
    }
}

// round 6
// speedup vs baseline: 4.0445x; 1.3942x over previous
#include <cuda_runtime.h>
#include <cuda_fp16.h>
#include <math.h>
#include <stdint.h>

#define BB 8
#define LL 1024
#define HH 768
#define NHEAD 12
#define HDIM 64
#define DIN 3072
#define ATT_SCALE 0.125f
#define FULLMASK 0xffffffffu

typedef __half f16;

// ---------------- scratch (device globals; no allocations allowed) ----------------
__device__ float g_nodes[BB*LL*HH];
__device__ float g_h[BB*LL*HH];
__device__ float g_q[BB*LL*HH];
__device__ float g_k[BB*LL*HH];
__device__ float g_v[BB*LL*HH];
__device__ float g_relay[BB*HH];
__device__ float g_rk[BB*HH];
__device__ float g_rv[BB*HH];
__device__ float g_sq[BB*HH];
__device__ float g_skr[BB*HH];
__device__ float g_svr[BB*HH];
__device__ float g_satt[BB*HH];
__device__ float g_ft[BB*2*HH];
__device__ float g_hid[3*BB*1024];
__device__ int   g_mask[BB*LL];

// fp16 hi/lo activation buffers
__device__ f16 g_nodes_h[BB*LL*HH];
__device__ f16 g_nodes_l[BB*LL*HH];
__device__ f16 g_h_h[BB*LL*HH];
__device__ f16 g_h_l[BB*LL*HH];
__device__ f16 g_att_h[BB*LL*HH];
__device__ f16 g_att_l[BB*LL*HH];
__device__ f16 g_ff_h[BB*LL*DIN];
__device__ f16 g_ff_l[BB*LL*DIN];

// fp16 weight buffers (single precision term, reused per layer)
__device__ f16 g_w1f[DIN*HH];
__device__ f16 g_w2f[HH*DIN];
__device__ f16 g_wqf[HH*HH];
__device__ f16 g_wkf[HH*HH];
__device__ f16 g_wvf[HH*HH];
__device__ f16 g_wof[HH*HH];
__device__ f16 g_skf[HH*HH];
__device__ f16 g_svf[HH*HH];

// ---------------- helpers ----------------
__device__ __forceinline__ uint32_t smem_u32(const void* p) {
    return (uint32_t)__cvta_generic_to_shared(p);
}

#define CP16(dst, src) asm volatile("cp.async.cg.shared.global [%0], [%1], 16;" :: "r"(dst), "l"(src))

#define LDSM4(R, addr) \
    asm volatile("ldmatrix.sync.aligned.m8n8.x4.shared.b16 {%0,%1,%2,%3}, [%4];" \
                 : "=r"((R)[0]), "=r"((R)[1]), "=r"((R)[2]), "=r"((R)[3]) : "r"(addr))

#define MMA16816(D, A, B0, B1) \
    asm volatile("mma.sync.aligned.m16n8k16.row.col.f32.f16.f16.f32 " \
                 "{%0,%1,%2,%3}, {%4,%5,%6,%7}, {%8,%9}, {%0,%1,%2,%3};" \
                 : "+f"((D)[0]), "+f"((D)[1]), "+f"((D)[2]), "+f"((D)[3]) \
                 : "r"((A)[0]), "r"((A)[1]), "r"((A)[2]), "r"((A)[3]), "r"(B0), "r"(B1))

__device__ __forceinline__ void split_store(float v, f16* h, f16* l, size_t idx) {
    f16 hi = __float2half(v);
    h[idx] = hi;
    l[idx] = __float2half(v - __half2float(hi));
}

// ---------------- fp32 -> fp16 convert (weights) ----------------
__global__ void convert_kernel(const float* __restrict__ x, f16* __restrict__ o, int n)
{
    int i = blockIdx.x * blockDim.x + threadIdx.x;
    if (i < n) o[i] = __float2half(x[i]);
}

// ---------------- embedding + positional (fp32 + hi/lo) ----------------
__global__ void embed_kernel(const int* __restrict__ src, const float* __restrict__ emb,
                             const float* __restrict__ pos, float* __restrict__ nodes,
                             f16* __restrict__ nh, f16* __restrict__ nl)
{
    int idx = blockIdx.x * blockDim.x + threadIdx.x;
    if (idx >= BB*LL*HH) return;
    int hh = idx % HH;
    int bl = idx / HH;
    int l  = bl % LL;
    int j  = hh >> 8;
    int d  = hh & 255;
    int tok = src[bl*3 + j];
    float v = emb[tok*256 + d] + pos[l*HH + hh];
    nodes[idx] = v;
    split_store(v, nh, nl, idx);
}

__global__ void mask_kernel(const int* __restrict__ src, int* __restrict__ mask)
{
    int i = blockIdx.x * blockDim.x + threadIdx.x;
    if (i < BB*LL) mask[i] = (src[i*3] == 0) ? 1 : 0;
}

__global__ void relay_zero_kernel(float* __restrict__ relay)
{
    int i = blockIdx.x * 256 + threadIdx.x;
    if (i < BB*HH) relay[i] = 0.f;
}

__global__ void relay_partial_kernel(const float* __restrict__ nodes, float* __restrict__ relay)
{
    int b  = blockIdx.x;
    int hh = blockIdx.y * 256 + threadIdx.x;
    int l0 = blockIdx.z * 64;
    const float* p = nodes + ((size_t)b*LL + l0)*HH + hh;
    float s = 0.f;
    #pragma unroll 8
    for (int l = 0; l < 64; l++) s += p[(size_t)l*HH];
    atomicAdd(&relay[b*HH + hh], s * (1.0f/1024.0f));
}

// ---------------- tensor-core GEMM (fp16x2): C = A*W^T + bias ----------------
// A: hi/lo [M,K] fp16 row-major; W: single fp16 [N,K] row-major.
// Block 128x128x32, 8 warps (4m x 2n), warp tile 32x64. K mult 32, M mult 128, N mult 128.
// outpair=0: Cf fp32; outpair=1: Ch/Cl fp16 pair. act: 0 none, 1 relu.
__global__ void __launch_bounds__(256, 2) gemm_h2(
    const f16* __restrict__ Ah, const f16* __restrict__ Al,
    const f16* __restrict__ W, const float* __restrict__ bias,
    float* __restrict__ Cf, f16* __restrict__ Ch, f16* __restrict__ Cl,
    int M, int N, int K, int act, int outpair)
{
    __shared__ __align__(16) f16 sAh[2][4096];
    __shared__ __align__(16) f16 sAl[2][4096];
    __shared__ __align__(16) f16 sW [2][4096];

    const int tid = threadIdx.x;
    const int bm = blockIdx.y * 128;
    const int bn = blockIdx.x * 128;
    const int lane = tid & 31;
    const int warp = tid >> 5;
    const int wm = warp & 3;    // 4 warps along M (32 rows each)
    const int wn = warp >> 2;   // 2 warps along N (64 cols each)

    const int niter = K >> 5;

    // ldmatrix byte offsets within a stage buffer (validated layout from R3)
    const int li = lane >> 3;
    const int lr = lane & 7;
    uint32_t aoff[2][2], woff[4][2];
    #pragma unroll
    for (int mi = 0; mi < 2; mi++)
        #pragma unroll
        for (int ks = 0; ks < 2; ks++) {
            int row = wm*32 + mi*16 + ((li & 1) << 3) + lr;
            int c   = (ks << 1) + (li >> 1);
            aoff[mi][ks] = (uint32_t)((row*32 + ((c ^ ((row >> 1) & 3)) << 3)) * 2);
        }
    #pragma unroll
    for (int nj = 0; nj < 4; nj++)
        #pragma unroll
        for (int ks = 0; ks < 2; ks++) {
            int row = wn*64 + nj*16 + ((li >> 1) << 3) + lr;
            int c   = (ks << 1) + (li & 1);
            woff[nj][ks] = (uint32_t)((row*32 + ((c ^ ((row >> 1) & 3)) << 3)) * 2);
        }

    // global load coordinates: 512 16B-chunks per 128x32 tile, 2 per thread
    const int r0 = tid >> 2,         c0 = tid & 3;
    const int r1 = (tid + 256) >> 2, c1 = (tid + 256) & 3;
    const uint32_t sw0 = (uint32_t)((r0*32 + ((c0 ^ ((r0 >> 1) & 3)) << 3)) * 2);
    const uint32_t sw1 = (uint32_t)((r1*32 + ((c1 ^ ((r1 >> 1) & 3)) << 3)) * 2);

    const uint32_t bAh = smem_u32(&sAh[0][0]);
    const uint32_t bAl = smem_u32(&sAl[0][0]);
    const uint32_t bW  = smem_u32(&sW[0][0]);

    #define LOAD_STAGE(s, kt) do { \
        uint32_t o = (s) ? 8192u : 0u; \
        CP16(bAh + o + sw0, Ah + (size_t)(bm + r0)*K + (kt) + c0*8); \
        CP16(bAh + o + sw1, Ah + (size_t)(bm + r1)*K + (kt) + c1*8); \
        CP16(bAl + o + sw0, Al + (size_t)(bm + r0)*K + (kt) + c0*8); \
        CP16(bAl + o + sw1, Al + (size_t)(bm + r1)*K + (kt) + c1*8); \
        CP16(bW  + o + sw0, W  + (size_t)(bn + r0)*K + (kt) + c0*8); \
        CP16(bW  + o + sw1, W  + (size_t)(bn + r1)*K + (kt) + c1*8); \
        asm volatile("cp.async.commit_group;"); \
    } while (0)

    float acc[2][8][4];
    #pragma unroll
    for (int mi = 0; mi < 2; mi++)
        #pragma unroll
        for (int nf = 0; nf < 8; nf++)
            #pragma unroll
            for (int e = 0; e < 4; e++) acc[mi][nf][e] = 0.f;

    LOAD_STAGE(0, 0);

    for (int it = 0; it < niter; it++) {
        if (it + 1 < niter) {
            LOAD_STAGE((it + 1) & 1, (it + 1) * 32);
            asm volatile("cp.async.wait_group 1;");
        } else {
            asm volatile("cp.async.wait_group 0;");
        }
        __syncthreads();

        const uint32_t o = (it & 1) ? 8192u : 0u;
        const uint32_t cAh = bAh + o;
        const uint32_t cAl = bAl + o;
        const uint32_t cW  = bW + o;

        #pragma unroll
        for (int ks = 0; ks < 2; ks++) {
            uint32_t fah[2][4], fal[2][4];
            LDSM4(fah[0], cAh + aoff[0][ks]);
            LDSM4(fah[1], cAh + aoff[1][ks]);
            LDSM4(fal[0], cAl + aoff[0][ks]);
            LDSM4(fal[1], cAl + aoff[1][ks]);
            uint32_t fw[8][2];
            #pragma unroll
            for (int nj = 0; nj < 4; nj++) {
                uint32_t t4[4];
                LDSM4(t4, cW + woff[nj][ks]);
                fw[nj*2][0]   = t4[0]; fw[nj*2][1]   = t4[1];
                fw[nj*2+1][0] = t4[2]; fw[nj*2+1][1] = t4[3];
            }
            #pragma unroll
            for (int mi = 0; mi < 2; mi++)
                #pragma unroll
                for (int nf = 0; nf < 8; nf++) {
                    MMA16816(acc[mi][nf], fah[mi], fw[nf][0], fw[nf][1]);
                    MMA16816(acc[mi][nf], fal[mi], fw[nf][0], fw[nf][1]);
                }
        }
        __syncthreads();
    }

    // epilogue
    const int em = lane >> 2;
    const int en = (lane & 3) << 1;
    #pragma unroll
    for (int mi = 0; mi < 2; mi++) {
        #pragma unroll
        for (int nf = 0; nf < 8; nf++) {
            int col = bn + wn*64 + nf*8 + en;
            float b0 = bias[col], b1 = bias[col + 1];
            #pragma unroll
            for (int hf = 0; hf < 2; hf++) {
                int row = bm + wm*32 + mi*16 + em + hf*8;
                float v0 = acc[mi][nf][hf*2 + 0] + b0;
                float v1 = acc[mi][nf][hf*2 + 1] + b1;
                if (act == 1) { v0 = fmaxf(v0, 0.f); v1 = fmaxf(v1, 0.f); }
                size_t o2 = (size_t)row*N + col;
                if (outpair) {
                    f16 h0 = __float2half(v0);
                    f16 h1 = __float2half(v1);
                    __half2 hp, lp;
                    hp.x = h0; hp.y = h1;
                    lp.x = __float2half(v0 - __half2float(h0));
                    lp.y = __float2half(v1 - __half2float(h1));
                    *(__half2*)(Ch + o2) = hp;
                    *(__half2*)(Cl + o2) = lp;
                } else {
                    float2 r; r.x = v0; r.y = v1;
                    *(float2*)(Cf + o2) = r;
                }
            }
        }
    }
    #undef LOAD_STAGE
}

// ---------------- small GEMM (warp-per-output) ----------------
__global__ void small_nt_kernel(const float* __restrict__ A, const float* __restrict__ W,
                                const float* __restrict__ bias, float* __restrict__ C,
                                int M, int N, int K, int ldc, int act)
{
    int w = (blockIdx.x * blockDim.x + threadIdx.x) >> 5;
    int lane = threadIdx.x & 31;
    if (w >= M*N) return;
    int m = w / N, n = w % N;
    const float4* a  = (const float4*)(A + (size_t)m*K);
    const float4* wr = (const float4*)(W + (size_t)n*K);
    float s = 0.f;
    int K4 = K >> 2;
    for (int c = lane; c < K4; c += 32) {
        float4 av = a[c], wv = wr[c];
        s += av.x*wv.x + av.y*wv.y + av.z*wv.z + av.w*wv.w;
    }
    #pragma unroll
    for (int o = 16; o > 0; o >>= 1) s += __shfl_xor_sync(FULLMASK, s, o);
    if (lane == 0) {
        s += bias[n];
        if (act == 1) s = fmaxf(s, 0.f);
        else if (act == 2 && s < 0.f) s *= 0.01f;
        C[(size_t)m*ldc + n] = s;
    }
}

// ---------------- LayerNorm (row=768) with optional residual/leaky + hi/lo out ----------------
__global__ void __launch_bounds__(256) ln_kernel(
    const float* __restrict__ X, const float* __restrict__ RES,
    const float* __restrict__ g, const float* __restrict__ b,
    float* __restrict__ out, f16* __restrict__ oh, f16* __restrict__ ol, int leaky)
{
    __shared__ float shs[8], shs2[8];
    __shared__ float smean, sinv;
    int row = blockIdx.x;
    int tid = threadIdx.x;
    const float* x = X + (size_t)row*HH;
    float v0 = x[tid], v1 = x[tid+256], v2 = x[tid+512];
    if (RES) {
        const float* r = RES + (size_t)row*HH;
        v0 += r[tid]; v1 += r[tid+256]; v2 += r[tid+512];
    }
    float s  = v0+v1+v2;
    float s2 = v0*v0 + v1*v1 + v2*v2;
    #pragma unroll
    for (int o = 16; o > 0; o >>= 1) {
        s  += __shfl_xor_sync(FULLMASK, s, o);
        s2 += __shfl_xor_sync(FULLMASK, s2, o);
    }
    if ((tid & 31) == 0) { shs[tid>>5] = s; shs2[tid>>5] = s2; }
    __syncthreads();
    if (tid == 0) {
        float ts = 0.f, ts2 = 0.f;
        for (int i = 0; i < 8; i++) { ts += shs[i]; ts2 += shs2[i]; }
        float mean = ts * (1.0f/768.0f);
        float var  = ts2 * (1.0f/768.0f) - mean*mean;
        smean = mean;
        sinv  = rsqrtf(var + 1e-5f);
    }
    __syncthreads();
    float mean = smean, inv = sinv;
    size_t base = (size_t)row*HH;
    float y0 = (v0-mean)*inv*g[tid]     + b[tid];
    float y1 = (v1-mean)*inv*g[tid+256] + b[tid+256];
    float y2 = (v2-mean)*inv*g[tid+512] + b[tid+512];
    if (leaky) {
        if (y0 < 0.f) y0 *= 0.01f;
        if (y1 < 0.f) y1 *= 0.01f;
        if (y2 < 0.f) y2 *= 0.01f;
    }
    out[base+tid] = y0; out[base+tid+256] = y1; out[base+tid+512] = y2;
    if (oh) {
        split_store(y0, oh, ol, base+tid);
        split_store(y1, oh, ol, base+tid+256);
        split_store(y2, oh, ol, base+tid+512);
    }
}

// ---------------- ring attention (outputs hi/lo fp16) ----------------
__global__ void __launch_bounds__(256) ring_attn_kernel(
    const float* __restrict__ q, const float* __restrict__ k, const float* __restrict__ v,
    const float* __restrict__ rk, const float* __restrict__ rv,
    f16* __restrict__ ah, f16* __restrict__ al)
{
    int gw = (blockIdx.x * 256 + threadIdx.x) >> 5;
    int lane = threadIdx.x & 31;
    if (gw >= BB*LL*NHEAD) return;
    int n  = gw % NHEAD;
    int bl = gw / NHEAD;
    int l  = bl % LL;
    int b  = bl / LL;
    const float* qp = q + (size_t)bl*HH + n*HDIM;
    float q0 = qp[lane], q1 = qp[lane+32];

    float s[4];
    #pragma unroll
    for (int w = 0; w < 3; w++) {
        int ll = l + w - 1;
        float d = 0.f;
        if (ll >= 0 && ll < LL) {
            const float* kp = k + ((size_t)b*LL + ll)*HH + n*HDIM;
            d = q0*kp[lane] + q1*kp[lane+32];
        }
        #pragma unroll
        for (int o = 16; o > 0; o >>= 1) d += __shfl_xor_sync(FULLMASK, d, o);
        s[w] = d;
    }
    {
        const float* kp = rk + b*HH + n*HDIM;
        float d = q0*kp[lane] + q1*kp[lane+32];
        #pragma unroll
        for (int o = 16; o > 0; o >>= 1) d += __shfl_xor_sync(FULLMASK, d, o);
        s[3] = d;
    }
    float sc0 = s[0]*ATT_SCALE, sc1 = s[1]*ATT_SCALE, sc2 = s[2]*ATT_SCALE, sc3 = s[3]*ATT_SCALE;
    float m = fmaxf(fmaxf(sc0, sc1), fmaxf(sc2, sc3));
    float e0 = expf(sc0-m), e1 = expf(sc1-m), e2 = expf(sc2-m), e3 = expf(sc3-m);
    float inv = 1.f / (e0+e1+e2+e3);
    float a0 = e0*inv, a1 = e1*inv, a2 = e2*inv, a3 = e3*inv;

    const float* rvp = rv + b*HH + n*HDIM;
    float o0 = a3 * rvp[lane];
    float o1 = a3 * rvp[lane+32];
    float aw[3] = {a0, a1, a2};
    #pragma unroll
    for (int w = 0; w < 3; w++) {
        int ll = l + w - 1;
        if (ll >= 0 && ll < LL) {
            const float* vp = v + ((size_t)b*LL + ll)*HH + n*HDIM;
            o0 += aw[w] * vp[lane];
            o1 += aw[w] * vp[lane+32];
        }
    }
    size_t o = (size_t)bl*HH + n*HDIM;
    split_store(o0, ah, al, o + lane);
    split_store(o1, ah, al, o + lane + 32);
}

// ---------------- star attention: block per (b,head) ----------------
__global__ void __launch_bounds__(256) star_attn_kernel(
    const float* __restrict__ sq, const float* __restrict__ skr, const float* __restrict__ svr,
    const float* __restrict__ k, const float* __restrict__ v, const int* __restrict__ mask,
    float* __restrict__ satt)
{
    __shared__ float sc[LL+1];
    __shared__ float qv[HDIM];
    __shared__ float red[8];
    __shared__ float bmax, bsum;
    __shared__ float part[4][HDIM];
    int b = blockIdx.x / NHEAD;
    int n = blockIdx.x % NHEAD;
    int tid = threadIdx.x;

    if (tid < HDIM) qv[tid] = sq[b*HH + n*HDIM + tid];
    __syncthreads();

    for (int s = tid; s <= LL; s += 256) {
        float d;
        if (s > 0 && mask[b*LL + s-1]) d = -INFINITY;
        else {
            const float* kp = (s == 0) ? (skr + b*HH + n*HDIM)
                                       : (k + ((size_t)b*LL + s-1)*HH + n*HDIM);
            float acc = 0.f;
            #pragma unroll 16
            for (int dd = 0; dd < HDIM; dd++) acc += qv[dd]*kp[dd];
            d = acc * ATT_SCALE;
        }
        sc[s] = d;
    }
    __syncthreads();

    float m = -INFINITY;
    for (int s = tid; s <= LL; s += 256) m = fmaxf(m, sc[s]);
    #pragma unroll
    for (int o = 16; o > 0; o >>= 1) m = fmaxf(m, __shfl_xor_sync(FULLMASK, m, o));
    if ((tid & 31) == 0) red[tid>>5] = m;
    __syncthreads();
    if (tid == 0) {
        float mm = red[0];
        for (int i = 1; i < 8; i++) mm = fmaxf(mm, red[i]);
        bmax = mm;
    }
    __syncthreads();

    float psum = 0.f;
    for (int s = tid; s <= LL; s += 256) {
        float e = expf(sc[s] - bmax);
        sc[s] = e;
        psum += e;
    }
    #pragma unroll
    for (int o = 16; o > 0; o >>= 1) psum += __shfl_xor_sync(FULLMASK, psum, o);
    if ((tid & 31) == 0) red[tid>>5] = psum;
    __syncthreads();
    if (tid == 0) {
        float ss = 0.f;
        for (int i = 0; i < 8; i++) ss += red[i];
        bsum = ss;
    }
    __syncthreads();

    int d = tid & 63, stripe = tid >> 6;
    float acc = 0.f;
    for (int s = stripe; s <= LL; s += 4) {
        float w = sc[s];
        float vv = (s == 0) ? svr[b*HH + n*HDIM + d]
                            : v[((size_t)b*LL + s-1)*HH + n*HDIM + d];
        acc += w*vv;
    }
    part[stripe][d] = acc;
    __syncthreads();
    if (tid < HDIM) {
        float r = (part[0][tid] + part[1][tid] + part[2][tid] + part[3][tid]) / bsum;
        satt[b*HH + n*HDIM + tid] = r;
    }
}

// ---------------- zero out masked node rows (fp32 + hi/lo) ----------------
__global__ void mask_nodes_kernel(float* __restrict__ nodes, f16* __restrict__ nh,
                                  f16* __restrict__ nl, const int* __restrict__ mask)
{
    int idx = blockIdx.x * blockDim.x + threadIdx.x;
    if (idx >= BB*LL*HH) return;
    if (mask[idx / HH]) {
        nodes[idx] = 0.f;
        nh[idx] = __float2half(0.f);
        nl[idx] = __float2half(0.f);
    }
}

// ---------------- build ft = [relay, nodes[b, positions[b]]] ----------------
__global__ void gather_ft_kernel(const float* __restrict__ relay, const float* __restrict__ nodes,
                                 const int* __restrict__ pos, float* __restrict__ ft)
{
    int i = blockIdx.x * blockDim.x + threadIdx.x;
    if (i >= BB*2*HH) return;
    int b = i / (2*HH), c = i % (2*HH);
    ft[i] = (c < HH) ? relay[b*HH + c]
                     : nodes[((size_t)b*LL + pos[b])*HH + (c - HH)];
}

// ---------------- host orchestration ----------------
extern "C" void kernel_launch(void* const* d_in, const int* in_sizes, int n_in,
                              void* d_out, int out_size)
{
    const int*   src       = (const int*)d_in[0];
    const int*   positions = (const int*)d_in[1];
    const float* emb       = (const float*)d_in[2];
    const float* pos_table = (const float*)d_in[3];
    const float* norm_g    = (const float*)d_in[4];
    const float* norm_b    = (const float*)d_in[5];
    const float* pw_w1     = (const float*)d_in[6];
    const float* pw_b1     = (const float*)d_in[7];
    const float* pw_w2     = (const float*)d_in[8];
    const float* pw_b2     = (const float*)d_in[9];
    const float* pw_g      = (const float*)d_in[10];
    const float* pw_bn     = (const float*)d_in[11];
    const float* ring_wq   = (const float*)d_in[12];
    const float* ring_bq   = (const float*)d_in[13];
    const float* ring_wk   = (const float*)d_in[14];
    const float* ring_bk   = (const float*)d_in[15];
    const float* ring_wv   = (const float*)d_in[16];
    const float* ring_bv   = (const float*)d_in[17];
    const float* ring_wo   = (const float*)d_in[18];
    const float* ring_bo   = (const float*)d_in[19];
    const float* star_wq   = (const float*)d_in[20];
    const float* star_bq   = (const float*)d_in[21];
    const float* star_wk   = (const float*)d_in[22];
    const float* star_bk   = (const float*)d_in[23];
    const float* star_wv   = (const float*)d_in[24];
    const float* star_bv   = (const float*)d_in[25];
    const float* star_wo   = (const float*)d_in[26];
    const float* star_bo   = (const float*)d_in[27];
    const float* head_w1   = (const float*)d_in[28];
    const float* head_b1   = (const float*)d_in[29];
    const float* head_w2   = (const float*)d_in[30];
    const float* head_b2   = (const float*)d_in[31];
    float* out = (float*)d_out;

    float *nodes, *h, *q, *k, *v, *relay, *rk, *rv, *sq, *skr, *svr, *satt, *ft, *hid;
    int* maskp;
    f16 *nodes_h, *nodes_l, *h_h, *h_l, *att_h, *att_l, *ff_h, *ff_l;
    f16 *w1f, *w2f, *wqf, *wkf, *wvf, *wof, *skf, *svf;

    cudaGetSymbolAddress((void**)&nodes, g_nodes);
    cudaGetSymbolAddress((void**)&h,     g_h);
    cudaGetSymbolAddress((void**)&q,     g_q);
    cudaGetSymbolAddress((void**)&k,     g_k);
    cudaGetSymbolAddress((void**)&v,     g_v);
    cudaGetSymbolAddress((void**)&relay, g_relay);
    cudaGetSymbolAddress((void**)&rk,    g_rk);
    cudaGetSymbolAddress((void**)&rv,    g_rv);
    cudaGetSymbolAddress((void**)&sq,    g_sq);
    cudaGetSymbolAddress((void**)&skr,   g_skr);
    cudaGetSymbolAddress((void**)&svr,   g_svr);
    cudaGetSymbolAddress((void**)&satt,  g_satt);
    cudaGetSymbolAddress((void**)&ft,    g_ft);
    cudaGetSymbolAddress((void**)&hid,   g_hid);
    cudaGetSymbolAddress((void**)&maskp, g_mask);
    cudaGetSymbolAddress((void**)&nodes_h, g_nodes_h);
    cudaGetSymbolAddress((void**)&nodes_l, g_nodes_l);
    cudaGetSymbolAddress((void**)&h_h,   g_h_h);
    cudaGetSymbolAddress((void**)&h_l,   g_h_l);
    cudaGetSymbolAddress((void**)&att_h, g_att_h);
    cudaGetSymbolAddress((void**)&att_l, g_att_l);
    cudaGetSymbolAddress((void**)&ff_h,  g_ff_h);
    cudaGetSymbolAddress((void**)&ff_l,  g_ff_l);
    cudaGetSymbolAddress((void**)&w1f, g_w1f);
    cudaGetSymbolAddress((void**)&w2f, g_w2f);
    cudaGetSymbolAddress((void**)&wqf, g_wqf);
    cudaGetSymbolAddress((void**)&wkf, g_wkf);
    cudaGetSymbolAddress((void**)&wvf, g_wvf);
    cudaGetSymbolAddress((void**)&wof, g_wof);
    cudaGetSymbolAddress((void**)&skf, g_skf);
    cudaGetSymbolAddress((void**)&svf, g_svf);

    const int M = BB*LL;                    // 8192
    dim3 g_wide(DIN/128, M/128);            // (24, 64)
    dim3 g_hh(HH/128, M/128);               // (6, 64)

    embed_kernel<<<(BB*LL*HH + 255)/256, 256>>>(src, emb, pos_table, nodes, nodes_h, nodes_l);
    mask_kernel<<<(BB*LL + 255)/256, 256>>>(src, maskp);
    relay_zero_kernel<<<(BB*HH + 255)/256, 256>>>(relay);
    relay_partial_kernel<<<dim3(BB, 3, 16), 256>>>(nodes, relay);

    for (int i = 0; i < 2; i++) {
        const float* w1 = pw_w1 + (size_t)i*DIN*HH;
        const float* b1 = pw_b1 + i*DIN;
        const float* w2 = pw_w2 + (size_t)i*HH*DIN;
        const float* b2 = pw_b2 + i*HH;
        const float* rwq = ring_wq + (size_t)i*HH*HH; const float* rbq = ring_bq + i*HH;
        const float* rwk = ring_wk + (size_t)i*HH*HH; const float* rbk = ring_bk + i*HH;
        const float* rwv = ring_wv + (size_t)i*HH*HH; const float* rbv = ring_bv + i*HH;
        const float* rwo = ring_wo + (size_t)i*HH*HH; const float* rbo = ring_bo + i*HH;
        const float* swq = star_wq + (size_t)i*HH*HH; const float* sbq = star_bq + i*HH;
        const float* swk = star_wk + (size_t)i*HH*HH; const float* sbk = star_bk + i*HH;
        const float* swv = star_wv + (size_t)i*HH*HH; const float* sbv = star_bv + i*HH;
        const float* swo = star_wo + (size_t)i*HH*HH; const float* sbo = star_bo + i*HH;

        convert_kernel<<<(DIN*HH + 255)/256, 256>>>(w1, w1f, DIN*HH);
        convert_kernel<<<(HH*DIN + 255)/256, 256>>>(w2, w2f, HH*DIN);
        convert_kernel<<<(HH*HH + 255)/256, 256>>>(rwq, wqf, HH*HH);
        convert_kernel<<<(HH*HH + 255)/256, 256>>>(rwk, wkf, HH*HH);
        convert_kernel<<<(HH*HH + 255)/256, 256>>>(rwv, wvf, HH*HH);
        convert_kernel<<<(HH*HH + 255)/256, 256>>>(rwo, wof, HH*HH);
        convert_kernel<<<(HH*HH + 255)/256, 256>>>(swk, skf, HH*HH);
        convert_kernel<<<(HH*HH + 255)/256, 256>>>(swv, svf, HH*HH);

        // PWFF: ff = relu(nodes@w1^T + b1) -> fp16 pair; h = LN(ff@w2^T + b2 + nodes)
        gemm_h2<<<g_wide, 256>>>(nodes_h, nodes_l, w1f, b1,
                                 (float*)0, ff_h, ff_l, M, DIN, HH, 1, 1);
        gemm_h2<<<g_hh, 256>>>(ff_h, ff_l, w2f, b2,
                               h, (f16*)0, (f16*)0, M, HH, DIN, 0, 0);
        ln_kernel<<<M, 256>>>(h, nodes, pw_g + i*HH, pw_bn + i*HH, h, h_h, h_l, 0);

        // ring q/k/v from h; relay k/v
        gemm_h2<<<g_hh, 256>>>(h_h, h_l, wqf, rbq, q, (f16*)0, (f16*)0, M, HH, HH, 0, 0);
        gemm_h2<<<g_hh, 256>>>(h_h, h_l, wkf, rbk, k, (f16*)0, (f16*)0, M, HH, HH, 0, 0);
        gemm_h2<<<g_hh, 256>>>(h_h, h_l, wvf, rbv, v, (f16*)0, (f16*)0, M, HH, HH, 0, 0);
        small_nt_kernel<<<(BB*HH + 7)/8, 256>>>(relay, rwk, rbk, rk, BB, HH, HH, HH, 0);
        small_nt_kernel<<<(BB*HH + 7)/8, 256>>>(relay, rwv, rbv, rv, BB, HH, HH, HH, 0);

        ring_attn_kernel<<<(BB*LL*NHEAD)/8, 256>>>(q, k, v, rk, rv, att_h, att_l);

        // ring output proj -> LN -> leaky -> nodes (+ hi/lo)
        gemm_h2<<<g_hh, 256>>>(att_h, att_l, wof, rbo, q, (f16*)0, (f16*)0, M, HH, HH, 0, 0);
        ln_kernel<<<M, 256>>>(q, (const float*)0, norm_g + i*HH, norm_b + i*HH,
                              nodes, nodes_h, nodes_l, 1);

        // star attention
        small_nt_kernel<<<(BB*HH + 7)/8, 256>>>(relay, swq, sbq, sq,  BB, HH, HH, HH, 0);
        small_nt_kernel<<<(BB*HH + 7)/8, 256>>>(relay, swk, sbk, skr, BB, HH, HH, HH, 0);
        small_nt_kernel<<<(BB*HH + 7)/8, 256>>>(relay, swv, sbv, svr, BB, HH, HH, HH, 0);
        gemm_h2<<<g_hh, 256>>>(nodes_h, nodes_l, skf, sbk, k, (f16*)0, (f16*)0, M, HH, HH, 0, 0);
        gemm_h2<<<g_hh, 256>>>(nodes_h, nodes_l, svf, sbv, v, (f16*)0, (f16*)0, M, HH, HH, 0, 0);
        star_attn_kernel<<<BB*NHEAD, 256>>>(sq, skr, svr, k, v, maskp, satt);
        small_nt_kernel<<<(BB*HH + 7)/8, 256>>>(satt, swo, sbo, relay, BB, HH, HH, HH, 2);

        mask_nodes_kernel<<<(BB*LL*HH + 255)/256, 256>>>(nodes, nodes_h, nodes_l, maskp);
    }

    // heads
    gather_ft_kernel<<<(BB*2*HH + 255)/256, 256>>>(relay, nodes, positions, ft);
    for (int j = 0; j < 3; j++) {
        small_nt_kernel<<<(BB*1024 + 7)/8, 256>>>(ft, head_w1 + (size_t)j*1024*2*HH,
                                                  head_b1 + j*1024, hid + (size_t)j*BB*1024,
                                                  BB, 1024, 2*HH, 1024, 1);
        small_nt_kernel<<<(BB*5000 + 7)/8, 256>>>(hid + (size_t)j*BB*1024,
                                                  head_w2 + (size_t)j*5000*1024,
                                                  head_b2 + j*5000, out + j*5000,
                                                  BB, 5000, 1024, 15000, 0);
    }
}

// round 9
// speedup vs baseline: 4.2844x; 1.0593x over previous
#include <cuda_runtime.h>
#include <cuda_fp16.h>
#include <math.h>
#include <stdint.h>

#define BB 8
#define LL 1024
#define HH 768
#define NHEAD 12
#define HDIM 64
#define DIN 3072
#define ATT_SCALE 0.125f
#define FULLMASK 0xffffffffu

typedef __half f16;

// ---------------- scratch (device globals; no allocations allowed) ----------------
__device__ float g_nodes[BB*LL*HH];
__device__ float g_h[BB*LL*HH];
__device__ float g_qkv[BB*LL*3*HH];     // fused q|k|v (stride 2304); reused for o-proj out and star kv
__device__ float g_relay[BB*HH];
__device__ float g_rk[BB*HH];
__device__ float g_rv[BB*HH];
__device__ float g_sq[BB*HH];
__device__ float g_skr[BB*HH];
__device__ float g_svr[BB*HH];
__device__ float g_satt[BB*HH];
__device__ float g_ft[BB*2*HH];
__device__ float g_hid[3*BB*1024];
__device__ int   g_mask[BB*LL];
__device__ float g_bqkv[3*HH];
__device__ float g_bkv2[2*HH];

// fp16 hi/lo activation buffers
__device__ f16 g_nodes_h[BB*LL*HH];
__device__ f16 g_nodes_l[BB*LL*HH];
__device__ f16 g_h_h[BB*LL*HH];
__device__ f16 g_h_l[BB*LL*HH];
__device__ f16 g_att_h[BB*LL*HH];
__device__ f16 g_att_l[BB*LL*HH];
__device__ f16 g_ff_h[BB*LL*DIN];
__device__ f16 g_ff_l[BB*LL*DIN];

// fp16 weight buffers (reused per layer)
__device__ f16 g_w1f[DIN*HH];
__device__ f16 g_w2f[HH*DIN];
__device__ f16 g_wqkv[3*HH*HH];   // ring q|k|v concat
__device__ f16 g_wof[HH*HH];
__device__ f16 g_wkv2[2*HH*HH];   // star k|v concat

// ---------------- helpers ----------------
__device__ __forceinline__ uint32_t smem_u32(const void* p) {
    return (uint32_t)__cvta_generic_to_shared(p);
}

#define CP16(dst, src) asm volatile("cp.async.cg.shared.global [%0], [%1], 16;" :: "r"(dst), "l"(src))

#define LDSM4(R, addr) \
    asm volatile("ldmatrix.sync.aligned.m8n8.x4.shared.b16 {%0,%1,%2,%3}, [%4];" \
                 : "=r"((R)[0]), "=r"((R)[1]), "=r"((R)[2]), "=r"((R)[3]) : "r"(addr))

#define MMA16816(D, A, B0, B1) \
    asm volatile("mma.sync.aligned.m16n8k16.row.col.f32.f16.f16.f32 " \
                 "{%0,%1,%2,%3}, {%4,%5,%6,%7}, {%8,%9}, {%0,%1,%2,%3};" \
                 : "+f"((D)[0]), "+f"((D)[1]), "+f"((D)[2]), "+f"((D)[3]) \
                 : "r"((A)[0]), "r"((A)[1]), "r"((A)[2]), "r"((A)[3]), "r"(B0), "r"(B1))

__device__ __forceinline__ void split_store(float v, f16* h, f16* l, size_t idx) {
    f16 hi = __float2half(v);
    h[idx] = hi;
    l[idx] = __float2half(v - __half2float(hi));
}

// ---------------- fp32 -> fp16 convert (weights) ----------------
__global__ void convert_kernel(const float* __restrict__ x, f16* __restrict__ o, int n)
{
    int i = blockIdx.x * blockDim.x + threadIdx.x;
    if (i < n) o[i] = __float2half(x[i]);
}

// ---------------- embedding + positional (fp32 + hi/lo) ----------------
__global__ void embed_kernel(const int* __restrict__ src, const float* __restrict__ emb,
                             const float* __restrict__ pos, float* __restrict__ nodes,
                             f16* __restrict__ nh, f16* __restrict__ nl)
{
    int idx = blockIdx.x * blockDim.x + threadIdx.x;
    if (idx >= BB*LL*HH) return;
    int hh = idx % HH;
    int bl = idx / HH;
    int l  = bl % LL;
    int j  = hh >> 8;
    int d  = hh & 255;
    int tok = src[bl*3 + j];
    float v = emb[tok*256 + d] + pos[l*HH + hh];
    nodes[idx] = v;
    split_store(v, nh, nl, idx);
}

__global__ void mask_kernel(const int* __restrict__ src, int* __restrict__ mask)
{
    int i = blockIdx.x * blockDim.x + threadIdx.x;
    if (i < BB*LL) mask[i] = (src[i*3] == 0) ? 1 : 0;
}

__global__ void relay_zero_kernel(float* __restrict__ relay)
{
    int i = blockIdx.x * 256 + threadIdx.x;
    if (i < BB*HH) relay[i] = 0.f;
}

__global__ void relay_partial_kernel(const float* __restrict__ nodes, float* __restrict__ relay)
{
    int b  = blockIdx.x;
    int hh = blockIdx.y * 256 + threadIdx.x;
    int l0 = blockIdx.z * 64;
    const float* p = nodes + ((size_t)b*LL + l0)*HH + hh;
    float s = 0.f;
    #pragma unroll 8
    for (int l = 0; l < 64; l++) s += p[(size_t)l*HH];
    atomicAdd(&relay[b*HH + hh], s * (1.0f/1024.0f));
}

// ---------------- tensor-core GEMM (fp16x2): C = A*W^T + bias ----------------
// Block 128x128x32; 4 warps, warp tile 64x64; 3-stage cp.async pipeline.
// A: hi/lo [M,K] fp16 row-major; W: fp16 [N,K] row-major.
// outpair=0: Cf fp32; outpair=1: Ch/Cl fp16 pair. act: 0 none, 1 relu.
#define GSTAGE 24576u
#define GSMEM  73728

__global__ void __launch_bounds__(128, 2) gemm_h2(
    const f16* __restrict__ Ah, const f16* __restrict__ Al,
    const f16* __restrict__ W, const float* __restrict__ bias,
    float* __restrict__ Cf, f16* __restrict__ Ch, f16* __restrict__ Cl,
    int M, int N, int K, int act, int outpair)
{
    extern __shared__ __align__(16) f16 smem[];
    const uint32_t sb = smem_u32(smem);
    const int tid  = threadIdx.x;
    const int lane = tid & 31;
    const int warp = tid >> 5;
    const int wm = warp & 1;     // 2 warps along M (64 rows each)
    const int wnn = warp >> 1;   // 2 warps along N (64 cols each)
    const int bm = blockIdx.y * 128;
    const int bn = blockIdx.x * 128;
    const int niter = K >> 5;

    // ldmatrix byte offsets within a stage tile (128 rows x 32 halves, swizzled)
    const int li = lane >> 3;
    const int lr = lane & 7;
    uint32_t aoff[4][2], woff[4][2];
    #pragma unroll
    for (int mi = 0; mi < 4; mi++)
        #pragma unroll
        for (int ks = 0; ks < 2; ks++) {
            int row = wm*64 + mi*16 + ((li & 1) << 3) + lr;
            int c   = (ks << 1) + (li >> 1);
            aoff[mi][ks] = (uint32_t)((row*32 + ((c ^ ((row >> 1) & 3)) << 3)) * 2);
        }
    #pragma unroll
    for (int nj = 0; nj < 4; nj++)
        #pragma unroll
        for (int ks = 0; ks < 2; ks++) {
            int row = wnn*64 + nj*16 + ((li >> 1) << 3) + lr;
            int c   = (ks << 1) + (li & 1);
            woff[nj][ks] = (uint32_t)((row*32 + ((c ^ ((row >> 1) & 3)) << 3)) * 2);
        }

    // global load coords: 512 16B-chunks per 128x32 tile, 4 per thread
    int rowv[4], cv[4]; uint32_t swv[4];
    #pragma unroll
    for (int i = 0; i < 4; i++) {
        int id = tid + i*128;
        rowv[i] = id >> 2;
        cv[i]   = id & 3;
        swv[i]  = (uint32_t)((rowv[i]*32 + ((cv[i] ^ ((rowv[i] >> 1) & 3)) << 3)) * 2);
    }

    #define LOAD_STAGE(st, kt) do { \
        uint32_t tb = sb + (uint32_t)(st)*GSTAGE; \
        _Pragma("unroll") \
        for (int i = 0; i < 4; i++) { \
            size_t ga = (size_t)(bm + rowv[i])*K + (kt) + cv[i]*8; \
            size_t gw = (size_t)(bn + rowv[i])*K + (kt) + cv[i]*8; \
            CP16(tb +          swv[i], Ah + ga); \
            CP16(tb + 8192u  + swv[i], Al + ga); \
            CP16(tb + 16384u + swv[i], W  + gw); \
        } \
        asm volatile("cp.async.commit_group;"); \
    } while (0)

    float acc[4][8][4];
    #pragma unroll
    for (int mi = 0; mi < 4; mi++)
        #pragma unroll
        for (int nf = 0; nf < 8; nf++)
            #pragma unroll
            for (int e = 0; e < 4; e++) acc[mi][nf][e] = 0.f;

    LOAD_STAGE(0, 0);
    LOAD_STAGE(1, 32);

    int st = 0;        // stage of current iter
    int lst = 2;       // stage to load next
    for (int it = 0; it < niter; it++) {
        if (it + 1 < niter) {
            asm volatile("cp.async.wait_group 1;");
        } else {
            asm volatile("cp.async.wait_group 0;");
        }
        __syncthreads();

        if (it + 2 < niter) {
            LOAD_STAGE(lst, (it + 2) * 32);
            if (++lst == 3) lst = 0;
        }

        const uint32_t cA  = sb + (uint32_t)st*GSTAGE;
        const uint32_t cAl = cA + 8192u;
        const uint32_t cW  = cA + 16384u;
        if (++st == 3) st = 0;

        #pragma unroll
        for (int ks = 0; ks < 2; ks++) {
            uint32_t fah[4][4], fal[4][4], fw[8][2];
            #pragma unroll
            for (int mi = 0; mi < 4; mi++) LDSM4(fah[mi], cA  + aoff[mi][ks]);
            #pragma unroll
            for (int mi = 0; mi < 4; mi++) LDSM4(fal[mi], cAl + aoff[mi][ks]);
            #pragma unroll
            for (int nj = 0; nj < 4; nj++) {
                uint32_t t4[4];
                LDSM4(t4, cW + woff[nj][ks]);
                fw[nj*2][0]   = t4[0]; fw[nj*2][1]   = t4[1];
                fw[nj*2+1][0] = t4[2]; fw[nj*2+1][1] = t4[3];
            }
            #pragma unroll
            for (int mi = 0; mi < 4; mi++)
                #pragma unroll
                for (int nf = 0; nf < 8; nf++) {
                    MMA16816(acc[mi][nf], fah[mi], fw[nf][0], fw[nf][1]);
                    MMA16816(acc[mi][nf], fal[mi], fw[nf][0], fw[nf][1]);
                }
        }
    }

    // epilogue
    const int em = lane >> 2;
    const int en = (lane & 3) << 1;
    #pragma unroll
    for (int mi = 0; mi < 4; mi++) {
        #pragma unroll
        for (int nf = 0; nf < 8; nf++) {
            int col = bn + wnn*64 + nf*8 + en;
            float b0 = bias[col], b1 = bias[col + 1];
            #pragma unroll
            for (int hf = 0; hf < 2; hf++) {
                int row = bm + wm*64 + mi*16 + em + hf*8;
                float v0 = acc[mi][nf][hf*2 + 0] + b0;
                float v1 = acc[mi][nf][hf*2 + 1] + b1;
                if (act == 1) { v0 = fmaxf(v0, 0.f); v1 = fmaxf(v1, 0.f); }
                size_t o2 = (size_t)row*N + col;
                if (outpair) {
                    f16 h0 = __float2half(v0);
                    f16 h1 = __float2half(v1);
                    __half2 hp, lp;
                    hp.x = h0; hp.y = h1;
                    lp.x = __float2half(v0 - __half2float(h0));
                    lp.y = __float2half(v1 - __half2float(h1));
                    *(__half2*)(Ch + o2) = hp;
                    *(__half2*)(Cl + o2) = lp;
                } else {
                    float2 r; r.x = v0; r.y = v1;
                    *(float2*)(Cf + o2) = r;
                }
            }
        }
    }
    #undef LOAD_STAGE
}

// ---------------- small GEMM (warp-per-output) ----------------
__global__ void small_nt_kernel(const float* __restrict__ A, const float* __restrict__ W,
                                const float* __restrict__ bias, float* __restrict__ C,
                                int M, int N, int K, int ldc, int act)
{
    int w = (blockIdx.x * blockDim.x + threadIdx.x) >> 5;
    int lane = threadIdx.x & 31;
    if (w >= M*N) return;
    int m = w / N, n = w % N;
    const float4* a  = (const float4*)(A + (size_t)m*K);
    const float4* wr = (const float4*)(W + (size_t)n*K);
    float s = 0.f;
    int K4 = K >> 2;
    for (int c = lane; c < K4; c += 32) {
        float4 av = a[c], wv = wr[c];
        s += av.x*wv.x + av.y*wv.y + av.z*wv.z + av.w*wv.w;
    }
    #pragma unroll
    for (int o = 16; o > 0; o >>= 1) s += __shfl_xor_sync(FULLMASK, s, o);
    if (lane == 0) {
        s += bias[n];
        if (act == 1) s = fmaxf(s, 0.f);
        else if (act == 2 && s < 0.f) s *= 0.01f;
        C[(size_t)m*ldc + n] = s;
    }
}

// ---------------- LayerNorm (row=768) with optional residual/leaky + hi/lo out ----------------
__global__ void __launch_bounds__(256) ln_kernel(
    const float* __restrict__ X, const float* __restrict__ RES,
    const float* __restrict__ g, const float* __restrict__ b,
    float* __restrict__ out, f16* __restrict__ oh, f16* __restrict__ ol, int leaky)
{
    __shared__ float shs[8], shs2[8];
    __shared__ float smean, sinv;
    int row = blockIdx.x;
    int tid = threadIdx.x;
    const float* x = X + (size_t)row*HH;
    float v0 = x[tid], v1 = x[tid+256], v2 = x[tid+512];
    if (RES) {
        const float* r = RES + (size_t)row*HH;
        v0 += r[tid]; v1 += r[tid+256]; v2 += r[tid+512];
    }
    float s  = v0+v1+v2;
    float s2 = v0*v0 + v1*v1 + v2*v2;
    #pragma unroll
    for (int o = 16; o > 0; o >>= 1) {
        s  += __shfl_xor_sync(FULLMASK, s, o);
        s2 += __shfl_xor_sync(FULLMASK, s2, o);
    }
    if ((tid & 31) == 0) { shs[tid>>5] = s; shs2[tid>>5] = s2; }
    __syncthreads();
    if (tid == 0) {
        float ts = 0.f, ts2 = 0.f;
        for (int i = 0; i < 8; i++) { ts += shs[i]; ts2 += shs2[i]; }
        float mean = ts * (1.0f/768.0f);
        float var  = ts2 * (1.0f/768.0f) - mean*mean;
        smean = mean;
        sinv  = rsqrtf(var + 1e-5f);
    }
    __syncthreads();
    float mean = smean, inv = sinv;
    size_t base = (size_t)row*HH;
    float y0 = (v0-mean)*inv*g[tid]     + b[tid];
    float y1 = (v1-mean)*inv*g[tid+256] + b[tid+256];
    float y2 = (v2-mean)*inv*g[tid+512] + b[tid+512];
    if (leaky) {
        if (y0 < 0.f) y0 *= 0.01f;
        if (y1 < 0.f) y1 *= 0.01f;
        if (y2 < 0.f) y2 *= 0.01f;
    }
    out[base+tid] = y0; out[base+tid+256] = y1; out[base+tid+512] = y2;
    if (oh) {
        split_store(y0, oh, ol, base+tid);
        split_store(y1, oh, ol, base+tid+256);
        split_store(y2, oh, ol, base+tid+512);
    }
}

// ---------------- ring attention over fused qkv (stride 2304) ----------------
__global__ void __launch_bounds__(256) ring_attn_kernel(
    const float* __restrict__ qkv, const float* __restrict__ rk, const float* __restrict__ rv,
    f16* __restrict__ ah, f16* __restrict__ al)
{
    int gw = (blockIdx.x * 256 + threadIdx.x) >> 5;
    int lane = threadIdx.x & 31;
    if (gw >= BB*LL*NHEAD) return;
    int n  = gw % NHEAD;
    int bl = gw / NHEAD;
    int l  = bl % LL;
    int b  = bl / LL;
    const float* qp = qkv + (size_t)bl*(3*HH) + n*HDIM;
    float q0 = qp[lane], q1 = qp[lane+32];

    float s[4];
    #pragma unroll
    for (int w = 0; w < 3; w++) {
        int ll = l + w - 1;
        float d = 0.f;
        if (ll >= 0 && ll < LL) {
            const float* kp = qkv + ((size_t)b*LL + ll)*(3*HH) + HH + n*HDIM;
            d = q0*kp[lane] + q1*kp[lane+32];
        }
        #pragma unroll
        for (int o = 16; o > 0; o >>= 1) d += __shfl_xor_sync(FULLMASK, d, o);
        s[w] = d;
    }
    {
        const float* kp = rk + b*HH + n*HDIM;
        float d = q0*kp[lane] + q1*kp[lane+32];
        #pragma unroll
        for (int o = 16; o > 0; o >>= 1) d += __shfl_xor_sync(FULLMASK, d, o);
        s[3] = d;
    }
    float sc0 = s[0]*ATT_SCALE, sc1 = s[1]*ATT_SCALE, sc2 = s[2]*ATT_SCALE, sc3 = s[3]*ATT_SCALE;
    float m = fmaxf(fmaxf(sc0, sc1), fmaxf(sc2, sc3));
    float e0 = expf(sc0-m), e1 = expf(sc1-m), e2 = expf(sc2-m), e3 = expf(sc3-m);
    float inv = 1.f / (e0+e1+e2+e3);
    float a0 = e0*inv, a1 = e1*inv, a2 = e2*inv, a3 = e3*inv;

    const float* rvp = rv + b*HH + n*HDIM;
    float o0 = a3 * rvp[lane];
    float o1 = a3 * rvp[lane+32];
    float aw[3] = {a0, a1, a2};
    #pragma unroll
    for (int w = 0; w < 3; w++) {
        int ll = l + w - 1;
        if (ll >= 0 && ll < LL) {
            const float* vp = qkv + ((size_t)b*LL + ll)*(3*HH) + 2*HH + n*HDIM;
            o0 += aw[w] * vp[lane];
            o1 += aw[w] * vp[lane+32];
        }
    }
    size_t o = (size_t)bl*HH + n*HDIM;
    split_store(o0, ah, al, o + lane);
    split_store(o1, ah, al, o + lane + 32);
}

// ---------------- star attention over fused kv (stride 1536) ----------------
__global__ void __launch_bounds__(256) star_attn_kernel(
    const float* __restrict__ sq, const float* __restrict__ skr, const float* __restrict__ svr,
    const float* __restrict__ kv2, const int* __restrict__ mask,
    float* __restrict__ satt)
{
    __shared__ float sc[LL+1];
    __shared__ float qv[HDIM];
    __shared__ float red[8];
    __shared__ float bmax, bsum;
    __shared__ float part[4][HDIM];
    int b = blockIdx.x / NHEAD;
    int n = blockIdx.x % NHEAD;
    int tid = threadIdx.x;

    if (tid < HDIM) qv[tid] = sq[b*HH + n*HDIM + tid];
    __syncthreads();

    for (int s = tid; s <= LL; s += 256) {
        float d;
        if (s > 0 && mask[b*LL + s-1]) d = -INFINITY;
        else {
            const float* kp = (s == 0) ? (skr + b*HH + n*HDIM)
                                       : (kv2 + ((size_t)b*LL + s-1)*(2*HH) + n*HDIM);
            float acc = 0.f;
            #pragma unroll 16
            for (int dd = 0; dd < HDIM; dd++) acc += qv[dd]*kp[dd];
            d = acc * ATT_SCALE;
        }
        sc[s] = d;
    }
    __syncthreads();

    float m = -INFINITY;
    for (int s = tid; s <= LL; s += 256) m = fmaxf(m, sc[s]);
    #pragma unroll
    for (int o = 16; o > 0; o >>= 1) m = fmaxf(m, __shfl_xor_sync(FULLMASK, m, o));
    if ((tid & 31) == 0) red[tid>>5] = m;
    __syncthreads();
    if (tid == 0) {
        float mm = red[0];
        for (int i = 1; i < 8; i++) mm = fmaxf(mm, red[i]);
        bmax = mm;
    }
    __syncthreads();

    float psum = 0.f;
    for (int s = tid; s <= LL; s += 256) {
        float e = expf(sc[s] - bmax);
        sc[s] = e;
        psum += e;
    }
    #pragma unroll
    for (int o = 16; o > 0; o >>= 1) psum += __shfl_xor_sync(FULLMASK, psum, o);
    if ((tid & 31) == 0) red[tid>>5] = psum;
    __syncthreads();
    if (tid == 0) {
        float ss = 0.f;
        for (int i = 0; i < 8; i++) ss += red[i];
        bsum = ss;
    }
    __syncthreads();

    int d = tid & 63, stripe = tid >> 6;
    float acc = 0.f;
    for (int s = stripe; s <= LL; s += 4) {
        float w = sc[s];
        float vv = (s == 0) ? svr[b*HH + n*HDIM + d]
                            : kv2[((size_t)b*LL + s-1)*(2*HH) + HH + n*HDIM + d];
        acc += w*vv;
    }
    part[stripe][d] = acc;
    __syncthreads();
    if (tid < HDIM) {
        float r = (part[0][tid] + part[1][tid] + part[2][tid] + part[3][tid]) / bsum;
        satt[b*HH + n*HDIM + tid] = r;
    }
}

// ---------------- zero out masked node rows (fp32 + hi/lo) ----------------
__global__ void mask_nodes_kernel(float* __restrict__ nodes, f16* __restrict__ nh,
                                  f16* __restrict__ nl, const int* __restrict__ mask)
{
    int idx = blockIdx.x * blockDim.x + threadIdx.x;
    if (idx >= BB*LL*HH) return;
    if (mask[idx / HH]) {
        nodes[idx] = 0.f;
        nh[idx] = __float2half(0.f);
        nl[idx] = __float2half(0.f);
    }
}

// ---------------- build ft = [relay, nodes[b, positions[b]]] ----------------
__global__ void gather_ft_kernel(const float* __restrict__ relay, const float* __restrict__ nodes,
                                 const int* __restrict__ pos, float* __restrict__ ft)
{
    int i = blockIdx.x * blockDim.x + threadIdx.x;
    if (i >= BB*2*HH) return;
    int b = i / (2*HH), c = i % (2*HH);
    ft[i] = (c < HH) ? relay[b*HH + c]
                     : nodes[((size_t)b*LL + pos[b])*HH + (c - HH)];
}

// ---------------- host orchestration ----------------
extern "C" void kernel_launch(void* const* d_in, const int* in_sizes, int n_in,
                              void* d_out, int out_size)
{
    const int*   src       = (const int*)d_in[0];
    const int*   positions = (const int*)d_in[1];
    const float* emb       = (const float*)d_in[2];
    const float* pos_table = (const float*)d_in[3];
    const float* norm_g    = (const float*)d_in[4];
    const float* norm_b    = (const float*)d_in[5];
    const float* pw_w1     = (const float*)d_in[6];
    const float* pw_b1     = (const float*)d_in[7];
    const float* pw_w2     = (const float*)d_in[8];
    const float* pw_b2     = (const float*)d_in[9];
    const float* pw_g      = (const float*)d_in[10];
    const float* pw_bn     = (const float*)d_in[11];
    const float* ring_wq   = (const float*)d_in[12];
    const float* ring_bq   = (const float*)d_in[13];
    const float* ring_wk   = (const float*)d_in[14];
    const float* ring_bk   = (const float*)d_in[15];
    const float* ring_wv   = (const float*)d_in[16];
    const float* ring_bv   = (const float*)d_in[17];
    const float* ring_wo   = (const float*)d_in[18];
    const float* ring_bo   = (const float*)d_in[19];
    const float* star_wq   = (const float*)d_in[20];
    const float* star_bq   = (const float*)d_in[21];
    const float* star_wk   = (const float*)d_in[22];
    const float* star_bk   = (const float*)d_in[23];
    const float* star_wv   = (const float*)d_in[24];
    const float* star_bv   = (const float*)d_in[25];
    const float* star_wo   = (const float*)d_in[26];
    const float* star_bo   = (const float*)d_in[27];
    const float* head_w1   = (const float*)d_in[28];
    const float* head_b1   = (const float*)d_in[29];
    const float* head_w2   = (const float*)d_in[30];
    const float* head_b2   = (const float*)d_in[31];
    float* out = (float*)d_out;

    cudaFuncSetAttribute(gemm_h2, cudaFuncAttributeMaxDynamicSharedMemorySize, GSMEM);

    float *nodes, *h, *qkv, *relay, *rk, *rv, *sq, *skr, *svr, *satt, *ft, *hid, *bqkv, *bkv2;
    int* maskp;
    f16 *nodes_h, *nodes_l, *h_h, *h_l, *att_h, *att_l, *ff_h, *ff_l;
    f16 *w1f, *w2f, *wqkvf, *wof, *wkv2f;

    cudaGetSymbolAddress((void**)&nodes, g_nodes);
    cudaGetSymbolAddress((void**)&h,     g_h);
    cudaGetSymbolAddress((void**)&qkv,   g_qkv);
    cudaGetSymbolAddress((void**)&relay, g_relay);
    cudaGetSymbolAddress((void**)&rk,    g_rk);
    cudaGetSymbolAddress((void**)&rv,    g_rv);
    cudaGetSymbolAddress((void**)&sq,    g_sq);
    cudaGetSymbolAddress((void**)&skr,   g_skr);
    cudaGetSymbolAddress((void**)&svr,   g_svr);
    cudaGetSymbolAddress((void**)&satt,  g_satt);
    cudaGetSymbolAddress((void**)&ft,    g_ft);
    cudaGetSymbolAddress((void**)&hid,   g_hid);
    cudaGetSymbolAddress((void**)&maskp, g_mask);
    cudaGetSymbolAddress((void**)&bqkv,  g_bqkv);
    cudaGetSymbolAddress((void**)&bkv2,  g_bkv2);
    cudaGetSymbolAddress((void**)&nodes_h, g_nodes_h);
    cudaGetSymbolAddress((void**)&nodes_l, g_nodes_l);
    cudaGetSymbolAddress((void**)&h_h,   g_h_h);
    cudaGetSymbolAddress((void**)&h_l,   g_h_l);
    cudaGetSymbolAddress((void**)&att_h, g_att_h);
    cudaGetSymbolAddress((void**)&att_l, g_att_l);
    cudaGetSymbolAddress((void**)&ff_h,  g_ff_h);
    cudaGetSymbolAddress((void**)&ff_l,  g_ff_l);
    cudaGetSymbolAddress((void**)&w1f,   g_w1f);
    cudaGetSymbolAddress((void**)&w2f,   g_w2f);
    cudaGetSymbolAddress((void**)&wqkvf, g_wqkv);
    cudaGetSymbolAddress((void**)&wof,   g_wof);
    cudaGetSymbolAddress((void**)&wkv2f, g_wkv2);

    const int M = BB*LL;                    // 8192
    dim3 g_ff1(DIN/128, M/128);             // (24, 64)
    dim3 g_ff2(HH/128, M/128);              // (6, 64)
    dim3 g_qkvd(3*HH/128, M/128);           // (18, 64)
    dim3 g_od(HH/128, M/128);               // (6, 64)
    dim3 g_kv2(2*HH/128, M/128);            // (12, 64)

    embed_kernel<<<(BB*LL*HH + 255)/256, 256>>>(src, emb, pos_table, nodes, nodes_h, nodes_l);
    mask_kernel<<<(BB*LL + 255)/256, 256>>>(src, maskp);
    relay_zero_kernel<<<(BB*HH + 255)/256, 256>>>(relay);
    relay_partial_kernel<<<dim3(BB, 3, 16), 256>>>(nodes, relay);

    for (int i = 0; i < 2; i++) {
        const float* w1 = pw_w1 + (size_t)i*DIN*HH;
        const float* b1 = pw_b1 + i*DIN;
        const float* w2 = pw_w2 + (size_t)i*HH*DIN;
        const float* b2 = pw_b2 + i*HH;
        const float* rwq = ring_wq + (size_t)i*HH*HH; const float* rbq = ring_bq + i*HH;
        const float* rwk = ring_wk + (size_t)i*HH*HH; const float* rbk = ring_bk + i*HH;
        const float* rwv = ring_wv + (size_t)i*HH*HH; const float* rbv = ring_bv + i*HH;
        const float* rwo = ring_wo + (size_t)i*HH*HH; const float* rbo = ring_bo + i*HH;
        const float* swq = star_wq + (size_t)i*HH*HH; const float* sbq = star_bq + i*HH;
        const float* swk = star_wk + (size_t)i*HH*HH; const float* sbk = star_bk + i*HH;
        const float* swv = star_wv + (size_t)i*HH*HH; const float* sbv = star_bv + i*HH;
        const float* swo = star_wo + (size_t)i*HH*HH; const float* sbo = star_bo + i*HH;

        convert_kernel<<<(DIN*HH + 255)/256, 256>>>(w1, w1f, DIN*HH);
        convert_kernel<<<(HH*DIN + 255)/256, 256>>>(w2, w2f, HH*DIN);
        convert_kernel<<<(HH*HH + 255)/256, 256>>>(rwq, wqkvf,           HH*HH);
        convert_kernel<<<(HH*HH + 255)/256, 256>>>(rwk, wqkvf + HH*HH,   HH*HH);
        convert_kernel<<<(HH*HH + 255)/256, 256>>>(rwv, wqkvf + 2*HH*HH, HH*HH);
        convert_kernel<<<(HH*HH + 255)/256, 256>>>(rwo, wof, HH*HH);
        convert_kernel<<<(HH*HH + 255)/256, 256>>>(swk, wkv2f,         HH*HH);
        convert_kernel<<<(HH*HH + 255)/256, 256>>>(swv, wkv2f + HH*HH, HH*HH);
        cudaMemcpyAsync(bqkv,        rbq, HH*sizeof(float), cudaMemcpyDeviceToDevice);
        cudaMemcpyAsync(bqkv + HH,   rbk, HH*sizeof(float), cudaMemcpyDeviceToDevice);
        cudaMemcpyAsync(bqkv + 2*HH, rbv, HH*sizeof(float), cudaMemcpyDeviceToDevice);
        cudaMemcpyAsync(bkv2,        sbk, HH*sizeof(float), cudaMemcpyDeviceToDevice);
        cudaMemcpyAsync(bkv2 + HH,   sbv, HH*sizeof(float), cudaMemcpyDeviceToDevice);

        // PWFF: ff = relu(nodes@w1^T + b1) -> fp16 pair; h = LN(ff@w2^T + b2 + nodes)
        gemm_h2<<<g_ff1, 128, GSMEM>>>(nodes_h, nodes_l, w1f, b1,
                                       (float*)0, ff_h, ff_l, M, DIN, HH, 1, 1);
        gemm_h2<<<g_ff2, 128, GSMEM>>>(ff_h, ff_l, w2f, b2,
                                       h, (f16*)0, (f16*)0, M, HH, DIN, 0, 0);
        ln_kernel<<<M, 256>>>(h, nodes, pw_g + i*HH, pw_bn + i*HH, h, h_h, h_l, 0);

        // fused ring q|k|v; relay k/v
        gemm_h2<<<g_qkvd, 128, GSMEM>>>(h_h, h_l, wqkvf, bqkv,
                                        qkv, (f16*)0, (f16*)0, M, 3*HH, HH, 0, 0);
        small_nt_kernel<<<(BB*HH + 7)/8, 256>>>(relay, rwk, rbk, rk, BB, HH, HH, HH, 0);
        small_nt_kernel<<<(BB*HH + 7)/8, 256>>>(relay, rwv, rbv, rv, BB, HH, HH, HH, 0);

        ring_attn_kernel<<<(BB*LL*NHEAD)/8, 256>>>(qkv, rk, rv, att_h, att_l);

        // ring output proj (into qkv scratch) -> LN -> leaky -> nodes (+ hi/lo)
        gemm_h2<<<g_od, 128, GSMEM>>>(att_h, att_l, wof, rbo,
                                      qkv, (f16*)0, (f16*)0, M, HH, HH, 0, 0);
        ln_kernel<<<M, 256>>>(qkv, (const float*)0, norm_g + i*HH, norm_b + i*HH,
                              nodes, nodes_h, nodes_l, 1);

        // star attention: fused k|v GEMM (into qkv scratch, stride 1536)
        small_nt_kernel<<<(BB*HH + 7)/8, 256>>>(relay, swq, sbq, sq,  BB, HH, HH, HH, 0);
        small_nt_kernel<<<(BB*HH + 7)/8, 256>>>(relay, swk, sbk, skr, BB, HH, HH, HH, 0);
        small_nt_kernel<<<(BB*HH + 7)/8, 256>>>(relay, swv, sbv, svr, BB, HH, HH, HH, 0);
        gemm_h2<<<g_kv2, 128, GSMEM>>>(nodes_h, nodes_l, wkv2f, bkv2,
                                       qkv, (f16*)0, (f16*)0, M, 2*HH, HH, 0, 0);
        star_attn_kernel<<<BB*NHEAD, 256>>>(sq, skr, svr, qkv, maskp, satt);
        small_nt_kernel<<<(BB*HH + 7)/8, 256>>>(satt, swo, sbo, relay, BB, HH, HH, HH, 2);

        mask_nodes_kernel<<<(BB*LL*HH + 255)/256, 256>>>(nodes, nodes_h, nodes_l, maskp);
    }

    // heads
    gather_ft_kernel<<<(BB*2*HH + 255)/256, 256>>>(relay, nodes, positions, ft);
    for (int j = 0; j < 3; j++) {
        small_nt_kernel<<<(BB*1024 + 7)/8, 256>>>(ft, head_w1 + (size_t)j*1024*2*HH,
                                                  head_b1 + j*1024, hid + (size_t)j*BB*1024,
                                                  BB, 1024, 2*HH, 1024, 1);
        small_nt_kernel<<<(BB*5000 + 7)/8, 256>>>(hid + (size_t)j*BB*1024,
                                                  head_w2 + (size_t)j*5000*1024,
                                                  head_b2 + j*5000, out + j*5000,
                                                  BB, 5000, 1024, 15000, 0);
    }
}

// round 10
// speedup vs baseline: 4.3368x; 1.0122x over previous
#include <cuda_runtime.h>
#include <cuda_fp16.h>
#include <math.h>
#include <stdint.h>

#define BB 8
#define LL 1024
#define HH 768
#define NHEAD 12
#define HDIM 64
#define DIN 3072
#define ATT_SCALE 0.125f
#define FULLMASK 0xffffffffu

typedef __half f16;

// ---------------- scratch (device globals; no allocations allowed) ----------------
__device__ float g_nodes[BB*LL*HH];
__device__ float g_h[BB*LL*HH];
__device__ float g_qkv[BB*LL*3*HH];     // fused q|k|v (stride 2304); also split-K partial buffers
__device__ float g_relay[BB*HH];
__device__ float g_rk[BB*HH];
__device__ float g_rv[BB*HH];
__device__ float g_sq[BB*HH];
__device__ float g_skr[BB*HH];
__device__ float g_svr[BB*HH];
__device__ float g_satt[BB*HH];
__device__ float g_ft[BB*2*HH];
__device__ float g_hid[3*BB*1024];
__device__ int   g_mask[BB*LL];
__device__ float g_bqkv[3*HH];
__device__ float g_bkv2[2*HH];

// fp16 hi/lo activation buffers
__device__ f16 g_nodes_h[BB*LL*HH];
__device__ f16 g_nodes_l[BB*LL*HH];
__device__ f16 g_h_h[BB*LL*HH];
__device__ f16 g_h_l[BB*LL*HH];
__device__ f16 g_att_h[BB*LL*HH];
__device__ f16 g_att_l[BB*LL*HH];
__device__ f16 g_ff_h[BB*LL*DIN];
__device__ f16 g_ff_l[BB*LL*DIN];

// fp16 weight buffers (reused per layer)
__device__ f16 g_w1f[DIN*HH];
__device__ f16 g_w2f[HH*DIN];
__device__ f16 g_wqkv[3*HH*HH];   // ring q|k|v concat
__device__ f16 g_wof[HH*HH];
__device__ f16 g_wkv2[2*HH*HH];   // star k|v concat

// ---------------- helpers ----------------
__device__ __forceinline__ uint32_t smem_u32(const void* p) {
    return (uint32_t)__cvta_generic_to_shared(p);
}

#define CP16(dst, src) asm volatile("cp.async.cg.shared.global [%0], [%1], 16;" :: "r"(dst), "l"(src))

#define LDSM4(R, addr) \
    asm volatile("ldmatrix.sync.aligned.m8n8.x4.shared.b16 {%0,%1,%2,%3}, [%4];" \
                 : "=r"((R)[0]), "=r"((R)[1]), "=r"((R)[2]), "=r"((R)[3]) : "r"(addr))

#define MMA16816(D, A, B0, B1) \
    asm volatile("mma.sync.aligned.m16n8k16.row.col.f32.f16.f16.f32 " \
                 "{%0,%1,%2,%3}, {%4,%5,%6,%7}, {%8,%9}, {%0,%1,%2,%3};" \
                 : "+f"((D)[0]), "+f"((D)[1]), "+f"((D)[2]), "+f"((D)[3]) \
                 : "r"((A)[0]), "r"((A)[1]), "r"((A)[2]), "r"((A)[3]), "r"(B0), "r"(B1))

__device__ __forceinline__ void split_store(float v, f16* h, f16* l, size_t idx) {
    f16 hi = __float2half(v);
    h[idx] = hi;
    l[idx] = __float2half(v - __half2float(hi));
}

// ---------------- fp32 -> fp16 weight converts (fused variants) ----------------
__global__ void convert_kernel(const float* __restrict__ x, f16* __restrict__ o, int n)
{
    int i = blockIdx.x * blockDim.x + threadIdx.x;
    if (i < n) o[i] = __float2half(x[i]);
}

__global__ void convert3_kernel(const float* __restrict__ a, const float* __restrict__ b,
                                const float* __restrict__ c, f16* __restrict__ o, int n)
{
    int i = blockIdx.x * blockDim.x + threadIdx.x;
    if (i < n) o[i] = __float2half(a[i]);
    else if (i < 2*n) o[i] = __float2half(b[i - n]);
    else if (i < 3*n) o[i] = __float2half(c[i - 2*n]);
}

__global__ void convert2_kernel(const float* __restrict__ a, const float* __restrict__ b,
                                f16* __restrict__ o, int n)
{
    int i = blockIdx.x * blockDim.x + threadIdx.x;
    if (i < n) o[i] = __float2half(a[i]);
    else if (i < 2*n) o[i] = __float2half(b[i - n]);
}

__global__ void bias3_kernel(const float* __restrict__ a, const float* __restrict__ b,
                             const float* __restrict__ c, float* __restrict__ o)
{
    int i = blockIdx.x * blockDim.x + threadIdx.x;
    if (i < HH) o[i] = a[i];
    else if (i < 2*HH) o[i] = b[i - HH];
    else if (i < 3*HH) o[i] = c[i - 2*HH];
}

__global__ void bias2_kernel(const float* __restrict__ a, const float* __restrict__ b,
                             float* __restrict__ o)
{
    int i = blockIdx.x * blockDim.x + threadIdx.x;
    if (i < HH) o[i] = a[i];
    else if (i < 2*HH) o[i] = b[i - HH];
}

// ---------------- embedding + positional (fp32 + hi/lo) ----------------
__global__ void embed_kernel(const int* __restrict__ src, const float* __restrict__ emb,
                             const float* __restrict__ pos, float* __restrict__ nodes,
                             f16* __restrict__ nh, f16* __restrict__ nl)
{
    int idx = blockIdx.x * blockDim.x + threadIdx.x;
    if (idx >= BB*LL*HH) return;
    int hh = idx % HH;
    int bl = idx / HH;
    int l  = bl % LL;
    int j  = hh >> 8;
    int d  = hh & 255;
    int tok = src[bl*3 + j];
    float v = emb[tok*256 + d] + pos[l*HH + hh];
    nodes[idx] = v;
    split_store(v, nh, nl, idx);
}

__global__ void mask_kernel(const int* __restrict__ src, int* __restrict__ mask)
{
    int i = blockIdx.x * blockDim.x + threadIdx.x;
    if (i < BB*LL) mask[i] = (src[i*3] == 0) ? 1 : 0;
}

__global__ void relay_zero_kernel(float* __restrict__ relay)
{
    int i = blockIdx.x * 256 + threadIdx.x;
    if (i < BB*HH) relay[i] = 0.f;
}

__global__ void relay_partial_kernel(const float* __restrict__ nodes, float* __restrict__ relay)
{
    int b  = blockIdx.x;
    int hh = blockIdx.y * 256 + threadIdx.x;
    int l0 = blockIdx.z * 64;
    const float* p = nodes + ((size_t)b*LL + l0)*HH + hh;
    float s = 0.f;
    #pragma unroll 8
    for (int l = 0; l < 64; l++) s += p[(size_t)l*HH];
    atomicAdd(&relay[b*HH + hh], s * (1.0f/1024.0f));
}

// ---------------- tensor-core GEMM (fp16x2): C = A*W^T + bias ----------------
// Block 128x128x32; 4 warps, warp tile 64x64; 3-stage cp.async pipeline.
// A: hi/lo [M,K] fp16 row-major; W: fp16 [N,K] row-major.
// gridDim.z == 1: normal. gridDim.z == 2: split-K; each z writes its partial
// (fp32 only) to Cf + z*M*N; bias added by z==0 only. Consumer sums partials.
// outpair=0: Cf fp32; outpair=1: Ch/Cl fp16 pair. act: 0 none, 1 relu.
#define GSTAGE 24576u
#define GSMEM  73728

__global__ void __launch_bounds__(128, 2) gemm_h2(
    const f16* __restrict__ Ah, const f16* __restrict__ Al,
    const f16* __restrict__ W, const float* __restrict__ bias,
    float* __restrict__ Cf, f16* __restrict__ Ch, f16* __restrict__ Cl,
    int M, int N, int K, int act, int outpair)
{
    extern __shared__ __align__(16) f16 smem[];
    const uint32_t sb = smem_u32(smem);
    const int tid  = threadIdx.x;
    const int lane = tid & 31;
    const int warp = tid >> 5;
    const int wm = warp & 1;     // 2 warps along M (64 rows each)
    const int wnn = warp >> 1;   // 2 warps along N (64 cols each)
    const int bm = blockIdx.y * 128;
    const int bn = blockIdx.x * 128;
    const int kz = blockIdx.z;
    const int kseg = K / gridDim.z;
    const int kof = kz * kseg;
    const int niter = kseg >> 5;

    // ldmatrix byte offsets within a stage tile (128 rows x 32 halves, swizzled)
    const int li = lane >> 3;
    const int lr = lane & 7;
    uint32_t aoff[4][2], woff[4][2];
    #pragma unroll
    for (int mi = 0; mi < 4; mi++)
        #pragma unroll
        for (int ks = 0; ks < 2; ks++) {
            int row = wm*64 + mi*16 + ((li & 1) << 3) + lr;
            int c   = (ks << 1) + (li >> 1);
            aoff[mi][ks] = (uint32_t)((row*32 + ((c ^ ((row >> 1) & 3)) << 3)) * 2);
        }
    #pragma unroll
    for (int nj = 0; nj < 4; nj++)
        #pragma unroll
        for (int ks = 0; ks < 2; ks++) {
            int row = wnn*64 + nj*16 + ((li >> 1) << 3) + lr;
            int c   = (ks << 1) + (li & 1);
            woff[nj][ks] = (uint32_t)((row*32 + ((c ^ ((row >> 1) & 3)) << 3)) * 2);
        }

    // global load coords: 512 16B-chunks per 128x32 tile, 4 per thread
    int rowv[4], cv[4]; uint32_t swv[4];
    #pragma unroll
    for (int i = 0; i < 4; i++) {
        int id = tid + i*128;
        rowv[i] = id >> 2;
        cv[i]   = id & 3;
        swv[i]  = (uint32_t)((rowv[i]*32 + ((cv[i] ^ ((rowv[i] >> 1) & 3)) << 3)) * 2);
    }

    #define LOAD_STAGE(st, kt) do { \
        uint32_t tb = sb + (uint32_t)(st)*GSTAGE; \
        _Pragma("unroll") \
        for (int i = 0; i < 4; i++) { \
            size_t ga = (size_t)(bm + rowv[i])*K + kof + (kt) + cv[i]*8; \
            size_t gw = (size_t)(bn + rowv[i])*K + kof + (kt) + cv[i]*8; \
            CP16(tb +          swv[i], Ah + ga); \
            CP16(tb + 8192u  + swv[i], Al + ga); \
            CP16(tb + 16384u + swv[i], W  + gw); \
        } \
        asm volatile("cp.async.commit_group;"); \
    } while (0)

    float acc[4][8][4];
    #pragma unroll
    for (int mi = 0; mi < 4; mi++)
        #pragma unroll
        for (int nf = 0; nf < 8; nf++)
            #pragma unroll
            for (int e = 0; e < 4; e++) acc[mi][nf][e] = 0.f;

    LOAD_STAGE(0, 0);
    LOAD_STAGE(1, 32);

    int st = 0;        // stage of current iter
    int lst = 2;       // stage to load next
    for (int it = 0; it < niter; it++) {
        if (it + 1 < niter) {
            asm volatile("cp.async.wait_group 1;");
        } else {
            asm volatile("cp.async.wait_group 0;");
        }
        __syncthreads();

        if (it + 2 < niter) {
            LOAD_STAGE(lst, (it + 2) * 32);
            if (++lst == 3) lst = 0;
        }

        const uint32_t cA  = sb + (uint32_t)st*GSTAGE;
        const uint32_t cAl = cA + 8192u;
        const uint32_t cW  = cA + 16384u;
        if (++st == 3) st = 0;

        #pragma unroll
        for (int ks = 0; ks < 2; ks++) {
            uint32_t fah[4][4], fal[4][4], fw[8][2];
            #pragma unroll
            for (int mi = 0; mi < 4; mi++) LDSM4(fah[mi], cA  + aoff[mi][ks]);
            #pragma unroll
            for (int mi = 0; mi < 4; mi++) LDSM4(fal[mi], cAl + aoff[mi][ks]);
            #pragma unroll
            for (int nj = 0; nj < 4; nj++) {
                uint32_t t4[4];
                LDSM4(t4, cW + woff[nj][ks]);
                fw[nj*2][0]   = t4[0]; fw[nj*2][1]   = t4[1];
                fw[nj*2+1][0] = t4[2]; fw[nj*2+1][1] = t4[3];
            }
            #pragma unroll
            for (int mi = 0; mi < 4; mi++)
                #pragma unroll
                for (int nf = 0; nf < 8; nf++) {
                    MMA16816(acc[mi][nf], fah[mi], fw[nf][0], fw[nf][1]);
                    MMA16816(acc[mi][nf], fal[mi], fw[nf][0], fw[nf][1]);
                }
        }
    }

    // epilogue
    float* Cfz = Cf + (size_t)kz * M * N;
    const int useb = (kz == 0);
    const int em = lane >> 2;
    const int en = (lane & 3) << 1;
    #pragma unroll
    for (int mi = 0; mi < 4; mi++) {
        #pragma unroll
        for (int nf = 0; nf < 8; nf++) {
            int col = bn + wnn*64 + nf*8 + en;
            float b0 = useb ? bias[col] : 0.f;
            float b1 = useb ? bias[col + 1] : 0.f;
            #pragma unroll
            for (int hf = 0; hf < 2; hf++) {
                int row = bm + wm*64 + mi*16 + em + hf*8;
                float v0 = acc[mi][nf][hf*2 + 0] + b0;
                float v1 = acc[mi][nf][hf*2 + 1] + b1;
                if (act == 1) { v0 = fmaxf(v0, 0.f); v1 = fmaxf(v1, 0.f); }
                size_t o2 = (size_t)row*N + col;
                if (outpair) {
                    f16 h0 = __float2half(v0);
                    f16 h1 = __float2half(v1);
                    __half2 hp, lp;
                    hp.x = h0; hp.y = h1;
                    lp.x = __float2half(v0 - __half2float(h0));
                    lp.y = __float2half(v1 - __half2float(h1));
                    *(__half2*)(Ch + o2) = hp;
                    *(__half2*)(Cl + o2) = lp;
                } else {
                    float2 r; r.x = v0; r.y = v1;
                    *(float2*)(Cfz + o2) = r;
                }
            }
        }
    }
    #undef LOAD_STAGE
}

// ---------------- small GEMM (warp-per-output) ----------------
__global__ void small_nt_kernel(const float* __restrict__ A, const float* __restrict__ W,
                                const float* __restrict__ bias, float* __restrict__ C,
                                int M, int N, int K, int ldc, int act)
{
    int w = (blockIdx.x * blockDim.x + threadIdx.x) >> 5;
    int lane = threadIdx.x & 31;
    if (w >= M*N) return;
    int m = w / N, n = w % N;
    const float4* a  = (const float4*)(A + (size_t)m*K);
    const float4* wr = (const float4*)(W + (size_t)n*K);
    float s = 0.f;
    int K4 = K >> 2;
    for (int c = lane; c < K4; c += 32) {
        float4 av = a[c], wv = wr[c];
        s += av.x*wv.x + av.y*wv.y + av.z*wv.z + av.w*wv.w;
    }
    #pragma unroll
    for (int o = 16; o > 0; o >>= 1) s += __shfl_xor_sync(FULLMASK, s, o);
    if (lane == 0) {
        s += bias[n];
        if (act == 1) s = fmaxf(s, 0.f);
        else if (act == 2 && s < 0.f) s *= 0.01f;
        C[(size_t)m*ldc + n] = s;
    }
}

// ---------------- LayerNorm (row=768): X (+X2) (+RES), optional leaky, hi/lo out ----------------
__global__ void __launch_bounds__(256) ln_kernel(
    const float* __restrict__ X, const float* __restrict__ X2,
    const float* __restrict__ RES,
    const float* __restrict__ g, const float* __restrict__ b,
    float* __restrict__ out, f16* __restrict__ oh, f16* __restrict__ ol, int leaky)
{
    __shared__ float shs[8], shs2[8];
    __shared__ float smean, sinv;
    int row = blockIdx.x;
    int tid = threadIdx.x;
    const float* x = X + (size_t)row*HH;
    float v0 = x[tid], v1 = x[tid+256], v2 = x[tid+512];
    if (X2) {
        const float* x2 = X2 + (size_t)row*HH;
        v0 += x2[tid]; v1 += x2[tid+256]; v2 += x2[tid+512];
    }
    if (RES) {
        const float* r = RES + (size_t)row*HH;
        v0 += r[tid]; v1 += r[tid+256]; v2 += r[tid+512];
    }
    float s  = v0+v1+v2;
    float s2 = v0*v0 + v1*v1 + v2*v2;
    #pragma unroll
    for (int o = 16; o > 0; o >>= 1) {
        s  += __shfl_xor_sync(FULLMASK, s, o);
        s2 += __shfl_xor_sync(FULLMASK, s2, o);
    }
    if ((tid & 31) == 0) { shs[tid>>5] = s; shs2[tid>>5] = s2; }
    __syncthreads();
    if (tid == 0) {
        float ts = 0.f, ts2 = 0.f;
        for (int i = 0; i < 8; i++) { ts += shs[i]; ts2 += shs2[i]; }
        float mean = ts * (1.0f/768.0f);
        float var  = ts2 * (1.0f/768.0f) - mean*mean;
        smean = mean;
        sinv  = rsqrtf(var + 1e-5f);
    }
    __syncthreads();
    float mean = smean, inv = sinv;
    size_t base = (size_t)row*HH;
    float y0 = (v0-mean)*inv*g[tid]     + b[tid];
    float y1 = (v1-mean)*inv*g[tid+256] + b[tid+256];
    float y2 = (v2-mean)*inv*g[tid+512] + b[tid+512];
    if (leaky) {
        if (y0 < 0.f) y0 *= 0.01f;
        if (y1 < 0.f) y1 *= 0.01f;
        if (y2 < 0.f) y2 *= 0.01f;
    }
    out[base+tid] = y0; out[base+tid+256] = y1; out[base+tid+512] = y2;
    if (oh) {
        split_store(y0, oh, ol, base+tid);
        split_store(y1, oh, ol, base+tid+256);
        split_store(y2, oh, ol, base+tid+512);
    }
}

// ---------------- ring attention over fused qkv (stride 2304) ----------------
__global__ void __launch_bounds__(256) ring_attn_kernel(
    const float* __restrict__ qkv, const float* __restrict__ rk, const float* __restrict__ rv,
    f16* __restrict__ ah, f16* __restrict__ al)
{
    int gw = (blockIdx.x * 256 + threadIdx.x) >> 5;
    int lane = threadIdx.x & 31;
    if (gw >= BB*LL*NHEAD) return;
    int n  = gw % NHEAD;
    int bl = gw / NHEAD;
    int l  = bl % LL;
    int b  = bl / LL;
    const float* qp = qkv + (size_t)bl*(3*HH) + n*HDIM;
    float q0 = qp[lane], q1 = qp[lane+32];

    float s[4];
    #pragma unroll
    for (int w = 0; w < 3; w++) {
        int ll = l + w - 1;
        float d = 0.f;
        if (ll >= 0 && ll < LL) {
            const float* kp = qkv + ((size_t)b*LL + ll)*(3*HH) + HH + n*HDIM;
            d = q0*kp[lane] + q1*kp[lane+32];
        }
        #pragma unroll
        for (int o = 16; o > 0; o >>= 1) d += __shfl_xor_sync(FULLMASK, d, o);
        s[w] = d;
    }
    {
        const float* kp = rk + b*HH + n*HDIM;
        float d = q0*kp[lane] + q1*kp[lane+32];
        #pragma unroll
        for (int o = 16; o > 0; o >>= 1) d += __shfl_xor_sync(FULLMASK, d, o);
        s[3] = d;
    }
    float sc0 = s[0]*ATT_SCALE, sc1 = s[1]*ATT_SCALE, sc2 = s[2]*ATT_SCALE, sc3 = s[3]*ATT_SCALE;
    float m = fmaxf(fmaxf(sc0, sc1), fmaxf(sc2, sc3));
    float e0 = expf(sc0-m), e1 = expf(sc1-m), e2 = expf(sc2-m), e3 = expf(sc3-m);
    float inv = 1.f / (e0+e1+e2+e3);
    float a0 = e0*inv, a1 = e1*inv, a2 = e2*inv, a3 = e3*inv;

    const float* rvp = rv + b*HH + n*HDIM;
    float o0 = a3 * rvp[lane];
    float o1 = a3 * rvp[lane+32];
    float aw[3] = {a0, a1, a2};
    #pragma unroll
    for (int w = 0; w < 3; w++) {
        int ll = l + w - 1;
        if (ll >= 0 && ll < LL) {
            const float* vp = qkv + ((size_t)b*LL + ll)*(3*HH) + 2*HH + n*HDIM;
            o0 += aw[w] * vp[lane];
            o1 += aw[w] * vp[lane+32];
        }
    }
    size_t o = (size_t)bl*HH + n*HDIM;
    split_store(o0, ah, al, o + lane);
    split_store(o1, ah, al, o + lane + 32);
}

// ---------------- star attention over fused kv (stride 1536) ----------------
__global__ void __launch_bounds__(256) star_attn_kernel(
    const float* __restrict__ sq, const float* __restrict__ skr, const float* __restrict__ svr,
    const float* __restrict__ kv2, const int* __restrict__ mask,
    float* __restrict__ satt)
{
    __shared__ float sc[LL+1];
    __shared__ float qv[HDIM];
    __shared__ float red[8];
    __shared__ float bmax, bsum;
    __shared__ float part[4][HDIM];
    int b = blockIdx.x / NHEAD;
    int n = blockIdx.x % NHEAD;
    int tid = threadIdx.x;

    if (tid < HDIM) qv[tid] = sq[b*HH + n*HDIM + tid];
    __syncthreads();

    for (int s = tid; s <= LL; s += 256) {
        float d;
        if (s > 0 && mask[b*LL + s-1]) d = -INFINITY;
        else {
            const float* kp = (s == 0) ? (skr + b*HH + n*HDIM)
                                       : (kv2 + ((size_t)b*LL + s-1)*(2*HH) + n*HDIM);
            float acc = 0.f;
            #pragma unroll 16
            for (int dd = 0; dd < HDIM; dd++) acc += qv[dd]*kp[dd];
            d = acc * ATT_SCALE;
        }
        sc[s] = d;
    }
    __syncthreads();

    float m = -INFINITY;
    for (int s = tid; s <= LL; s += 256) m = fmaxf(m, sc[s]);
    #pragma unroll
    for (int o = 16; o > 0; o >>= 1) m = fmaxf(m, __shfl_xor_sync(FULLMASK, m, o));
    if ((tid & 31) == 0) red[tid>>5] = m;
    __syncthreads();
    if (tid == 0) {
        float mm = red[0];
        for (int i = 1; i < 8; i++) mm = fmaxf(mm, red[i]);
        bmax = mm;
    }
    __syncthreads();

    float psum = 0.f;
    for (int s = tid; s <= LL; s += 256) {
        float e = expf(sc[s] - bmax);
        sc[s] = e;
        psum += e;
    }
    #pragma unroll
    for (int o = 16; o > 0; o >>= 1) psum += __shfl_xor_sync(FULLMASK, psum, o);
    if ((tid & 31) == 0) red[tid>>5] = psum;
    __syncthreads();
    if (tid == 0) {
        float ss = 0.f;
        for (int i = 0; i < 8; i++) ss += red[i];
        bsum = ss;
    }
    __syncthreads();

    int d = tid & 63, stripe = tid >> 6;
    float acc = 0.f;
    for (int s = stripe; s <= LL; s += 4) {
        float w = sc[s];
        float vv = (s == 0) ? svr[b*HH + n*HDIM + d]
                            : kv2[((size_t)b*LL + s-1)*(2*HH) + HH + n*HDIM + d];
        acc += w*vv;
    }
    part[stripe][d] = acc;
    __syncthreads();
    if (tid < HDIM) {
        float r = (part[0][tid] + part[1][tid] + part[2][tid] + part[3][tid]) / bsum;
        satt[b*HH + n*HDIM + tid] = r;
    }
}

// ---------------- zero out masked node rows (fp32 + hi/lo) ----------------
__global__ void mask_nodes_kernel(float* __restrict__ nodes, f16* __restrict__ nh,
                                  f16* __restrict__ nl, const int* __restrict__ mask)
{
    int idx = blockIdx.x * blockDim.x + threadIdx.x;
    if (idx >= BB*LL*HH) return;
    if (mask[idx / HH]) {
        nodes[idx] = 0.f;
        nh[idx] = __float2half(0.f);
        nl[idx] = __float2half(0.f);
    }
}

// ---------------- build ft = [relay, nodes[b, positions[b]]] ----------------
__global__ void gather_ft_kernel(const float* __restrict__ relay, const float* __restrict__ nodes,
                                 const int* __restrict__ pos, float* __restrict__ ft)
{
    int i = blockIdx.x * blockDim.x + threadIdx.x;
    if (i >= BB*2*HH) return;
    int b = i / (2*HH), c = i % (2*HH);
    ft[i] = (c < HH) ? relay[b*HH + c]
                     : nodes[((size_t)b*LL + pos[b])*HH + (c - HH)];
}

// ---------------- host orchestration ----------------
extern "C" void kernel_launch(void* const* d_in, const int* in_sizes, int n_in,
                              void* d_out, int out_size)
{
    const int*   src       = (const int*)d_in[0];
    const int*   positions = (const int*)d_in[1];
    const float* emb       = (const float*)d_in[2];
    const float* pos_table = (const float*)d_in[3];
    const float* norm_g    = (const float*)d_in[4];
    const float* norm_b    = (const float*)d_in[5];
    const float* pw_w1     = (const float*)d_in[6];
    const float* pw_b1     = (const float*)d_in[7];
    const float* pw_w2     = (const float*)d_in[8];
    const float* pw_b2     = (const float*)d_in[9];
    const float* pw_g      = (const float*)d_in[10];
    const float* pw_bn     = (const float*)d_in[11];
    const float* ring_wq   = (const float*)d_in[12];
    const float* ring_bq   = (const float*)d_in[13];
    const float* ring_wk   = (const float*)d_in[14];
    const float* ring_bk   = (const float*)d_in[15];
    const float* ring_wv   = (const float*)d_in[16];
    const float* ring_bv   = (const float*)d_in[17];
    const float* ring_wo   = (const float*)d_in[18];
    const float* ring_bo   = (const float*)d_in[19];
    const float* star_wq   = (const float*)d_in[20];
    const float* star_bq   = (const float*)d_in[21];
    const float* star_wk   = (const float*)d_in[22];
    const float* star_bk   = (const float*)d_in[23];
    const float* star_wv   = (const float*)d_in[24];
    const float* star_bv   = (const float*)d_in[25];
    const float* star_wo   = (const float*)d_in[26];
    const float* star_bo   = (const float*)d_in[27];
    const float* head_w1   = (const float*)d_in[28];
    const float* head_b1   = (const float*)d_in[29];
    const float* head_w2   = (const float*)d_in[30];
    const float* head_b2   = (const float*)d_in[31];
    float* out = (float*)d_out;

    cudaFuncSetAttribute(gemm_h2, cudaFuncAttributeMaxDynamicSharedMemorySize, GSMEM);

    float *nodes, *h, *qkv, *relay, *rk, *rv, *sq, *skr, *svr, *satt, *ft, *hid, *bqkv, *bkv2;
    int* maskp;
    f16 *nodes_h, *nodes_l, *h_h, *h_l, *att_h, *att_l, *ff_h, *ff_l;
    f16 *w1f, *w2f, *wqkvf, *wof, *wkv2f;

    cudaGetSymbolAddress((void**)&nodes, g_nodes);
    cudaGetSymbolAddress((void**)&h,     g_h);
    cudaGetSymbolAddress((void**)&qkv,   g_qkv);
    cudaGetSymbolAddress((void**)&relay, g_relay);
    cudaGetSymbolAddress((void**)&rk,    g_rk);
    cudaGetSymbolAddress((void**)&rv,    g_rv);
    cudaGetSymbolAddress((void**)&sq,    g_sq);
    cudaGetSymbolAddress((void**)&skr,   g_skr);
    cudaGetSymbolAddress((void**)&svr,   g_svr);
    cudaGetSymbolAddress((void**)&satt,  g_satt);
    cudaGetSymbolAddress((void**)&ft,    g_ft);
    cudaGetSymbolAddress((void**)&hid,   g_hid);
    cudaGetSymbolAddress((void**)&maskp, g_mask);
    cudaGetSymbolAddress((void**)&bqkv,  g_bqkv);
    cudaGetSymbolAddress((void**)&bkv2,  g_bkv2);
    cudaGetSymbolAddress((void**)&nodes_h, g_nodes_h);
    cudaGetSymbolAddress((void**)&nodes_l, g_nodes_l);
    cudaGetSymbolAddress((void**)&h_h,   g_h_h);
    cudaGetSymbolAddress((void**)&h_l,   g_h_l);
    cudaGetSymbolAddress((void**)&att_h, g_att_h);
    cudaGetSymbolAddress((void**)&att_l, g_att_l);
    cudaGetSymbolAddress((void**)&ff_h,  g_ff_h);
    cudaGetSymbolAddress((void**)&ff_l,  g_ff_l);
    cudaGetSymbolAddress((void**)&w1f,   g_w1f);
    cudaGetSymbolAddress((void**)&w2f,   g_w2f);
    cudaGetSymbolAddress((void**)&wqkvf, g_wqkv);
    cudaGetSymbolAddress((void**)&wof,   g_wof);
    cudaGetSymbolAddress((void**)&wkv2f, g_wkv2);

    const int M = BB*LL;                    // 8192
    float* part1 = qkv + (size_t)M*HH;      // second split-K partial lives in qkv scratch
    dim3 g_ff1(DIN/128, M/128);             // (24, 64)
    dim3 g_ff2s(HH/128, M/128, 2);          // (6, 64, 2) split-K
    dim3 g_qkvd(3*HH/128, M/128);           // (18, 64)
    dim3 g_ods(HH/128, M/128, 2);           // (6, 64, 2) split-K
    dim3 g_kv2(2*HH/128, M/128);            // (12, 64)

    embed_kernel<<<(BB*LL*HH + 255)/256, 256>>>(src, emb, pos_table, nodes, nodes_h, nodes_l);
    mask_kernel<<<(BB*LL + 255)/256, 256>>>(src, maskp);
    relay_zero_kernel<<<(BB*HH + 255)/256, 256>>>(relay);
    relay_partial_kernel<<<dim3(BB, 3, 16), 256>>>(nodes, relay);

    for (int i = 0; i < 2; i++) {
        const float* w1 = pw_w1 + (size_t)i*DIN*HH;
        const float* b1 = pw_b1 + i*DIN;
        const float* w2 = pw_w2 + (size_t)i*HH*DIN;
        const float* b2 = pw_b2 + i*HH;
        const float* rwq = ring_wq + (size_t)i*HH*HH; const float* rbq = ring_bq + i*HH;
        const float* rwk = ring_wk + (size_t)i*HH*HH; const float* rbk = ring_bk + i*HH;
        const float* rwv = ring_wv + (size_t)i*HH*HH; const float* rbv = ring_bv + i*HH;
        const float* rwo = ring_wo + (size_t)i*HH*HH; const float* rbo = ring_bo + i*HH;
        const float* swq = star_wq + (size_t)i*HH*HH; const float* sbq = star_bq + i*HH;
        const float* swk = star_wk + (size_t)i*HH*HH; const float* sbk = star_bk + i*HH;
        const float* swv = star_wv + (size_t)i*HH*HH; const float* sbv = star_bv + i*HH;
        const float* swo = star_wo + (size_t)i*HH*HH; const float* sbo = star_bo + i*HH;

        convert_kernel<<<(DIN*HH + 255)/256, 256>>>(w1, w1f, DIN*HH);
        convert_kernel<<<(HH*DIN + 255)/256, 256>>>(w2, w2f, HH*DIN);
        convert3_kernel<<<(3*HH*HH + 255)/256, 256>>>(rwq, rwk, rwv, wqkvf, HH*HH);
        convert_kernel<<<(HH*HH + 255)/256, 256>>>(rwo, wof, HH*HH);
        convert2_kernel<<<(2*HH*HH + 255)/256, 256>>>(swk, swv, wkv2f, HH*HH);
        bias3_kernel<<<(3*HH + 255)/256, 256>>>(rbq, rbk, rbv, bqkv);
        bias2_kernel<<<(2*HH + 255)/256, 256>>>(sbk, sbv, bkv2);

        // PWFF: ff = relu(nodes@w1^T + b1) -> fp16 pair; h = LN(ff@w2^T(splitK) + b2 + nodes)
        gemm_h2<<<g_ff1, 128, GSMEM>>>(nodes_h, nodes_l, w1f, b1,
                                       (float*)0, ff_h, ff_l, M, DIN, HH, 1, 1);
        gemm_h2<<<g_ff2s, 128, GSMEM>>>(ff_h, ff_l, w2f, b2,
                                        qkv, (f16*)0, (f16*)0, M, HH, DIN, 0, 0);
        ln_kernel<<<M, 256>>>(qkv, part1, nodes, pw_g + i*HH, pw_bn + i*HH, h, h_h, h_l, 0);

        // fused ring q|k|v; relay k/v
        gemm_h2<<<g_qkvd, 128, GSMEM>>>(h_h, h_l, wqkvf, bqkv,
                                        qkv, (f16*)0, (f16*)0, M, 3*HH, HH, 0, 0);
        small_nt_kernel<<<(BB*HH + 7)/8, 256>>>(relay, rwk, rbk, rk, BB, HH, HH, HH, 0);
        small_nt_kernel<<<(BB*HH + 7)/8, 256>>>(relay, rwv, rbv, rv, BB, HH, HH, HH, 0);

        ring_attn_kernel<<<(BB*LL*NHEAD)/8, 256>>>(qkv, rk, rv, att_h, att_l);

        // ring output proj (splitK into qkv scratch) -> LN -> leaky -> nodes (+ hi/lo)
        gemm_h2<<<g_ods, 128, GSMEM>>>(att_h, att_l, wof, rbo,
                                       qkv, (f16*)0, (f16*)0, M, HH, HH, 0, 0);
        ln_kernel<<<M, 256>>>(qkv, part1, (const float*)0, norm_g + i*HH, norm_b + i*HH,
                              nodes, nodes_h, nodes_l, 1);

        // star attention: fused k|v GEMM (into qkv scratch, stride 1536)
        small_nt_kernel<<<(BB*HH + 7)/8, 256>>>(relay, swq, sbq, sq,  BB, HH, HH, HH, 0);
        small_nt_kernel<<<(BB*HH + 7)/8, 256>>>(relay, swk, sbk, skr, BB, HH, HH, HH, 0);
        small_nt_kernel<<<(BB*HH + 7)/8, 256>>>(relay, swv, sbv, svr, BB, HH, HH, HH, 0);
        gemm_h2<<<g_kv2, 128, GSMEM>>>(nodes_h, nodes_l, wkv2f, bkv2,
                                       qkv, (f16*)0, (f16*)0, M, 2*HH, HH, 0, 0);
        star_attn_kernel<<<BB*NHEAD, 256>>>(sq, skr, svr, qkv, maskp, satt);
        small_nt_kernel<<<(BB*HH + 7)/8, 256>>>(satt, swo, sbo, relay, BB, HH, HH, HH, 2);

        mask_nodes_kernel<<<(BB*LL*HH + 255)/256, 256>>>(nodes, nodes_h, nodes_l, maskp);
    }

    // heads
    gather_ft_kernel<<<(BB*2*HH + 255)/256, 256>>>(relay, nodes, positions, ft);
    for (int j = 0; j < 3; j++) {
        small_nt_kernel<<<(BB*1024 + 7)/8, 256>>>(ft, head_w1 + (size_t)j*1024*2*HH,
                                                  head_b1 + j*1024, hid + (size_t)j*BB*1024,
                                                  BB, 1024, 2*HH, 1024, 1);
        small_nt_kernel<<<(BB*5000 + 7)/8, 256>>>(hid + (size_t)j*BB*1024,
                                                  head_w2 + (size_t)j*5000*1024,
                                                  head_b2 + j*5000, out + j*5000,
                                                  BB, 5000, 1024, 15000, 0);
    }
}

// round 12
// speedup vs baseline: 4.4299x; 1.0215x over previous
#include <cuda_runtime.h>
#include <cuda_fp16.h>
#include <math.h>
#include <stdint.h>

#define BB 8
#define LL 1024
#define HH 768
#define NHEAD 12
#define HDIM 64
#define DIN 3072
#define ATT_SCALE 0.125f
#define FULLMASK 0xffffffffu

typedef __half f16;

// ---------------- scratch (device globals; no allocations allowed) ----------------
__device__ float g_nodes[BB*LL*HH];
__device__ float g_h[BB*LL*HH];
__device__ float g_qkv[BB*LL*3*HH];     // fused q|k|v (stride 2304); also split-K partial buffers
__device__ float g_relay[BB*HH];
__device__ float g_rk[BB*HH];
__device__ float g_rv[BB*HH];
__device__ float g_sq[BB*HH];
__device__ float g_skr[BB*HH];
__device__ float g_svr[BB*HH];
__device__ float g_satt[BB*HH];
__device__ float g_ft[BB*2*HH];
__device__ float g_hid[3*BB*1024];
__device__ int   g_mask[BB*LL];
__device__ float g_bqkv[2*3*HH];
__device__ float g_bkv2[2*2*HH];

// fp16 hi/lo activation buffers
__device__ f16 g_nodes_h[BB*LL*HH];
__device__ f16 g_nodes_l[BB*LL*HH];
__device__ f16 g_h_h[BB*LL*HH];
__device__ f16 g_h_l[BB*LL*HH];
__device__ f16 g_att_h[BB*LL*HH];
__device__ f16 g_att_l[BB*LL*HH];
__device__ f16 g_ff_h[BB*LL*DIN];
__device__ f16 g_ff_l[BB*LL*DIN];

// fp16 weight buffers (double-buffered per layer)
__device__ f16 g_w1f[2*DIN*HH];
__device__ f16 g_w2f[2*HH*DIN];
__device__ f16 g_wqkv[2*3*HH*HH];   // ring q|k|v concat
__device__ f16 g_wof[2*HH*HH];
__device__ f16 g_wkv2[2*2*HH*HH];   // star k|v concat

// ---------------- helpers ----------------
__device__ __forceinline__ uint32_t smem_u32(const void* p) {
    return (uint32_t)__cvta_generic_to_shared(p);
}

#define CP16(dst, src) asm volatile("cp.async.cg.shared.global [%0], [%1], 16;" :: "r"(dst), "l"(src))

#define LDSM4(R, addr) \
    asm volatile("ldmatrix.sync.aligned.m8n8.x4.shared.b16 {%0,%1,%2,%3}, [%4];" \
                 : "=r"((R)[0]), "=r"((R)[1]), "=r"((R)[2]), "=r"((R)[3]) : "r"(addr))

#define MMA16816(D, A, B0, B1) \
    asm volatile("mma.sync.aligned.m16n8k16.row.col.f32.f16.f16.f32 " \
                 "{%0,%1,%2,%3}, {%4,%5,%6,%7}, {%8,%9}, {%0,%1,%2,%3};" \
                 : "+f"((D)[0]), "+f"((D)[1]), "+f"((D)[2]), "+f"((D)[3]) \
                 : "r"((A)[0]), "r"((A)[1]), "r"((A)[2]), "r"((A)[3]), "r"(B0), "r"(B1))

__device__ __forceinline__ void split_store(float v, f16* h, f16* l, size_t idx) {
    f16 hi = __float2half(v);
    h[idx] = hi;
    l[idx] = __float2half(v - __half2float(hi));
}

// ---------------- fp32 -> fp16 weight converts (fused variants) ----------------
__global__ void convert_kernel(const float* __restrict__ x, f16* __restrict__ o, int n)
{
    int i = blockIdx.x * blockDim.x + threadIdx.x;
    if (i < n) o[i] = __float2half(x[i]);
}

__global__ void convert3_kernel(const float* __restrict__ a, const float* __restrict__ b,
                                const float* __restrict__ c, f16* __restrict__ o, int n)
{
    int i = blockIdx.x * blockDim.x + threadIdx.x;
    if (i < n) o[i] = __float2half(a[i]);
    else if (i < 2*n) o[i] = __float2half(b[i - n]);
    else if (i < 3*n) o[i] = __float2half(c[i - 2*n]);
}

__global__ void convert2_kernel(const float* __restrict__ a, const float* __restrict__ b,
                                f16* __restrict__ o, int n)
{
    int i = blockIdx.x * blockDim.x + threadIdx.x;
    if (i < n) o[i] = __float2half(a[i]);
    else if (i < 2*n) o[i] = __float2half(b[i - n]);
}

__global__ void bias3_kernel(const float* __restrict__ a, const float* __restrict__ b,
                             const float* __restrict__ c, float* __restrict__ o)
{
    int i = blockIdx.x * blockDim.x + threadIdx.x;
    if (i < HH) o[i] = a[i];
    else if (i < 2*HH) o[i] = b[i - HH];
    else if (i < 3*HH) o[i] = c[i - 2*HH];
}

__global__ void bias2_kernel(const float* __restrict__ a, const float* __restrict__ b,
                             float* __restrict__ o)
{
    int i = blockIdx.x * blockDim.x + threadIdx.x;
    if (i < HH) o[i] = a[i];
    else if (i < 2*HH) o[i] = b[i - HH];
}

// ---------------- embedding + positional (fp32 + hi/lo) ----------------
__global__ void embed_kernel(const int* __restrict__ src, const float* __restrict__ emb,
                             const float* __restrict__ pos, float* __restrict__ nodes,
                             f16* __restrict__ nh, f16* __restrict__ nl)
{
    int idx = blockIdx.x * blockDim.x + threadIdx.x;
    if (idx >= BB*LL*HH) return;
    int hh = idx % HH;
    int bl = idx / HH;
    int l  = bl % LL;
    int j  = hh >> 8;
    int d  = hh & 255;
    int tok = src[bl*3 + j];
    float v = emb[tok*256 + d] + pos[l*HH + hh];
    nodes[idx] = v;
    split_store(v, nh, nl, idx);
}

__global__ void mask_kernel(const int* __restrict__ src, int* __restrict__ mask)
{
    int i = blockIdx.x * blockDim.x + threadIdx.x;
    if (i < BB*LL) mask[i] = (src[i*3] == 0) ? 1 : 0;
}

__global__ void relay_zero_kernel(float* __restrict__ relay)
{
    int i = blockIdx.x * 256 + threadIdx.x;
    if (i < BB*HH) relay[i] = 0.f;
}

__global__ void relay_partial_kernel(const float* __restrict__ nodes, float* __restrict__ relay)
{
    int b  = blockIdx.x;
    int hh = blockIdx.y * 256 + threadIdx.x;
    int l0 = blockIdx.z * 64;
    const float* p = nodes + ((size_t)b*LL + l0)*HH + hh;
    float s = 0.f;
    #pragma unroll 8
    for (int l = 0; l < 64; l++) s += p[(size_t)l*HH];
    atomicAdd(&relay[b*HH + hh], s * (1.0f/1024.0f));
}

// ---------------- tensor-core GEMM (fp16x2): C = A*W^T + bias ----------------
// Block 128x128x32; 4 warps, warp tile 64x64; 3-stage cp.async pipeline.
// gridDim.z == 2: split-K; partial z written to Cf + z*M*N (bias on z==0 only).
#define GSTAGE 24576u
#define GSMEM  73728

__global__ void __launch_bounds__(128, 2) gemm_h2(
    const f16* __restrict__ Ah, const f16* __restrict__ Al,
    const f16* __restrict__ W, const float* __restrict__ bias,
    float* __restrict__ Cf, f16* __restrict__ Ch, f16* __restrict__ Cl,
    int M, int N, int K, int act, int outpair)
{
    extern __shared__ __align__(16) f16 smem[];
    const uint32_t sb = smem_u32(smem);
    const int tid  = threadIdx.x;
    const int lane = tid & 31;
    const int warp = tid >> 5;
    const int wm = warp & 1;
    const int wnn = warp >> 1;
    const int bm = blockIdx.y * 128;
    const int bn = blockIdx.x * 128;
    const int kz = blockIdx.z;
    const int kseg = K / gridDim.z;
    const int kof = kz * kseg;
    const int niter = kseg >> 5;

    const int li = lane >> 3;
    const int lr = lane & 7;
    uint32_t aoff[4][2], woff[4][2];
    #pragma unroll
    for (int mi = 0; mi < 4; mi++)
        #pragma unroll
        for (int ks = 0; ks < 2; ks++) {
            int row = wm*64 + mi*16 + ((li & 1) << 3) + lr;
            int c   = (ks << 1) + (li >> 1);
            aoff[mi][ks] = (uint32_t)((row*32 + ((c ^ ((row >> 1) & 3)) << 3)) * 2);
        }
    #pragma unroll
    for (int nj = 0; nj < 4; nj++)
        #pragma unroll
        for (int ks = 0; ks < 2; ks++) {
            int row = wnn*64 + nj*16 + ((li >> 1) << 3) + lr;
            int c   = (ks << 1) + (li & 1);
            woff[nj][ks] = (uint32_t)((row*32 + ((c ^ ((row >> 1) & 3)) << 3)) * 2);
        }

    int rowv[4], cv[4]; uint32_t swv[4];
    #pragma unroll
    for (int i = 0; i < 4; i++) {
        int id = tid + i*128;
        rowv[i] = id >> 2;
        cv[i]   = id & 3;
        swv[i]  = (uint32_t)((rowv[i]*32 + ((cv[i] ^ ((rowv[i] >> 1) & 3)) << 3)) * 2);
    }

    #define LOAD_STAGE(st, kt) do { \
        uint32_t tb = sb + (uint32_t)(st)*GSTAGE; \
        _Pragma("unroll") \
        for (int i = 0; i < 4; i++) { \
            size_t ga = (size_t)(bm + rowv[i])*K + kof + (kt) + cv[i]*8; \
            size_t gw = (size_t)(bn + rowv[i])*K + kof + (kt) + cv[i]*8; \
            CP16(tb +          swv[i], Ah + ga); \
            CP16(tb + 8192u  + swv[i], Al + ga); \
            CP16(tb + 16384u + swv[i], W  + gw); \
        } \
        asm volatile("cp.async.commit_group;"); \
    } while (0)

    float acc[4][8][4];
    #pragma unroll
    for (int mi = 0; mi < 4; mi++)
        #pragma unroll
        for (int nf = 0; nf < 8; nf++)
            #pragma unroll
            for (int e = 0; e < 4; e++) acc[mi][nf][e] = 0.f;

    LOAD_STAGE(0, 0);
    LOAD_STAGE(1, 32);

    int st = 0;
    int lst = 2;
    for (int it = 0; it < niter; it++) {
        if (it + 1 < niter) {
            asm volatile("cp.async.wait_group 1;");
        } else {
            asm volatile("cp.async.wait_group 0;");
        }
        __syncthreads();

        if (it + 2 < niter) {
            LOAD_STAGE(lst, (it + 2) * 32);
            if (++lst == 3) lst = 0;
        }

        const uint32_t cA  = sb + (uint32_t)st*GSTAGE;
        const uint32_t cAl = cA + 8192u;
        const uint32_t cW  = cA + 16384u;
        if (++st == 3) st = 0;

        #pragma unroll
        for (int ks = 0; ks < 2; ks++) {
            uint32_t fah[4][4], fal[4][4], fw[8][2];
            #pragma unroll
            for (int mi = 0; mi < 4; mi++) LDSM4(fah[mi], cA  + aoff[mi][ks]);
            #pragma unroll
            for (int mi = 0; mi < 4; mi++) LDSM4(fal[mi], cAl + aoff[mi][ks]);
            #pragma unroll
            for (int nj = 0; nj < 4; nj++) {
                uint32_t t4[4];
                LDSM4(t4, cW + woff[nj][ks]);
                fw[nj*2][0]   = t4[0]; fw[nj*2][1]   = t4[1];
                fw[nj*2+1][0] = t4[2]; fw[nj*2+1][1] = t4[3];
            }
            #pragma unroll
            for (int mi = 0; mi < 4; mi++)
                #pragma unroll
                for (int nf = 0; nf < 8; nf++) {
                    MMA16816(acc[mi][nf], fah[mi], fw[nf][0], fw[nf][1]);
                    MMA16816(acc[mi][nf], fal[mi], fw[nf][0], fw[nf][1]);
                }
        }
    }

    float* Cfz = Cf + (size_t)kz * M * N;
    const int useb = (kz == 0);
    const int em = lane >> 2;
    const int en = (lane & 3) << 1;
    #pragma unroll
    for (int mi = 0; mi < 4; mi++) {
        #pragma unroll
        for (int nf = 0; nf < 8; nf++) {
            int col = bn + wnn*64 + nf*8 + en;
            float b0 = useb ? bias[col] : 0.f;
            float b1 = useb ? bias[col + 1] : 0.f;
            #pragma unroll
            for (int hf = 0; hf < 2; hf++) {
                int row = bm + wm*64 + mi*16 + em + hf*8;
                float v0 = acc[mi][nf][hf*2 + 0] + b0;
                float v1 = acc[mi][nf][hf*2 + 1] + b1;
                if (act == 1) { v0 = fmaxf(v0, 0.f); v1 = fmaxf(v1, 0.f); }
                size_t o2 = (size_t)row*N + col;
                if (outpair) {
                    f16 h0 = __float2half(v0);
                    f16 h1 = __float2half(v1);
                    __half2 hp, lp;
                    hp.x = h0; hp.y = h1;
                    lp.x = __float2half(v0 - __half2float(h0));
                    lp.y = __float2half(v1 - __half2float(h1));
                    *(__half2*)(Ch + o2) = hp;
                    *(__half2*)(Cl + o2) = lp;
                } else {
                    float2 r; r.x = v0; r.y = v1;
                    *(float2*)(Cfz + o2) = r;
                }
            }
        }
    }
    #undef LOAD_STAGE
}

// ---------------- small GEMM (warp-per-output) ----------------
__global__ void small_nt_kernel(const float* __restrict__ A, const float* __restrict__ W,
                                const float* __restrict__ bias, float* __restrict__ C,
                                int M, int N, int K, int ldc, int act)
{
    int w = (blockIdx.x * blockDim.x + threadIdx.x) >> 5;
    int lane = threadIdx.x & 31;
    if (w >= M*N) return;
    int m = w / N, n = w % N;
    const float4* a  = (const float4*)(A + (size_t)m*K);
    const float4* wr = (const float4*)(W + (size_t)n*K);
    float s = 0.f;
    int K4 = K >> 2;
    for (int c = lane; c < K4; c += 32) {
        float4 av = a[c], wv = wr[c];
        s += av.x*wv.x + av.y*wv.y + av.z*wv.z + av.w*wv.w;
    }
    #pragma unroll
    for (int o = 16; o > 0; o >>= 1) s += __shfl_xor_sync(FULLMASK, s, o);
    if (lane == 0) {
        s += bias[n];
        if (act == 1) s = fmaxf(s, 0.f);
        else if (act == 2 && s < 0.f) s *= 0.01f;
        C[(size_t)m*ldc + n] = s;
    }
}

// ---------------- LayerNorm (row=768): X (+X2) (+RES), optional leaky, optional fp32/hi-lo out ----------------
__global__ void __launch_bounds__(256) ln_kernel(
    const float* __restrict__ X, const float* __restrict__ X2,
    const float* __restrict__ RES,
    const float* __restrict__ g, const float* __restrict__ b,
    float* __restrict__ out, f16* __restrict__ oh, f16* __restrict__ ol, int leaky)
{
    __shared__ float shs[8], shs2[8];
    __shared__ float smean, sinv;
    int row = blockIdx.x;
    int tid = threadIdx.x;
    const float* x = X + (size_t)row*HH;
    float v0 = x[tid], v1 = x[tid+256], v2 = x[tid+512];
    if (X2) {
        const float* x2 = X2 + (size_t)row*HH;
        v0 += x2[tid]; v1 += x2[tid+256]; v2 += x2[tid+512];
    }
    if (RES) {
        const float* r = RES + (size_t)row*HH;
        v0 += r[tid]; v1 += r[tid+256]; v2 += r[tid+512];
    }
    float s  = v0+v1+v2;
    float s2 = v0*v0 + v1*v1 + v2*v2;
    #pragma unroll
    for (int o = 16; o > 0; o >>= 1) {
        s  += __shfl_xor_sync(FULLMASK, s, o);
        s2 += __shfl_xor_sync(FULLMASK, s2, o);
    }
    if ((tid & 31) == 0) { shs[tid>>5] = s; shs2[tid>>5] = s2; }
    __syncthreads();
    if (tid == 0) {
        float ts = 0.f, ts2 = 0.f;
        for (int i = 0; i < 8; i++) { ts += shs[i]; ts2 += shs2[i]; }
        float mean = ts * (1.0f/768.0f);
        float var  = ts2 * (1.0f/768.0f) - mean*mean;
        smean = mean;
        sinv  = rsqrtf(var + 1e-5f);
    }
    __syncthreads();
    float mean = smean, inv = sinv;
    size_t base = (size_t)row*HH;
    float y0 = (v0-mean)*inv*g[tid]     + b[tid];
    float y1 = (v1-mean)*inv*g[tid+256] + b[tid+256];
    float y2 = (v2-mean)*inv*g[tid+512] + b[tid+512];
    if (leaky) {
        if (y0 < 0.f) y0 *= 0.01f;
        if (y1 < 0.f) y1 *= 0.01f;
        if (y2 < 0.f) y2 *= 0.01f;
    }
    if (out) {
        out[base+tid] = y0; out[base+tid+256] = y1; out[base+tid+512] = y2;
    }
    if (oh) {
        split_store(y0, oh, ol, base+tid);
        split_store(y1, oh, ol, base+tid+256);
        split_store(y2, oh, ol, base+tid+512);
    }
}

// ---------------- ring attention over fused qkv (stride 2304) ----------------
__global__ void __launch_bounds__(256) ring_attn_kernel(
    const float* __restrict__ qkv, const float* __restrict__ rk, const float* __restrict__ rv,
    f16* __restrict__ ah, f16* __restrict__ al)
{
    int gw = (blockIdx.x * 256 + threadIdx.x) >> 5;
    int lane = threadIdx.x & 31;
    if (gw >= BB*LL*NHEAD) return;
    int n  = gw % NHEAD;
    int bl = gw / NHEAD;
    int l  = bl % LL;
    int b  = bl / LL;
    const float* qp = qkv + (size_t)bl*(3*HH) + n*HDIM;
    float q0 = qp[lane], q1 = qp[lane+32];

    float s[4];
    #pragma unroll
    for (int w = 0; w < 3; w++) {
        int ll = l + w - 1;
        float d = 0.f;
        if (ll >= 0 && ll < LL) {
            const float* kp = qkv + ((size_t)b*LL + ll)*(3*HH) + HH + n*HDIM;
            d = q0*kp[lane] + q1*kp[lane+32];
        }
        #pragma unroll
        for (int o = 16; o > 0; o >>= 1) d += __shfl_xor_sync(FULLMASK, d, o);
        s[w] = d;
    }
    {
        const float* kp = rk + b*HH + n*HDIM;
        float d = q0*kp[lane] + q1*kp[lane+32];
        #pragma unroll
        for (int o = 16; o > 0; o >>= 1) d += __shfl_xor_sync(FULLMASK, d, o);
        s[3] = d;
    }
    float sc0 = s[0]*ATT_SCALE, sc1 = s[1]*ATT_SCALE, sc2 = s[2]*ATT_SCALE, sc3 = s[3]*ATT_SCALE;
    float m = fmaxf(fmaxf(sc0, sc1), fmaxf(sc2, sc3));
    float e0 = expf(sc0-m), e1 = expf(sc1-m), e2 = expf(sc2-m), e3 = expf(sc3-m);
    float inv = 1.f / (e0+e1+e2+e3);
    float a0 = e0*inv, a1 = e1*inv, a2 = e2*inv, a3 = e3*inv;

    const float* rvp = rv + b*HH + n*HDIM;
    float o0 = a3 * rvp[lane];
    float o1 = a3 * rvp[lane+32];
    float aw[3] = {a0, a1, a2};
    #pragma unroll
    for (int w = 0; w < 3; w++) {
        int ll = l + w - 1;
        if (ll >= 0 && ll < LL) {
            const float* vp = qkv + ((size_t)b*LL + ll)*(3*HH) + 2*HH + n*HDIM;
            o0 += aw[w] * vp[lane];
            o1 += aw[w] * vp[lane+32];
        }
    }
    size_t o = (size_t)bl*HH + n*HDIM;
    split_store(o0, ah, al, o + lane);
    split_store(o1, ah, al, o + lane + 32);
}

// ---------------- star attention over fused kv (stride 1536) ----------------
__global__ void __launch_bounds__(256) star_attn_kernel(
    const float* __restrict__ sq, const float* __restrict__ skr, const float* __restrict__ svr,
    const float* __restrict__ kv2, const int* __restrict__ mask,
    float* __restrict__ satt)
{
    __shared__ float sc[LL+1];
    __shared__ float qv[HDIM];
    __shared__ float red[8];
    __shared__ float bmax, bsum;
    __shared__ float part[4][HDIM];
    int b = blockIdx.x / NHEAD;
    int n = blockIdx.x % NHEAD;
    int tid = threadIdx.x;

    if (tid < HDIM) qv[tid] = sq[b*HH + n*HDIM + tid];
    __syncthreads();

    for (int s = tid; s <= LL; s += 256) {
        float d;
        if (s > 0 && mask[b*LL + s-1]) d = -INFINITY;
        else {
            const float* kp = (s == 0) ? (skr + b*HH + n*HDIM)
                                       : (kv2 + ((size_t)b*LL + s-1)*(2*HH) + n*HDIM);
            float acc = 0.f;
            #pragma unroll 16
            for (int dd = 0; dd < HDIM; dd++) acc += qv[dd]*kp[dd];
            d = acc * ATT_SCALE;
        }
        sc[s] = d;
    }
    __syncthreads();

    float m = -INFINITY;
    for (int s = tid; s <= LL; s += 256) m = fmaxf(m, sc[s]);
    #pragma unroll
    for (int o = 16; o > 0; o >>= 1) m = fmaxf(m, __shfl_xor_sync(FULLMASK, m, o));
    if ((tid & 31) == 0) red[tid>>5] = m;
    __syncthreads();
    if (tid == 0) {
        float mm = red[0];
        for (int i = 1; i < 8; i++) mm = fmaxf(mm, red[i]);
        bmax = mm;
    }
    __syncthreads();

    float psum = 0.f;
    for (int s = tid; s <= LL; s += 256) {
        float e = expf(sc[s] - bmax);
        sc[s] = e;
        psum += e;
    }
    #pragma unroll
    for (int o = 16; o > 0; o >>= 1) psum += __shfl_xor_sync(FULLMASK, psum, o);
    if ((tid & 31) == 0) red[tid>>5] = psum;
    __syncthreads();
    if (tid == 0) {
        float ss = 0.f;
        for (int i = 0; i < 8; i++) ss += red[i];
        bsum = ss;
    }
    __syncthreads();

    int d = tid & 63, stripe = tid >> 6;
    float acc = 0.f;
    for (int s = stripe; s <= LL; s += 4) {
        float w = sc[s];
        float vv = (s == 0) ? svr[b*HH + n*HDIM + d]
                            : kv2[((size_t)b*LL + s-1)*(2*HH) + HH + n*HDIM + d];
        acc += w*vv;
    }
    part[stripe][d] = acc;
    __syncthreads();
    if (tid < HDIM) {
        float r = (part[0][tid] + part[1][tid] + part[2][tid] + part[3][tid]) / bsum;
        satt[b*HH + n*HDIM + tid] = r;
    }
}

// ---------------- zero out masked node rows (fp32 + hi/lo) ----------------
__global__ void mask_nodes_kernel(float* __restrict__ nodes, f16* __restrict__ nh,
                                  f16* __restrict__ nl, const int* __restrict__ mask)
{
    int idx = blockIdx.x * blockDim.x + threadIdx.x;
    if (idx >= BB*LL*HH) return;
    if (mask[idx / HH]) {
        nodes[idx] = 0.f;
        nh[idx] = __float2half(0.f);
        nl[idx] = __float2half(0.f);
    }
}

// ---------------- build ft = [relay, nodes[b, positions[b]]] ----------------
__global__ void gather_ft_kernel(const float* __restrict__ relay, const float* __restrict__ nodes,
                                 const int* __restrict__ pos, float* __restrict__ ft)
{
    int i = blockIdx.x * blockDim.x + threadIdx.x;
    if (i >= BB*2*HH) return;
    int b = i / (2*HH), c = i % (2*HH);
    ft[i] = (c < HH) ? relay[b*HH + c]
                     : nodes[((size_t)b*LL + pos[b])*HH + (c - HH)];
}

// ---------------- host orchestration ----------------
extern "C" void kernel_launch(void* const* d_in, const int* in_sizes, int n_in,
                              void* d_out, int out_size)
{
    const int*   src       = (const int*)d_in[0];
    const int*   positions = (const int*)d_in[1];
    const float* emb       = (const float*)d_in[2];
    const float* pos_table = (const float*)d_in[3];
    const float* norm_g    = (const float*)d_in[4];
    const float* norm_b    = (const float*)d_in[5];
    const float* pw_w1     = (const float*)d_in[6];
    const float* pw_b1     = (const float*)d_in[7];
    const float* pw_w2     = (const float*)d_in[8];
    const float* pw_b2     = (const float*)d_in[9];
    const float* pw_g      = (const float*)d_in[10];
    const float* pw_bn     = (const float*)d_in[11];
    const float* ring_wq   = (const float*)d_in[12];
    const float* ring_bq   = (const float*)d_in[13];
    const float* ring_wk   = (const float*)d_in[14];
    const float* ring_bk   = (const float*)d_in[15];
    const float* ring_wv   = (const float*)d_in[16];
    const float* ring_bv   = (const float*)d_in[17];
    const float* ring_wo   = (const float*)d_in[18];
    const float* ring_bo   = (const float*)d_in[19];
    const float* star_wq   = (const float*)d_in[20];
    const float* star_bq   = (const float*)d_in[21];
    const float* star_wk   = (const float*)d_in[22];
    const float* star_bk   = (const float*)d_in[23];
    const float* star_wv   = (const float*)d_in[24];
    const float* star_bv   = (const float*)d_in[25];
    const float* star_wo   = (const float*)d_in[26];
    const float* star_bo   = (const float*)d_in[27];
    const float* head_w1   = (const float*)d_in[28];
    const float* head_b1   = (const float*)d_in[29];
    const float* head_w2   = (const float*)d_in[30];
    const float* head_b2   = (const float*)d_in[31];
    float* out = (float*)d_out;

    cudaFuncSetAttribute(gemm_h2, cudaFuncAttributeMaxDynamicSharedMemorySize, GSMEM);

    // second stream + fork/join events (created once; host-side scheduling objects)
    static cudaStream_t s2 = 0;
    static cudaEvent_t evStart = 0, evConv = 0, evFork[2], evSmall[2];
    if (!s2) {
        cudaStreamCreateWithFlags(&s2, cudaStreamNonBlocking);
        cudaEventCreateWithFlags(&evStart, cudaEventDisableTiming);
        cudaEventCreateWithFlags(&evConv,  cudaEventDisableTiming);
        for (int i = 0; i < 2; i++) {
            cudaEventCreateWithFlags(&evFork[i],  cudaEventDisableTiming);
            cudaEventCreateWithFlags(&evSmall[i], cudaEventDisableTiming);
        }
    }

    float *nodes, *h, *qkv, *relay, *rk, *rv, *sq, *skr, *svr, *satt, *ft, *hid, *bqkv, *bkv2;
    int* maskp;
    f16 *nodes_h, *nodes_l, *h_h, *h_l, *att_h, *att_l, *ff_h, *ff_l;
    f16 *w1f, *w2f, *wqkvf, *wof, *wkv2f;

    cudaGetSymbolAddress((void**)&nodes, g_nodes);
    cudaGetSymbolAddress((void**)&h,     g_h);
    cudaGetSymbolAddress((void**)&qkv,   g_qkv);
    cudaGetSymbolAddress((void**)&relay, g_relay);
    cudaGetSymbolAddress((void**)&rk,    g_rk);
    cudaGetSymbolAddress((void**)&rv,    g_rv);
    cudaGetSymbolAddress((void**)&sq,    g_sq);
    cudaGetSymbolAddress((void**)&skr,   g_skr);
    cudaGetSymbolAddress((void**)&svr,   g_svr);
    cudaGetSymbolAddress((void**)&satt,  g_satt);
    cudaGetSymbolAddress((void**)&ft,    g_ft);
    cudaGetSymbolAddress((void**)&hid,   g_hid);
    cudaGetSymbolAddress((void**)&maskp, g_mask);
    cudaGetSymbolAddress((void**)&bqkv,  g_bqkv);
    cudaGetSymbolAddress((void**)&bkv2,  g_bkv2);
    cudaGetSymbolAddress((void**)&nodes_h, g_nodes_h);
    cudaGetSymbolAddress((void**)&nodes_l, g_nodes_l);
    cudaGetSymbolAddress((void**)&h_h,   g_h_h);
    cudaGetSymbolAddress((void**)&h_l,   g_h_l);
    cudaGetSymbolAddress((void**)&att_h, g_att_h);
    cudaGetSymbolAddress((void**)&att_l, g_att_l);
    cudaGetSymbolAddress((void**)&ff_h,  g_ff_h);
    cudaGetSymbolAddress((void**)&ff_l,  g_ff_l);
    cudaGetSymbolAddress((void**)&w1f,   g_w1f);
    cudaGetSymbolAddress((void**)&w2f,   g_w2f);
    cudaGetSymbolAddress((void**)&wqkvf, g_wqkv);
    cudaGetSymbolAddress((void**)&wof,   g_wof);
    cudaGetSymbolAddress((void**)&wkv2f, g_wkv2);

    const int M = BB*LL;                    // 8192
    float* part1 = qkv + (size_t)M*HH;      // second split-K partial lives in qkv scratch
    dim3 g_ff1(DIN/128, M/128);
    dim3 g_ff2s(HH/128, M/128, 2);
    dim3 g_qkvd(3*HH/128, M/128);
    dim3 g_ods(HH/128, M/128, 2);
    dim3 g_kv2(2*HH/128, M/128);

    // ---- fork stream2: convert ALL weights for both layers up front ----
    cudaEventRecord(evStart, 0);
    cudaStreamWaitEvent(s2, evStart, 0);
    for (int i = 0; i < 2; i++) {
        const float* w1 = pw_w1 + (size_t)i*DIN*HH;
        const float* w2 = pw_w2 + (size_t)i*HH*DIN;
        const float* rwq = ring_wq + (size_t)i*HH*HH;
        const float* rwk = ring_wk + (size_t)i*HH*HH;
        const float* rwv = ring_wv + (size_t)i*HH*HH;
        const float* rwo = ring_wo + (size_t)i*HH*HH;
        const float* swk = star_wk + (size_t)i*HH*HH;
        const float* swv = star_wv + (size_t)i*HH*HH;
        convert_kernel<<<(DIN*HH + 255)/256, 256, 0, s2>>>(w1, w1f + (size_t)i*DIN*HH, DIN*HH);
        convert_kernel<<<(HH*DIN + 255)/256, 256, 0, s2>>>(w2, w2f + (size_t)i*HH*DIN, HH*DIN);
        convert3_kernel<<<(3*HH*HH + 255)/256, 256, 0, s2>>>(rwq, rwk, rwv, wqkvf + (size_t)i*3*HH*HH, HH*HH);
        convert_kernel<<<(HH*HH + 255)/256, 256, 0, s2>>>(rwo, wof + (size_t)i*HH*HH, HH*HH);
        convert2_kernel<<<(2*HH*HH + 255)/256, 256, 0, s2>>>(swk, swv, wkv2f + (size_t)i*2*HH*HH, HH*HH);
        bias3_kernel<<<(3*HH + 255)/256, 256, 0, s2>>>(ring_bq + i*HH, ring_bk + i*HH, ring_bv + i*HH, bqkv + i*3*HH);
        bias2_kernel<<<(2*HH + 255)/256, 256, 0, s2>>>(star_bk + i*HH, star_bv + i*HH, bkv2 + i*2*HH);
    }
    cudaEventRecord(evConv, s2);

    // ---- main stream: input prep (overlaps converts) ----
    embed_kernel<<<(BB*LL*HH + 255)/256, 256>>>(src, emb, pos_table, nodes, nodes_h, nodes_l);
    mask_kernel<<<(BB*LL + 255)/256, 256>>>(src, maskp);
    relay_zero_kernel<<<(BB*HH + 255)/256, 256>>>(relay);
    relay_partial_kernel<<<dim3(BB, 3, 16), 256>>>(nodes, relay);
    cudaEventRecord(evFork[0], 0);           // relay ready for layer-0 projections
    cudaStreamWaitEvent(0, evConv, 0);       // weights ready for GEMMs

    for (int i = 0; i < 2; i++) {
        const float* b1 = pw_b1 + i*DIN;
        const float* b2 = pw_b2 + i*HH;
        const float* rwk = ring_wk + (size_t)i*HH*HH; const float* rbk = ring_bk + i*HH;
        const float* rwv = ring_wv + (size_t)i*HH*HH; const float* rbv = ring_bv + i*HH;
        const float* rbo = ring_bo + i*HH;
        const float* swq = star_wq + (size_t)i*HH*HH; const float* sbq = star_bq + i*HH;
        const float* swk = star_wk + (size_t)i*HH*HH; const float* sbk = star_bk + i*HH;
        const float* swv = star_wv + (size_t)i*HH*HH; const float* sbv = star_bv + i*HH;
        const float* swo = star_wo + (size_t)i*HH*HH; const float* sbo = star_bo + i*HH;
        f16* w1fi   = w1f   + (size_t)i*DIN*HH;
        f16* w2fi   = w2f   + (size_t)i*HH*DIN;
        f16* wqkvi  = wqkvf + (size_t)i*3*HH*HH;
        f16* wofi   = wof   + (size_t)i*HH*HH;
        f16* wkv2i  = wkv2f + (size_t)i*2*HH*HH;

        // ---- stream2: relay projections for this layer (overlap FF GEMMs) ----
        cudaStreamWaitEvent(s2, evFork[i], 0);
        small_nt_kernel<<<(BB*HH + 7)/8, 256, 0, s2>>>(relay, rwk, rbk, rk, BB, HH, HH, HH, 0);
        small_nt_kernel<<<(BB*HH + 7)/8, 256, 0, s2>>>(relay, rwv, rbv, rv, BB, HH, HH, HH, 0);
        small_nt_kernel<<<(BB*HH + 7)/8, 256, 0, s2>>>(relay, swq, sbq, sq,  BB, HH, HH, HH, 0);
        small_nt_kernel<<<(BB*HH + 7)/8, 256, 0, s2>>>(relay, swk, sbk, skr, BB, HH, HH, HH, 0);
        small_nt_kernel<<<(BB*HH + 7)/8, 256, 0, s2>>>(relay, swv, sbv, svr, BB, HH, HH, HH, 0);
        cudaEventRecord(evSmall[i], s2);

        // PWFF: ff = relu(nodes@w1^T + b1) -> fp16 pair; h = LN(ff@w2^T(splitK) + b2 + nodes)
        gemm_h2<<<g_ff1, 128, GSMEM>>>(nodes_h, nodes_l, w1fi, b1,
                                       (float*)0, ff_h, ff_l, M, DIN, HH, 1, 1);
        gemm_h2<<<g_ff2s, 128, GSMEM>>>(ff_h, ff_l, w2fi, b2,
                                        qkv, (f16*)0, (f16*)0, M, HH, DIN, 0, 0);
        ln_kernel<<<M, 256>>>(qkv, part1, nodes, pw_g + i*HH, pw_bn + i*HH,
                              (float*)0, h_h, h_l, 0);

        // fused ring q|k|v
        gemm_h2<<<g_qkvd, 128, GSMEM>>>(h_h, h_l, wqkvi, bqkv + i*3*HH,
                                        qkv, (f16*)0, (f16*)0, M, 3*HH, HH, 0, 0);

        cudaStreamWaitEvent(0, evSmall[i], 0);   // need rk/rv (and star q/k/v later)
        ring_attn_kernel<<<(BB*LL*NHEAD)/8, 256>>>(qkv, rk, rv, att_h, att_l);

        // ring output proj (splitK) -> LN -> leaky -> nodes (+ hi/lo)
        gemm_h2<<<g_ods, 128, GSMEM>>>(att_h, att_l, wofi, rbo,
                                       qkv, (f16*)0, (f16*)0, M, HH, HH, 0, 0);
        ln_kernel<<<M, 256>>>(qkv, part1, (const float*)0, norm_g + i*HH, norm_b + i*HH,
                              nodes, nodes_h, nodes_l, 1);

        // star attention: fused k|v GEMM (into qkv scratch, stride 1536)
        gemm_h2<<<g_kv2, 128, GSMEM>>>(nodes_h, nodes_l, wkv2i, bkv2 + i*2*HH,
                                       qkv, (f16*)0, (f16*)0, M, 2*HH, HH, 0, 0);
        star_attn_kernel<<<BB*NHEAD, 256>>>(sq, skr, svr, qkv, maskp, satt);
        small_nt_kernel<<<(BB*HH + 7)/8, 256>>>(satt, swo, sbo, relay, BB, HH, HH, HH, 2);
        if (i == 0) cudaEventRecord(evFork[1], 0);   // relay ready for layer-1 projections

        mask_nodes_kernel<<<(BB*LL*HH + 255)/256, 256>>>(nodes, nodes_h, nodes_l, maskp);
    }

    // heads
    gather_ft_kernel<<<(BB*2*HH + 255)/256, 256>>>(relay, nodes, positions, ft);
    for (int j = 0; j < 3; j++) {
        small_nt_kernel<<<(BB*1024 + 7)/8, 256>>>(ft, head_w1 + (size_t)j*1024*2*HH,
                                                  head_b1 + j*1024, hid + (size_t)j*BB*1024,
                                                  BB, 1024, 2*HH, 1024, 1);
        small_nt_kernel<<<(BB*5000 + 7)/8, 256>>>(hid + (size_t)j*BB*1024,
                                                  head_w2 + (size_t)j*5000*1024,
                                                  head_b2 + j*5000, out + j*5000,
                                                  BB, 5000, 1024, 15000, 0);
    }
}